// round 8
// baseline (speedup 1.0000x reference)
#include <cuda_runtime.h>
#include <cuda_bf16.h>
#include <math.h>

#define BB 4
#define TT 2048
#define BT (BB*TT)
#define DM 256
#define HH 8
#define DKk 32
#define DHid 1024
#define ND 8192
#define NL 4

#define KP_DM (DM/2)      // 128 pairs
#define KP_HID (DHid/2)   // 512 pairs

// packed-weight region offsets (u32 elements); B operands stored n-major [N][KP]
#define W_M0 (NL*3*DM*KP_DM)
#define W_M1 (W_M0 + NL*DHid*KP_DM)
#define W_UE (W_M1 + NL*DM*KP_HID)
#define W_TOT (W_UE + ND*KP_DM)

// -------------------- scratch (device globals) ---------------------------------
__device__ float    g_h  [BT*DM];
__device__ unsigned g_hh [BT*KP_DM];
__device__ unsigned g_hl [BT*KP_DM];
__device__ unsigned g_qh [BT*KP_DM];
__device__ unsigned g_ql [BT*KP_DM];
__device__ unsigned g_kh [BT*KP_DM];
__device__ unsigned g_kl [BT*KP_DM];
__device__ float    g_v  [BT*DM];
__device__ unsigned g_vth[BT*KP_DM];   // V transposed+packed: [bh][vd0..31][kp]
__device__ unsigned g_vtl[BT*KP_DM];
__device__ float    g_ov [BT*DM];
__device__ unsigned g_yh [BT*KP_HID];
__device__ unsigned g_yl [BT*KP_HID];
__device__ float    g_tmp[BT*DM];
__device__ unsigned g_wh [W_TOT];
__device__ unsigned g_wl [W_TOT];
__device__ float    g_wosum[NL*DKk*DM];
__device__ int      g_is64;

// -------------------- helpers -------------------------------------------------
__device__ __forceinline__ void pack_hilo(float x, float y, unsigned& hi, unsigned& lo) {
    __nv_bfloat16 hx = __float2bfloat16(x);
    __nv_bfloat16 hy = __float2bfloat16(y);
    float rx = x - __bfloat162float(hx);
    float ry = y - __bfloat162float(hy);
    __nv_bfloat16 lx = __float2bfloat16(rx);
    __nv_bfloat16 ly = __float2bfloat16(ry);
    hi = ((unsigned)__bfloat16_as_ushort(hy) << 16) | (unsigned)__bfloat16_as_ushort(hx);
    lo = ((unsigned)__bfloat16_as_ushort(ly) << 16) | (unsigned)__bfloat16_as_ushort(lx);
}

__device__ __forceinline__ void mma16816(float* c, const unsigned* a, const unsigned* b) {
    asm volatile(
        "mma.sync.aligned.m16n8k16.row.col.f32.bf16.bf16.f32 "
        "{%0,%1,%2,%3}, {%4,%5,%6,%7}, {%8,%9}, {%0,%1,%2,%3};\n"
        : "+f"(c[0]), "+f"(c[1]), "+f"(c[2]), "+f"(c[3])
        : "r"(a[0]), "r"(a[1]), "r"(a[2]), "r"(a[3]), "r"(b[0]), "r"(b[1]));
}

__device__ __forceinline__ void ldsm4(unsigned* r, const void* p) {
    unsigned a = (unsigned)__cvta_generic_to_shared(p);
    asm volatile("ldmatrix.sync.aligned.m8n8.x4.shared.b16 {%0,%1,%2,%3}, [%4];\n"
        : "=r"(r[0]), "=r"(r[1]), "=r"(r[2]), "=r"(r[3]) : "r"(a));
}

__device__ __forceinline__ void cp16(void* sdst, const void* gsrc) {
    unsigned sa = (unsigned)__cvta_generic_to_shared(sdst);
    asm volatile("cp.async.cg.shared.global [%0], [%1], 16;\n" :: "r"(sa), "l"(gsrc));
}
#define CP_COMMIT() asm volatile("cp.async.commit_group;\n" ::: "memory")
template <int N> __device__ __forceinline__ void cp_wait() {
    asm volatile("cp.async.wait_group %0;\n" :: "n"(N) : "memory");
}

__device__ __forceinline__ float warp_sum(float v) {
    #pragma unroll
    for (int o = 16; o; o >>= 1) v += __shfl_xor_sync(0xffffffffu, v, o);
    return v;
}

// -------------------- index dtype probe ---------------------------------------
__global__ void detect_idx(const int* __restrict__ xi) {
    __shared__ int ok;
    if (threadIdx.x == 0) ok = 1;
    __syncthreads();
    if (xi[2 * threadIdx.x + 1] != 0) atomicAnd(&ok, 0);
    __syncthreads();
    if (threadIdx.x == 0) g_is64 = ok;
}

// -------------------- one-shot weight pre-conversion (n-major) -----------------
// Output layout per region: [n][kp]. Source reads kept coalesced (n fastest).
__global__ __launch_bounds__(256) void convert_weights(
    const float* __restrict__ wq, const float* __restrict__ wk,
    const float* __restrict__ wv, const float* __restrict__ m0,
    const float* __restrict__ m1, const float* __restrict__ ue) {
    int i = blockIdx.x * 256 + threadIdx.x;
    if (i >= W_TOT) return;
    float a, b;
    size_t out;
    if (i < W_M0) {                       // QKV per-head [n/32][k][n%32] source
        int l3 = i >> 15;
        int r  = i & 32767;
        int kp = r >> 8;
        int n  = r & 255;
        int l = l3 / 3, mi = l3 % 3;
        const float* W = (mi == 0) ? wq : (mi == 1) ? wk : wv;
        size_t base = (size_t)l * HH * DM * DKk + (size_t)(n >> 5) * DM * DKk + (n & 31);
        a = W[base + (size_t)(2 * kp)     * DKk];
        b = W[base + (size_t)(2 * kp + 1) * DKk];
        out = (size_t)l3 * 32768 + (size_t)n * KP_DM + kp;
    } else if (i < W_M1) {                // mlp0 [k][1024] -> [1024][128]
        int r = i - W_M0;
        int l = r >> 17;
        int rr = r & 131071;
        int kp = rr >> 10;
        int n  = rr & 1023;
        const float* W = m0 + (size_t)l * DM * DHid;
        a = W[(size_t)(2 * kp)     * DHid + n];
        b = W[(size_t)(2 * kp + 1) * DHid + n];
        out = W_M0 + (size_t)l * 131072 + (size_t)n * KP_DM + kp;
    } else if (i < W_UE) {                // mlp1 [k][256] -> [256][512]
        int r = i - W_M1;
        int l = r >> 17;
        int rr = r & 131071;
        int kp = rr >> 8;
        int n  = rr & 255;
        const float* W = m1 + (size_t)l * DHid * DM;
        a = W[(size_t)(2 * kp)     * DM + n];
        b = W[(size_t)(2 * kp + 1) * DM + n];
        out = W_M1 + (size_t)l * 131072 + (size_t)n * KP_HID + kp;
    } else {                              // unembedding [k][8192] -> [8192][128]
        int r = i - W_UE;
        int kp = r >> 13;
        int n  = r & 8191;
        a = ue[(size_t)(2 * kp)     * ND + n];
        b = ue[(size_t)(2 * kp + 1) * ND + n];
        out = W_UE + (size_t)n * KP_DM + kp;
    }
    unsigned hi, lo;
    pack_hilo(a, b, hi, lo);
    g_wh[out] = hi;
    g_wl[out] = lo;
}

// -------------------- wo summed over heads, all layers -------------------------
__global__ void compute_wosum_all(const float* __restrict__ wo) {
    int i = blockIdx.x * 256 + threadIdx.x;
    if (i < NL * DKk * DM) {
        int l = i / (DKk * DM);
        int r = i % (DKk * DM);
        float s = 0.f;
        #pragma unroll
        for (int hh = 0; hh < HH; hh++)
            s += wo[(size_t)l * HH * DKk * DM + (size_t)hh * DKk * DM + r];
        g_wosum[i] = s;
    }
}

// -------------------- warp-per-token LN core -----------------------------------
__device__ __forceinline__ void ln_store_warp(int token, int lane, float* val) {
    float s = 0.f;
    #pragma unroll
    for (int j = 0; j < 8; j++) s += val[j];
    s = warp_sum(s);
    float m = s * (1.f / DM);
    float vv = 0.f;
    #pragma unroll
    for (int j = 0; j < 8; j++) { val[j] -= m; vv += val[j] * val[j]; }
    vv = warp_sum(vv);
    float inv = rsqrtf(vv * (1.f / DM) + 1e-5f);
    #pragma unroll
    for (int j = 0; j < 8; j++) {
        float out = val[j] * inv;
        int d = j * 32 + lane;
        g_h[(size_t)token * DM + d] = out;
        float other = __shfl_xor_sync(0xffffffffu, out, 1);
        if (!(lane & 1)) {
            unsigned hi, lo;
            pack_hilo(out, other, hi, lo);
            g_hh[(size_t)token * KP_DM + j * 16 + (lane >> 1)] = hi;
            g_hl[(size_t)token * KP_DM + j * 16 + (lane >> 1)] = lo;
        }
    }
}

__global__ __launch_bounds__(256) void embed_ln_w(const int* __restrict__ xi,
                                                  const float* __restrict__ emb,
                                                  const float* __restrict__ pos) {
    int token = blockIdx.x * 8 + (threadIdx.x >> 5);
    int lane = threadIdx.x & 31;
    int t = token % TT;
    int idx = g_is64 ? xi[2 * token] : xi[token];
    float val[8];
    #pragma unroll
    for (int j = 0; j < 8; j++) {
        int d = j * 32 + lane;
        val[j] = emb[(size_t)idx * DM + d] + pos[(size_t)t * DM + d];
    }
    ln_store_warp(token, lane, val);
}

__global__ __launch_bounds__(256) void attn_out_ln_w(const float* __restrict__ ov,
                                                     const float* __restrict__ wos) {
    int token = blockIdx.x * 8 + (threadIdx.x >> 5);
    int lane = threadIdx.x & 31;
    float vs = 0.f;
    float val[8];
    #pragma unroll
    for (int j = 0; j < 8; j++) {
        float o = ov[(size_t)token * DM + j * 32 + lane];
        vs += o;
        val[j] = g_h[(size_t)token * DM + j * 32 + lane];
    }
    #pragma unroll
    for (int v = 0; v < DKk; v++) {
        float sv = __shfl_sync(0xffffffffu, vs, v);
        #pragma unroll
        for (int j = 0; j < 8; j++) val[j] += sv * wos[v * DM + j * 32 + lane];
    }
    ln_store_warp(token, lane, val);
}

__global__ __launch_bounds__(256) void ln_residual_w(const float* __restrict__ add) {
    int token = blockIdx.x * 8 + (threadIdx.x >> 5);
    int lane = threadIdx.x & 31;
    float val[8];
    #pragma unroll
    for (int j = 0; j < 8; j++) {
        int d = j * 32 + lane;
        val[j] = g_h[(size_t)token * DM + d] + add[(size_t)token * DM + d];
    }
    ln_store_warp(token, lane, val);
}

// -------------------- packed GEMM: cp.async 2-buffer + LDSM fragments ----------
// 256 threads, 8 warps (4 in m x 2 in n), 32x(BN/2) warp tiles.
// A [M][KP] hi/lo.  B n-major [N][KP] hi/lo.  Smem rows stride-20 u32
// (LDSM phase banks 20r mod 32 distinct -> conflict-free).
// EPI 0: fp32. 1: relu(acc+bias)->packed. 2: acc+bias fp32. 4: fused QKV.
template <int EPI, int BN>
__global__ __launch_bounds__(256, 2) void mgemm_db(
    const unsigned* __restrict__ Ah, const unsigned* __restrict__ Al,
    const unsigned* __restrict__ Bh, const unsigned* __restrict__ Bl,
    float* __restrict__ C, unsigned* __restrict__ Ch, unsigned* __restrict__ Cl,
    unsigned* __restrict__ Ch2, unsigned* __restrict__ Cl2,
    const float* __restrict__ bias, int M, int N, int KP) {
    constexpr int NT = BN / 16;
    constexpr int NP = NT / 2;
    constexpr int ASZ = 128 * 20;          // one A buffer (u32), per hi/lo
    constexpr int BSZ = BN * 20;           // one B buffer (u32), per hi/lo
    extern __shared__ unsigned smp[];
    unsigned* AsH = smp;                    // [2][128][20]
    unsigned* AsL = smp + 2 * ASZ;
    unsigned* BsH = smp + 4 * ASZ;          // [2][BN][20]
    unsigned* BsL = BsH + 2 * BSZ;

    const int bm = blockIdx.y * 128;
    int bn, mat = 0;
    if (EPI == 4) {
        mat = blockIdx.x >> 1;
        bn = (blockIdx.x & 1) * 128;
        Bh += (size_t)mat * DM * KP_DM;
        Bl += (size_t)mat * DM * KP_DM;
    } else {
        bn = blockIdx.x * BN;
    }
    const int tid  = threadIdx.x;
    const int lane = tid & 31;
    const int wid  = tid >> 5;
    const int g = lane >> 2;
    const int t = lane & 3;
    const int wm = (wid & 3) * 32;
    const int wn = (wid >> 2) * (BN / 2);
    const int lrow = lane & 15;
    const int lcol = (lane >> 4) << 2;

    float acc[2][NT][4];
    #pragma unroll
    for (int mt = 0; mt < 2; mt++)
        #pragma unroll
        for (int nt = 0; nt < NT; nt++)
            #pragma unroll
            for (int r = 0; r < 4; r++) acc[mt][nt][r] = 0.f;

    // fill: A 128 rows x 16 kp, B BN rows x 16 kp; both [row][20] layout.
    #define FILL_TILE(s, kp0)                                                       \
        do {                                                                         \
            _Pragma("unroll")                                                        \
            for (int it_ = 0; it_ < 2; it_++) {                                      \
                int i_ = it_ * 256 + tid;                                            \
                int m_ = i_ >> 2, c4_ = (i_ & 3) * 4;                                \
                size_t ga_ = (size_t)(bm + m_) * KP + (kp0) + c4_;                   \
                cp16(&AsH[(s) * ASZ + m_ * 20 + c4_], Ah + ga_);                     \
                cp16(&AsL[(s) * ASZ + m_ * 20 + c4_], Al + ga_);                     \
            }                                                                        \
            _Pragma("unroll")                                                        \
            for (int it_ = 0; it_ < BN / 64; it_++) {                                \
                int i_ = it_ * 256 + tid;                                            \
                int n_ = i_ >> 2, c4_ = (i_ & 3) * 4;                                \
                size_t gb_ = (size_t)(bn + n_) * KP + (kp0) + c4_;                   \
                cp16(&BsH[(s) * BSZ + n_ * 20 + c4_], Bh + gb_);                     \
                cp16(&BsL[(s) * BSZ + n_ * 20 + c4_], Bl + gb_);                     \
            }                                                                        \
        } while (0)

    const int NKT = KP / 16;
    FILL_TILE(0, 0);
    CP_COMMIT();

    for (int kt = 0; kt < NKT; kt++) {
        const int s = kt & 1;
        if (kt + 1 < NKT) {
            FILL_TILE(s ^ 1, (kt + 1) * 16);
            CP_COMMIT();
            cp_wait<1>();
        } else {
            cp_wait<0>();
        }
        __syncthreads();

        #pragma unroll
        for (int ks = 0; ks < 2; ks++) {
            const int kb = ks * 8 + lcol;
            unsigned ah[2][4], al[2][4];
            #pragma unroll
            for (int mt = 0; mt < 2; mt++) {
                ldsm4(ah[mt], &AsH[s * ASZ + (wm + mt * 16 + lrow) * 20 + kb]);
                ldsm4(al[mt], &AsL[s * ASZ + (wm + mt * 16 + lrow) * 20 + kb]);
            }
            #pragma unroll
            for (int np = 0; np < NP; np++) {
                unsigned bh4[4], bl4[4];
                ldsm4(bh4, &BsH[s * BSZ + (wn + np * 16 + lrow) * 20 + kb]);
                ldsm4(bl4, &BsL[s * BSZ + (wn + np * 16 + lrow) * 20 + kb]);
                unsigned beh[2] = {bh4[0], bh4[2]}, boh[2] = {bh4[1], bh4[3]};
                unsigned bel[2] = {bl4[0], bl4[2]}, bol[2] = {bl4[1], bl4[3]};
                #pragma unroll
                for (int mt = 0; mt < 2; mt++) {
                    mma16816(acc[mt][2 * np],     ah[mt], beh);
                    mma16816(acc[mt][2 * np],     ah[mt], bel);
                    mma16816(acc[mt][2 * np],     al[mt], beh);
                    mma16816(acc[mt][2 * np + 1], ah[mt], boh);
                    mma16816(acc[mt][2 * np + 1], ah[mt], bol);
                    mma16816(acc[mt][2 * np + 1], al[mt], boh);
                }
            }
        }
        __syncthreads();
    }
    #undef FILL_TILE

    #pragma unroll
    for (int mt = 0; mt < 2; mt++) {
        #pragma unroll
        for (int nt = 0; nt < NT; nt++) {
            int row0 = bm + wm + mt * 16 + g;
            int col  = bn + wn + nt * 8 + 2 * t;
            float v0 = acc[mt][nt][0], v1 = acc[mt][nt][1];
            float v2 = acc[mt][nt][2], v3 = acc[mt][nt][3];
            if (EPI == 1) {
                float b0 = bias[col], b1 = bias[col + 1];
                v0 = fmaxf(v0 + b0, 0.f); v1 = fmaxf(v1 + b1, 0.f);
                v2 = fmaxf(v2 + b0, 0.f); v3 = fmaxf(v3 + b1, 0.f);
            }
            if (EPI == 2) {
                float b0 = bias[col], b1 = bias[col + 1];
                v0 += b0; v1 += b1; v2 += b0; v3 += b1;
            }
            bool fp32out = (EPI == 0 || EPI == 2 || (EPI == 4 && mat == 2));
            if (fp32out) {
                *(float2*)(C + (size_t)row0 * N + col)       = make_float2(v0, v1);
                *(float2*)(C + (size_t)(row0 + 8) * N + col) = make_float2(v2, v3);
            } else {
                unsigned* Dh = (EPI == 4 && mat == 1) ? Ch2 : Ch;
                unsigned* Dl = (EPI == 4 && mat == 1) ? Cl2 : Cl;
                unsigned h0, l0, h1, l1;
                pack_hilo(v0, v1, h0, l0);
                pack_hilo(v2, v3, h1, l1);
                int NPk = N >> 1, cp = col >> 1;
                Dh[(size_t)row0 * NPk + cp]       = h0;
                Dl[(size_t)row0 * NPk + cp]       = l0;
                Dh[(size_t)(row0 + 8) * NPk + cp] = h1;
                Dl[(size_t)(row0 + 8) * NPk + cp] = l1;
            }
        }
    }
}

// -------------------- V transpose + pack ---------------------------------------
__global__ __launch_bounds__(256) void pack_v(const float* __restrict__ v,
                                              unsigned* __restrict__ vth,
                                              unsigned* __restrict__ vtl) {
    __shared__ float s[64][33];
    const int bh = blockIdx.y;
    const int b = bh >> 3, h = bh & 7;
    const int k0 = blockIdx.x * 64;
    const int tid = threadIdx.x;
    for (int i = tid; i < 2048; i += 256) {
        int key = i >> 5, vd = i & 31;
        s[key][vd] = v[(size_t)(b * TT + k0 + key) * DM + h * DKk + vd];
    }
    __syncthreads();
    for (int i = tid; i < 1024; i += 256) {
        int vd = i >> 5, kp = i & 31;
        unsigned hi, lo;
        pack_hilo(s[2 * kp][vd], s[2 * kp + 1][vd], hi, lo);
        size_t o = ((size_t)bh * DKk + vd) * (TT / 2) + (k0 >> 1) + kp;
        vth[o] = hi;
        vtl[o] = lo;
    }
}

// -------------------- tensor-core causal attention (all-MUFU exp) --------------
__global__ __launch_bounds__(256, 2) void attention_mma2(
    const unsigned* __restrict__ qh, const unsigned* __restrict__ ql,
    const unsigned* __restrict__ kh, const unsigned* __restrict__ kl,
    const unsigned* __restrict__ vth, const unsigned* __restrict__ vtl,
    float* __restrict__ ov) {
    __shared__ unsigned Ks_hi[2][64][20];
    __shared__ unsigned Ks_lo[2][64][20];
    __shared__ unsigned Vs_hi[2][32][36];
    __shared__ unsigned Vs_lo[2][32][36];

    const int bh = blockIdx.y;
    const int b  = bh >> 3, h = bh & 7;
    const int t0 = (gridDim.x - 1 - blockIdx.x) * 128;
    const int tid  = threadIdx.x;
    const int lane = tid & 31;
    const int wid  = tid >> 5;
    const int g = lane >> 2;
    const int t = lane & 3;
    const int wm = wid * 16;

    unsigned qfh[2][4], qfl[2][4];
    {
        size_t base = (size_t)(b * TT + t0 + wm) * KP_DM + h * 16;
        #pragma unroll
        for (int ks = 0; ks < 2; ks++) {
            qfh[ks][0] = qh[base + (size_t)g * KP_DM + ks * 8 + t];
            qfh[ks][1] = qh[base + (size_t)(g + 8) * KP_DM + ks * 8 + t];
            qfh[ks][2] = qh[base + (size_t)g * KP_DM + ks * 8 + t + 4];
            qfh[ks][3] = qh[base + (size_t)(g + 8) * KP_DM + ks * 8 + t + 4];
            qfl[ks][0] = ql[base + (size_t)g * KP_DM + ks * 8 + t];
            qfl[ks][1] = ql[base + (size_t)(g + 8) * KP_DM + ks * 8 + t];
            qfl[ks][2] = ql[base + (size_t)g * KP_DM + ks * 8 + t + 4];
            qfl[ks][3] = ql[base + (size_t)(g + 8) * KP_DM + ks * 8 + t + 4];
        }
    }

    float o[4][4];
    #pragma unroll
    for (int nf = 0; nf < 4; nf++)
        #pragma unroll
        for (int r = 0; r < 4; r++) o[nf][r] = 0.f;
    float rs0 = 0.f, rs1 = 0.f;

    const int row0 = t0 + wm + g;
    const int row1 = row0 + 8;
    const int nit = t0 / 64 + 2;

    const int kkey = tid >> 2, kseg = tid & 3;
    const int vvd  = tid >> 3, vseg = tid & 7;

    #define ISSUE_TILE(s, o0)                                                        \
        do {                                                                          \
            size_t kgi = (size_t)(b * TT + (o0) + kkey) * KP_DM + h * 16 + kseg * 4;  \
            cp16(&Ks_hi[s][kkey][kseg * 4], kh + kgi);                                \
            cp16(&Ks_lo[s][kkey][kseg * 4], kl + kgi);                                \
            size_t vgi = ((size_t)bh * DKk + vvd) * (TT / 2) + ((o0) >> 1) + vseg * 4;\
            cp16(&Vs_hi[s][vvd][vseg * 4], vth + vgi);                                \
            cp16(&Vs_lo[s][vvd][vseg * 4], vtl + vgi);                                \
        } while (0)

    ISSUE_TILE(0, 0);
    CP_COMMIT();

    for (int it = 0; it < nit; it++) {
        const int o0 = it * 64;
        const int s = it & 1;
        if (it + 1 < nit) {
            ISSUE_TILE(s ^ 1, o0 + 64);
            CP_COMMIT();
            cp_wait<1>();
        } else {
            cp_wait<0>();
        }
        __syncthreads();

        if (o0 <= t0 + wm + 15) {
            float c[8][4];
            #pragma unroll
            for (int j = 0; j < 8; j++)
                #pragma unroll
                for (int r = 0; r < 4; r++) c[j][r] = 0.f;
            #pragma unroll
            for (int j = 0; j < 8; j++) {
                int col = j * 8 + g;
                #pragma unroll
                for (int ks = 0; ks < 2; ks++) {
                    unsigned bhf[2], blf[2];
                    bhf[0] = Ks_hi[s][col][ks * 8 + t];
                    bhf[1] = Ks_hi[s][col][ks * 8 + t + 4];
                    blf[0] = Ks_lo[s][col][ks * 8 + t];
                    blf[1] = Ks_lo[s][col][ks * 8 + t + 4];
                    mma16816(c[j], qfh[ks], bhf);
                    mma16816(c[j], qfh[ks], blf);
                    mma16816(c[j], qfl[ks], bhf);
                }
            }
            // mask + exp + rowsum
            #pragma unroll
            for (int j = 0; j < 8; j++) {
                int cb = o0 + j * 8 + 2 * t;
                float e0 = __expf(fminf(c[j][0], 50.f));
                float e1 = __expf(fminf(c[j][1], 50.f));
                float e2 = __expf(fminf(c[j][2], 50.f));
                float e3 = __expf(fminf(c[j][3], 50.f));
                c[j][0] = (cb     <= row0) ? e0 : 0.f;
                c[j][1] = (cb + 1 <= row0) ? e1 : 0.f;
                c[j][2] = (cb     <= row1) ? e2 : 0.f;
                c[j][3] = (cb + 1 <= row1) ? e3 : 0.f;
                rs0 += c[j][0] + c[j][1];
                rs1 += c[j][2] + c[j][3];
            }
            // O += P V
            #pragma unroll
            for (int klq = 0; klq < 4; klq++) {
                unsigned ph[4], pl[4];
                pack_hilo(c[2 * klq][0],     c[2 * klq][1],     ph[0], pl[0]);
                pack_hilo(c[2 * klq][2],     c[2 * klq][3],     ph[1], pl[1]);
                pack_hilo(c[2 * klq + 1][0], c[2 * klq + 1][1], ph[2], pl[2]);
                pack_hilo(c[2 * klq + 1][2], c[2 * klq + 1][3], ph[3], pl[3]);
                int kb = klq * 8;
                #pragma unroll
                for (int nf = 0; nf < 4; nf++) {
                    int vc = nf * 8 + g;
                    unsigned vhf[2], vlf[2];
                    vhf[0] = Vs_hi[s][vc][kb + t];
                    vhf[1] = Vs_hi[s][vc][kb + t + 4];
                    vlf[0] = Vs_lo[s][vc][kb + t];
                    vlf[1] = Vs_lo[s][vc][kb + t + 4];
                    mma16816(o[nf], ph, vhf);
                    mma16816(o[nf], ph, vlf);
                    mma16816(o[nf], pl, vhf);
                }
            }
        }
        __syncthreads();
    }
    #undef ISSUE_TILE

    rs0 += __shfl_xor_sync(0xffffffffu, rs0, 1);
    rs0 += __shfl_xor_sync(0xffffffffu, rs0, 2);
    rs1 += __shfl_xor_sync(0xffffffffu, rs1, 1);
    rs1 += __shfl_xor_sync(0xffffffffu, rs1, 2);
    float i0 = 1.f / (rs0 + 1e-10f);
    float i1 = 1.f / (rs1 + 1e-10f);
    size_t r0 = (size_t)(b * TT + row0);
    #pragma unroll
    for (int nf = 0; nf < 4; nf++) {
        int vd = h * DKk + nf * 8 + 2 * t;
        *(float2*)(ov + r0 * DM + vd)       = make_float2(o[nf][0] * i0, o[nf][1] * i0);
        *(float2*)(ov + (r0 + 8) * DM + vd) = make_float2(o[nf][2] * i1, o[nf][3] * i1);
    }
}

// -------------------- launch --------------------------------------------------
extern "C" void kernel_launch(void* const* d_in, const int* in_sizes, int n_in,
                              void* d_out, int out_size) {
    const int*   x     = (const int*)  d_in[0];
    const float* emb   = (const float*)d_in[1];
    const float* pos   = (const float*)d_in[2];
    const float* wq    = (const float*)d_in[3];
    const float* wk    = (const float*)d_in[4];
    const float* wv    = (const float*)d_in[5];
    const float* wo    = (const float*)d_in[6];
    const float* mlp0  = (const float*)d_in[7];
    const float* mlpb  = (const float*)d_in[8];
    const float* mlp1  = (const float*)d_in[9];
    const float* unemb = (const float*)d_in[10];
    const float* bias  = (const float*)d_in[11];
    float* out = (float*)d_out;

    unsigned *hh_, *hl_, *qh_, *ql_, *kh_, *kl_, *yh_, *yl_, *wh_, *wl_, *vth_, *vtl_;
    float *v_, *ov_, *tmp_, *wos_;
    cudaGetSymbolAddress((void**)&hh_, g_hh);
    cudaGetSymbolAddress((void**)&hl_, g_hl);
    cudaGetSymbolAddress((void**)&qh_, g_qh);
    cudaGetSymbolAddress((void**)&ql_, g_ql);
    cudaGetSymbolAddress((void**)&kh_, g_kh);
    cudaGetSymbolAddress((void**)&kl_, g_kl);
    cudaGetSymbolAddress((void**)&yh_, g_yh);
    cudaGetSymbolAddress((void**)&yl_, g_yl);
    cudaGetSymbolAddress((void**)&wh_, g_wh);
    cudaGetSymbolAddress((void**)&wl_, g_wl);
    cudaGetSymbolAddress((void**)&vth_, g_vth);
    cudaGetSymbolAddress((void**)&vtl_, g_vtl);
    cudaGetSymbolAddress((void**)&v_,   g_v);
    cudaGetSymbolAddress((void**)&ov_,  g_ov);
    cudaGetSymbolAddress((void**)&tmp_, g_tmp);
    cudaGetSymbolAddress((void**)&wos_, g_wosum);

    // dyn smem: (A 2 bufs + B 2 bufs) x (hi+lo): 128 & BN rows, 20 u32 stride
    const int SM128 = (4 * 128 * 20 + 4 * 128 * 20) * 4;   // 81920 B
    const int SM64  = (4 * 128 * 20 + 4 * 64  * 20) * 4;   // 61440 B
    cudaFuncSetAttribute(mgemm_db<4, 128>, cudaFuncAttributeMaxDynamicSharedMemorySize, SM128);
    cudaFuncSetAttribute(mgemm_db<1, 128>, cudaFuncAttributeMaxDynamicSharedMemorySize, SM128);
    cudaFuncSetAttribute(mgemm_db<2, 128>, cudaFuncAttributeMaxDynamicSharedMemorySize, SM128);
    cudaFuncSetAttribute(mgemm_db<0, 64>,  cudaFuncAttributeMaxDynamicSharedMemorySize, SM64);

    detect_idx<<<1, 64>>>(x);
    convert_weights<<<(W_TOT + 255) / 256, 256>>>(wq, wk, wv, mlp0, mlp1, unemb);
    compute_wosum_all<<<(NL * DKk * DM + 255) / 256, 256>>>(wo);
    embed_ln_w<<<BT / 8, 256>>>(x, emb, pos);

    for (int l = 0; l < NL; l++) {
        const unsigned* wqkv_h = wh_ + (size_t)(l * 3) * DM * KP_DM;
        const unsigned* wqkv_l = wl_ + (size_t)(l * 3) * DM * KP_DM;
        const unsigned* m0h = wh_ + W_M0 + (size_t)l * DHid * KP_DM;
        const unsigned* m0l = wl_ + W_M0 + (size_t)l * DHid * KP_DM;
        const unsigned* m1h = wh_ + W_M1 + (size_t)l * DM * KP_HID;
        const unsigned* m1l = wl_ + W_M1 + (size_t)l * DM * KP_HID;

        mgemm_db<4, 128><<<dim3(6, BT / 128), 256, SM128>>>(
            hh_, hl_, wqkv_h, wqkv_l, v_, qh_, ql_, kh_, kl_, nullptr, BT, DM, KP_DM);
        pack_v<<<dim3(TT / 64, BB * HH), 256>>>(v_, vth_, vtl_);

        attention_mma2<<<dim3(TT / 128, BB * HH), 256>>>(qh_, ql_, kh_, kl_, vth_, vtl_, ov_);
        attn_out_ln_w<<<BT / 8, 256>>>(ov_, wos_ + (size_t)l * DKk * DM);

        mgemm_db<1, 128><<<dim3(DHid / 128, BT / 128), 256, SM128>>>(
            hh_, hl_, m0h, m0l, nullptr, yh_, yl_, nullptr, nullptr,
            mlpb + (size_t)l * DHid, BT, DHid, KP_DM);
        mgemm_db<0, 64><<<dim3(DM / 64, BT / 128), 256, SM64>>>(
            yh_, yl_, m1h, m1l, tmp_, nullptr, nullptr, nullptr, nullptr,
            nullptr, BT, DM, KP_HID);
        ln_residual_w<<<BT / 8, 256>>>(tmp_);
    }

    mgemm_db<2, 128><<<dim3(ND / 128, BT / 128), 256, SM128>>>(
        hh_, hl_, wh_ + W_UE, wl_ + W_UE, out, nullptr, nullptr, nullptr, nullptr,
        bias, BT, ND, KP_DM);
}

// round 9
// speedup vs baseline: 1.0457x; 1.0457x over previous
#include <cuda_runtime.h>
#include <cuda_bf16.h>
#include <math.h>

#define BB 4
#define TT 2048
#define BT (BB*TT)
#define DM 256
#define HH 8
#define DKk 32
#define DHid 1024
#define ND 8192
#define NL 4

#define KP_DM (DM/2)      // 128 pairs
#define KP_HID (DHid/2)   // 512 pairs

// packed-weight region offsets (u32 elements); B operands stored kp-major [KP][N]
#define W_M0 (NL*3*DM*KP_DM)
#define W_M1 (W_M0 + NL*DHid*KP_DM)
#define W_UE (W_M1 + NL*DM*KP_HID)
#define W_TOT (W_UE + ND*KP_DM)

// -------------------- scratch (device globals) ---------------------------------
__device__ float    g_h  [BT*DM];
__device__ unsigned g_hh [BT*KP_DM];
__device__ unsigned g_hl [BT*KP_DM];
__device__ unsigned g_qh [BT*KP_DM];
__device__ unsigned g_ql [BT*KP_DM];
__device__ unsigned g_kh [BT*KP_DM];
__device__ unsigned g_kl [BT*KP_DM];
__device__ unsigned g_vth[BT*KP_DM];   // V transposed+packed: [bh][vd0..31][kp]
__device__ unsigned g_vtl[BT*KP_DM];
__device__ float    g_ov [BT*DM];
__device__ unsigned g_yh [BT*KP_HID];
__device__ unsigned g_yl [BT*KP_HID];
__device__ float    g_tmp[BT*DM];
__device__ unsigned g_wh [W_TOT];
__device__ unsigned g_wl [W_TOT];
__device__ float    g_wosum[NL*DKk*DM];
__device__ int      g_is64;

// -------------------- helpers -------------------------------------------------
// fp32 pair -> packed bf16x2 hi + bf16x2 residual lo. 6 instructions, RN
// everywhere (bit-identical to the __float2bfloat16 version).
__device__ __forceinline__ void pack_hilo(float x, float y, unsigned& hi, unsigned& lo) {
    unsigned h;
    asm("cvt.rn.bf16x2.f32 %0, %1, %2;" : "=r"(h) : "f"(y), "f"(x));
    float xr = x - __uint_as_float(h << 16);
    float yr = y - __uint_as_float(h & 0xffff0000u);
    asm("cvt.rn.bf16x2.f32 %0, %1, %2;" : "=r"(lo) : "f"(yr), "f"(xr));
    hi = h;
}

__device__ __forceinline__ void mma16816(float* c, const unsigned* a, const unsigned* b) {
    asm volatile(
        "mma.sync.aligned.m16n8k16.row.col.f32.bf16.bf16.f32 "
        "{%0,%1,%2,%3}, {%4,%5,%6,%7}, {%8,%9}, {%0,%1,%2,%3};\n"
        : "+f"(c[0]), "+f"(c[1]), "+f"(c[2]), "+f"(c[3])
        : "r"(a[0]), "r"(a[1]), "r"(a[2]), "r"(a[3]), "r"(b[0]), "r"(b[1]));
}

__device__ __forceinline__ void cp16(void* sdst, const void* gsrc) {
    unsigned sa = (unsigned)__cvta_generic_to_shared(sdst);
    asm volatile("cp.async.cg.shared.global [%0], [%1], 16;\n" :: "r"(sa), "l"(gsrc));
}
#define CP_COMMIT() asm volatile("cp.async.commit_group;\n" ::: "memory")
template <int N> __device__ __forceinline__ void cp_wait() {
    asm volatile("cp.async.wait_group %0;\n" :: "n"(N) : "memory");
}

__device__ __forceinline__ float warp_sum(float v) {
    #pragma unroll
    for (int o = 16; o; o >>= 1) v += __shfl_xor_sync(0xffffffffu, v, o);
    return v;
}

// FMA-pipe exp (deg-5 2^f poly, rel err ~2e-6); offloads the MUFU pipe.
__device__ __forceinline__ float fast_exp(float x) {
    float t = x * 1.44269504f;
    float fi = rintf(t);
    float f = t - fi;
    int ei = __float2int_rn(fi);
    float p = 1.33336e-3f;
    p = fmaf(p, f, 9.61813e-3f);
    p = fmaf(p, f, 5.55041e-2f);
    p = fmaf(p, f, 2.40227e-1f);
    p = fmaf(p, f, 6.93147e-1f);
    p = fmaf(p, f, 1.0f);
    return __uint_as_float((unsigned)((ei + 127) << 23)) * p;
}

// -------------------- index dtype probe ---------------------------------------
__global__ void detect_idx(const int* __restrict__ xi) {
    __shared__ int ok;
    if (threadIdx.x == 0) ok = 1;
    __syncthreads();
    if (xi[2 * threadIdx.x + 1] != 0) atomicAnd(&ok, 0);
    __syncthreads();
    if (threadIdx.x == 0) g_is64 = ok;
}

// -------------------- one-shot weight pre-conversion (kp-major) ----------------
__global__ __launch_bounds__(256) void convert_weights(
    const float* __restrict__ wq, const float* __restrict__ wk,
    const float* __restrict__ wv, const float* __restrict__ m0,
    const float* __restrict__ m1, const float* __restrict__ ue) {
    int i = blockIdx.x * 256 + threadIdx.x;
    if (i >= W_TOT) return;
    float a, b;
    if (i < W_M0) {                       // QKV per-head [n/32][k][n%32] source
        int l3 = i >> 15;
        int r  = i & 32767;
        int kp = r >> 8;
        int n  = r & 255;
        int l = l3 / 3, mi = l3 % 3;
        const float* W = (mi == 0) ? wq : (mi == 1) ? wk : wv;
        size_t base = (size_t)l * HH * DM * DKk + (size_t)(n >> 5) * DM * DKk + (n & 31);
        a = W[base + (size_t)(2 * kp)     * DKk];
        b = W[base + (size_t)(2 * kp + 1) * DKk];
    } else if (i < W_M1) {
        int r = i - W_M0;
        int l = r >> 17;
        int rr = r & 131071;
        int kp = rr >> 10;
        int n  = rr & 1023;
        const float* W = m0 + (size_t)l * DM * DHid;
        a = W[(size_t)(2 * kp)     * DHid + n];
        b = W[(size_t)(2 * kp + 1) * DHid + n];
    } else if (i < W_UE) {
        int r = i - W_M1;
        int l = r >> 17;
        int rr = r & 131071;
        int kp = rr >> 8;
        int n  = rr & 255;
        const float* W = m1 + (size_t)l * DHid * DM;
        a = W[(size_t)(2 * kp)     * DM + n];
        b = W[(size_t)(2 * kp + 1) * DM + n];
    } else {
        int r = i - W_UE;
        int kp = r >> 13;
        int n  = r & 8191;
        a = ue[(size_t)(2 * kp)     * ND + n];
        b = ue[(size_t)(2 * kp + 1) * ND + n];
    }
    unsigned hi, lo;
    pack_hilo(a, b, hi, lo);
    g_wh[i] = hi;
    g_wl[i] = lo;
}

// -------------------- wo summed over heads, all layers -------------------------
__global__ void compute_wosum_all(const float* __restrict__ wo) {
    int i = blockIdx.x * 256 + threadIdx.x;
    if (i < NL * DKk * DM) {
        int l = i / (DKk * DM);
        int r = i % (DKk * DM);
        float s = 0.f;
        #pragma unroll
        for (int hh = 0; hh < HH; hh++)
            s += wo[(size_t)l * HH * DKk * DM + (size_t)hh * DKk * DM + r];
        g_wosum[i] = s;
    }
}

// -------------------- warp-per-token LN core -----------------------------------
__device__ __forceinline__ void ln_store_warp(int token, int lane, float* val) {
    float s = 0.f;
    #pragma unroll
    for (int j = 0; j < 8; j++) s += val[j];
    s = warp_sum(s);
    float m = s * (1.f / DM);
    float vv = 0.f;
    #pragma unroll
    for (int j = 0; j < 8; j++) { val[j] -= m; vv += val[j] * val[j]; }
    vv = warp_sum(vv);
    float inv = rsqrtf(vv * (1.f / DM) + 1e-5f);
    #pragma unroll
    for (int j = 0; j < 8; j++) {
        float out = val[j] * inv;
        int d = j * 32 + lane;
        g_h[(size_t)token * DM + d] = out;
        float other = __shfl_xor_sync(0xffffffffu, out, 1);
        if (!(lane & 1)) {
            unsigned hi, lo;
            pack_hilo(out, other, hi, lo);
            g_hh[(size_t)token * KP_DM + j * 16 + (lane >> 1)] = hi;
            g_hl[(size_t)token * KP_DM + j * 16 + (lane >> 1)] = lo;
        }
    }
}

__global__ __launch_bounds__(256) void embed_ln_w(const int* __restrict__ xi,
                                                  const float* __restrict__ emb,
                                                  const float* __restrict__ pos) {
    int token = blockIdx.x * 8 + (threadIdx.x >> 5);
    int lane = threadIdx.x & 31;
    int t = token % TT;
    int idx = g_is64 ? xi[2 * token] : xi[token];
    float val[8];
    #pragma unroll
    for (int j = 0; j < 8; j++) {
        int d = j * 32 + lane;
        val[j] = emb[(size_t)idx * DM + d] + pos[(size_t)t * DM + d];
    }
    ln_store_warp(token, lane, val);
}

__global__ __launch_bounds__(256) void attn_out_ln_w(const float* __restrict__ ov,
                                                     const float* __restrict__ wos) {
    int token = blockIdx.x * 8 + (threadIdx.x >> 5);
    int lane = threadIdx.x & 31;
    float vs = 0.f;
    float val[8];
    #pragma unroll
    for (int j = 0; j < 8; j++) {
        float o = ov[(size_t)token * DM + j * 32 + lane];
        vs += o;
        val[j] = g_h[(size_t)token * DM + j * 32 + lane];
    }
    #pragma unroll
    for (int v = 0; v < DKk; v++) {
        float sv = __shfl_sync(0xffffffffu, vs, v);
        #pragma unroll
        for (int j = 0; j < 8; j++) val[j] += sv * wos[v * DM + j * 32 + lane];
    }
    ln_store_warp(token, lane, val);
}

__global__ __launch_bounds__(256) void ln_residual_w(const float* __restrict__ add) {
    int token = blockIdx.x * 8 + (threadIdx.x >> 5);
    int lane = threadIdx.x & 31;
    float val[8];
    #pragma unroll
    for (int j = 0; j < 8; j++) {
        int d = j * 32 + lane;
        val[j] = g_h[(size_t)token * DM + d] + add[(size_t)token * DM + d];
    }
    ln_store_warp(token, lane, val);
}

// -------------------- packed GEMM: R7 structure (scalar LDS, cp.async 2-buf) ---
// 256 threads, 8 warps (4 in m x 2 in n), 32x(BN/2) warp tiles.
// A [M][KP] hi/lo.  B kp-major [KP][N] hi/lo.
// EPI 0: fp32. 1: relu(acc+bias)->packed. 2: acc+bias fp32.
// EPI 4: fused QKV; q->Ch/Cl, k->Ch2/Cl2, v-> packed transposed Vh/Vl.
template <int EPI, int BN>
__global__ __launch_bounds__(256, 2) void mgemm_db(
    const unsigned* __restrict__ Ah, const unsigned* __restrict__ Al,
    const unsigned* __restrict__ Bh, const unsigned* __restrict__ Bl,
    float* __restrict__ C, unsigned* __restrict__ Ch, unsigned* __restrict__ Cl,
    unsigned* __restrict__ Ch2, unsigned* __restrict__ Cl2,
    unsigned* __restrict__ Vh, unsigned* __restrict__ Vl,
    const float* __restrict__ bias, int M, int N, int KP) {
    constexpr int NT = BN / 16;
    constexpr int BSTR = BN + 4;            // B row stride (u32)
    constexpr int BS = 16 * BSTR;           // one B buffer (u32)
    extern __shared__ unsigned smp[];
    unsigned* AsH = smp;                    // [2][128][20]
    unsigned* AsL = smp + 5120;
    unsigned* BsH = smp + 10240;            // [2][16][BSTR]
    unsigned* BsL = BsH + 2 * BS;

    const int bm = blockIdx.y * 128;
    int bn, mat = 0;
    if (EPI == 4) {
        mat = blockIdx.x >> 1;
        bn = (blockIdx.x & 1) * 128;
        Bh += (size_t)mat * DM * KP_DM;
        Bl += (size_t)mat * DM * KP_DM;
    } else {
        bn = blockIdx.x * BN;
    }
    const int tid  = threadIdx.x;
    const int lane = tid & 31;
    const int wid  = tid >> 5;
    const int g = lane >> 2;
    const int t = lane & 3;
    const int wm = (wid & 3) * 32;
    const int wn = (wid >> 2) * (BN / 2);

    float acc[2][NT][4];
    #pragma unroll
    for (int mt = 0; mt < 2; mt++)
        #pragma unroll
        for (int nt = 0; nt < NT; nt++)
            #pragma unroll
            for (int r = 0; r < 4; r++) acc[mt][nt][r] = 0.f;

    #define FILL_TILE(s, kp0)                                                       \
        do {                                                                         \
            _Pragma("unroll")                                                        \
            for (int it_ = 0; it_ < 2; it_++) {                                      \
                int i_ = it_ * 256 + tid;                                            \
                int m_ = i_ >> 2, c4_ = (i_ & 3) * 4;                                \
                size_t ga_ = (size_t)(bm + m_) * KP + (kp0) + c4_;                   \
                cp16(&AsH[(s) * 2560 + m_ * 20 + c4_], Ah + ga_);                    \
                cp16(&AsL[(s) * 2560 + m_ * 20 + c4_], Al + ga_);                    \
            }                                                                        \
            _Pragma("unroll")                                                        \
            for (int it_ = 0; it_ < BN / 64; it_++) {                                \
                int i_ = it_ * 256 + tid;                                            \
                int kp_ = i_ / (BN / 4), n4_ = (i_ % (BN / 4)) * 4;                  \
                size_t gb_ = (size_t)((kp0) + kp_) * N + bn + n4_;                   \
                cp16(&BsH[(s) * BS + kp_ * BSTR + n4_], Bh + gb_);                   \
                cp16(&BsL[(s) * BS + kp_ * BSTR + n4_], Bl + gb_);                   \
            }                                                                        \
        } while (0)

    const int NKT = KP / 16;
    FILL_TILE(0, 0);
    CP_COMMIT();

    for (int kt = 0; kt < NKT; kt++) {
        const int s = kt & 1;
        if (kt + 1 < NKT) {
            FILL_TILE(s ^ 1, (kt + 1) * 16);
            CP_COMMIT();
            cp_wait<1>();
        } else {
            cp_wait<0>();
        }
        __syncthreads();

        #pragma unroll
        for (int ks = 0; ks < 2; ks++) {
            const int cb = ks * 8 + t;
            unsigned ah[2][4], al[2][4];
            #pragma unroll
            for (int mt = 0; mt < 2; mt++) {
                int r = wm + mt * 16;
                const unsigned* aH = AsH + s * 2560;
                const unsigned* aL = AsL + s * 2560;
                ah[mt][0] = aH[(r + g    ) * 20 + cb];
                ah[mt][1] = aH[(r + g + 8) * 20 + cb];
                ah[mt][2] = aH[(r + g    ) * 20 + cb + 4];
                ah[mt][3] = aH[(r + g + 8) * 20 + cb + 4];
                al[mt][0] = aL[(r + g    ) * 20 + cb];
                al[mt][1] = aL[(r + g + 8) * 20 + cb];
                al[mt][2] = aL[(r + g    ) * 20 + cb + 4];
                al[mt][3] = aL[(r + g + 8) * 20 + cb + 4];
            }
            const unsigned* bH = BsH + s * BS;
            const unsigned* bL = BsL + s * BS;
            #pragma unroll
            for (int nt = 0; nt < NT; nt++) {
                int col = wn + nt * 8 + g;
                unsigned bh[2], bl[2];
                bh[0] = bH[cb * BSTR + col];       bh[1] = bH[(cb + 4) * BSTR + col];
                bl[0] = bL[cb * BSTR + col];       bl[1] = bL[(cb + 4) * BSTR + col];
                #pragma unroll
                for (int mt = 0; mt < 2; mt++) {
                    mma16816(acc[mt][nt], ah[mt], bh);
                    mma16816(acc[mt][nt], ah[mt], bl);
                    mma16816(acc[mt][nt], al[mt], bh);
                }
            }
        }
        __syncthreads();
    }
    #undef FILL_TILE

    #pragma unroll
    for (int mt = 0; mt < 2; mt++) {
        #pragma unroll
        for (int nt = 0; nt < NT; nt++) {
            int row0 = bm + wm + mt * 16 + g;
            int col  = bn + wn + nt * 8 + 2 * t;
            float v0 = acc[mt][nt][0], v1 = acc[mt][nt][1];
            float v2 = acc[mt][nt][2], v3 = acc[mt][nt][3];
            if (EPI == 1) {
                float b0 = bias[col], b1 = bias[col + 1];
                v0 = fmaxf(v0 + b0, 0.f); v1 = fmaxf(v1 + b1, 0.f);
                v2 = fmaxf(v2 + b0, 0.f); v3 = fmaxf(v3 + b1, 0.f);
            }
            if (EPI == 2) {
                float b0 = bias[col], b1 = bias[col + 1];
                v0 += b0; v1 += b1; v2 += b0; v3 += b1;
            }
            if (EPI == 4 && mat == 2) {
                // V: pack token pairs (rows g even/odd are 4 lanes apart) and
                // write transposed [bh][vd][kp] directly.
                float p0 = __shfl_xor_sync(0xffffffffu, v0, 4);
                float p1 = __shfl_xor_sync(0xffffffffu, v1, 4);
                float p2 = __shfl_xor_sync(0xffffffffu, v2, 4);
                float p3 = __shfl_xor_sync(0xffffffffu, v3, 4);
                if (!(g & 1)) {
                    int bb = row0 >> 11;
                    int tt = row0 & (TT - 1);
                    int h  = col >> 5, vd = col & 31;
                    size_t base = ((size_t)(bb * HH + h) * DKk + vd) * (TT / 2) + (tt >> 1);
                    unsigned hi, lo;
                    pack_hilo(v0, p0, hi, lo);
                    Vh[base] = hi;                    Vl[base] = lo;
                    pack_hilo(v1, p1, hi, lo);
                    Vh[base + TT / 2] = hi;           Vl[base + TT / 2] = lo;
                    pack_hilo(v2, p2, hi, lo);
                    Vh[base + 4] = hi;                Vl[base + 4] = lo;
                    pack_hilo(v3, p3, hi, lo);
                    Vh[base + TT / 2 + 4] = hi;       Vl[base + TT / 2 + 4] = lo;
                }
            } else if (EPI == 0 || EPI == 2) {
                *(float2*)(C + (size_t)row0 * N + col)       = make_float2(v0, v1);
                *(float2*)(C + (size_t)(row0 + 8) * N + col) = make_float2(v2, v3);
            } else {
                unsigned* Dh = (EPI == 4 && mat == 1) ? Ch2 : Ch;
                unsigned* Dl = (EPI == 4 && mat == 1) ? Cl2 : Cl;
                unsigned h0, l0, h1, l1;
                pack_hilo(v0, v1, h0, l0);
                pack_hilo(v2, v3, h1, l1);
                int NP = N >> 1, cp = col >> 1;
                Dh[(size_t)row0 * NP + cp]       = h0;
                Dl[(size_t)row0 * NP + cp]       = l0;
                Dh[(size_t)(row0 + 8) * NP + cp] = h1;
                Dl[(size_t)(row0 + 8) * NP + cp] = l1;
            }
        }
    }
}

// -------------------- tensor-core causal attention (hybrid exp) ----------------
__global__ __launch_bounds__(256, 2) void attention_mma2(
    const unsigned* __restrict__ qh, const unsigned* __restrict__ ql,
    const unsigned* __restrict__ kh, const unsigned* __restrict__ kl,
    const unsigned* __restrict__ vth, const unsigned* __restrict__ vtl,
    float* __restrict__ ov) {
    __shared__ unsigned Ks_hi[2][64][20];
    __shared__ unsigned Ks_lo[2][64][20];
    __shared__ unsigned Vs_hi[2][32][36];
    __shared__ unsigned Vs_lo[2][32][36];

    const int bh = blockIdx.y;
    const int b  = bh >> 3, h = bh & 7;
    const int t0 = (gridDim.x - 1 - blockIdx.x) * 128;
    const int tid  = threadIdx.x;
    const int lane = tid & 31;
    const int wid  = tid >> 5;
    const int g = lane >> 2;
    const int t = lane & 3;
    const int wm = wid * 16;

    unsigned qfh[2][4], qfl[2][4];
    {
        size_t base = (size_t)(b * TT + t0 + wm) * KP_DM + h * 16;
        #pragma unroll
        for (int ks = 0; ks < 2; ks++) {
            qfh[ks][0] = qh[base + (size_t)g * KP_DM + ks * 8 + t];
            qfh[ks][1] = qh[base + (size_t)(g + 8) * KP_DM + ks * 8 + t];
            qfh[ks][2] = qh[base + (size_t)g * KP_DM + ks * 8 + t + 4];
            qfh[ks][3] = qh[base + (size_t)(g + 8) * KP_DM + ks * 8 + t + 4];
            qfl[ks][0] = ql[base + (size_t)g * KP_DM + ks * 8 + t];
            qfl[ks][1] = ql[base + (size_t)(g + 8) * KP_DM + ks * 8 + t];
            qfl[ks][2] = ql[base + (size_t)g * KP_DM + ks * 8 + t + 4];
            qfl[ks][3] = ql[base + (size_t)(g + 8) * KP_DM + ks * 8 + t + 4];
        }
    }

    float o[4][4];
    #pragma unroll
    for (int nf = 0; nf < 4; nf++)
        #pragma unroll
        for (int r = 0; r < 4; r++) o[nf][r] = 0.f;
    float rs0 = 0.f, rs1 = 0.f;

    const int row0 = t0 + wm + g;
    const int row1 = row0 + 8;
    const int nit = t0 / 64 + 2;

    const int kkey = tid >> 2, kseg = tid & 3;
    const int vvd  = tid >> 3, vseg = tid & 7;

    #define ISSUE_TILE(s, o0)                                                        \
        do {                                                                          \
            size_t kgi = (size_t)(b * TT + (o0) + kkey) * KP_DM + h * 16 + kseg * 4;  \
            cp16(&Ks_hi[s][kkey][kseg * 4], kh + kgi);                                \
            cp16(&Ks_lo[s][kkey][kseg * 4], kl + kgi);                                \
            size_t vgi = ((size_t)bh * DKk + vvd) * (TT / 2) + ((o0) >> 1) + vseg * 4;\
            cp16(&Vs_hi[s][vvd][vseg * 4], vth + vgi);                                \
            cp16(&Vs_lo[s][vvd][vseg * 4], vtl + vgi);                                \
        } while (0)

    ISSUE_TILE(0, 0);
    CP_COMMIT();

    for (int it = 0; it < nit; it++) {
        const int o0 = it * 64;
        const int s = it & 1;
        if (it + 1 < nit) {
            ISSUE_TILE(s ^ 1, o0 + 64);
            CP_COMMIT();
            cp_wait<1>();
        } else {
            cp_wait<0>();
        }
        __syncthreads();

        if (o0 <= t0 + wm + 15) {
            float c[8][4];
            #pragma unroll
            for (int j = 0; j < 8; j++)
                #pragma unroll
                for (int r = 0; r < 4; r++) c[j][r] = 0.f;
            #pragma unroll
            for (int j = 0; j < 8; j++) {
                int col = j * 8 + g;
                #pragma unroll
                for (int ks = 0; ks < 2; ks++) {
                    unsigned bhf[2], blf[2];
                    bhf[0] = Ks_hi[s][col][ks * 8 + t];
                    bhf[1] = Ks_hi[s][col][ks * 8 + t + 4];
                    blf[0] = Ks_lo[s][col][ks * 8 + t];
                    blf[1] = Ks_lo[s][col][ks * 8 + t + 4];
                    mma16816(c[j], qfh[ks], bhf);
                    mma16816(c[j], qfh[ks], blf);
                    mma16816(c[j], qfl[ks], bhf);
                }
            }
            // exp (hybrid: 2/8 groups on FMA-pipe poly, rest MUFU) + rowsum.
            // Interior tiles (all keys below both rows) skip the mask selects.
            if (o0 + 63 <= t0 + wm) {
                #pragma unroll
                for (int j = 0; j < 8; j++) {
                    if (j < 2) {
                        c[j][0] = fast_exp(fmaxf(fminf(c[j][0], 50.f), -80.f));
                        c[j][1] = fast_exp(fmaxf(fminf(c[j][1], 50.f), -80.f));
                        c[j][2] = fast_exp(fmaxf(fminf(c[j][2], 50.f), -80.f));
                        c[j][3] = fast_exp(fmaxf(fminf(c[j][3], 50.f), -80.f));
                    } else {
                        c[j][0] = __expf(fminf(c[j][0], 50.f));
                        c[j][1] = __expf(fminf(c[j][1], 50.f));
                        c[j][2] = __expf(fminf(c[j][2], 50.f));
                        c[j][3] = __expf(fminf(c[j][3], 50.f));
                    }
                    rs0 += c[j][0] + c[j][1];
                    rs1 += c[j][2] + c[j][3];
                }
            } else {
                #pragma unroll
                for (int j = 0; j < 8; j++) {
                    int cb = o0 + j * 8 + 2 * t;
                    float e0, e1, e2, e3;
                    if (j < 2) {
                        e0 = fast_exp(fmaxf(fminf(c[j][0], 50.f), -80.f));
                        e1 = fast_exp(fmaxf(fminf(c[j][1], 50.f), -80.f));
                        e2 = fast_exp(fmaxf(fminf(c[j][2], 50.f), -80.f));
                        e3 = fast_exp(fmaxf(fminf(c[j][3], 50.f), -80.f));
                    } else {
                        e0 = __expf(fminf(c[j][0], 50.f));
                        e1 = __expf(fminf(c[j][1], 50.f));
                        e2 = __expf(fminf(c[j][2], 50.f));
                        e3 = __expf(fminf(c[j][3], 50.f));
                    }
                    c[j][0] = (cb     <= row0) ? e0 : 0.f;
                    c[j][1] = (cb + 1 <= row0) ? e1 : 0.f;
                    c[j][2] = (cb     <= row1) ? e2 : 0.f;
                    c[j][3] = (cb + 1 <= row1) ? e3 : 0.f;
                    rs0 += c[j][0] + c[j][1];
                    rs1 += c[j][2] + c[j][3];
                }
            }
            // O += P V
            #pragma unroll
            for (int klq = 0; klq < 4; klq++) {
                unsigned ph[4], pl[4];
                pack_hilo(c[2 * klq][0],     c[2 * klq][1],     ph[0], pl[0]);
                pack_hilo(c[2 * klq][2],     c[2 * klq][3],     ph[1], pl[1]);
                pack_hilo(c[2 * klq + 1][0], c[2 * klq + 1][1], ph[2], pl[2]);
                pack_hilo(c[2 * klq + 1][2], c[2 * klq + 1][3], ph[3], pl[3]);
                int kb = klq * 8;
                #pragma unroll
                for (int nf = 0; nf < 4; nf++) {
                    int vc = nf * 8 + g;
                    unsigned vhf[2], vlf[2];
                    vhf[0] = Vs_hi[s][vc][kb + t];
                    vhf[1] = Vs_hi[s][vc][kb + t + 4];
                    vlf[0] = Vs_lo[s][vc][kb + t];
                    vlf[1] = Vs_lo[s][vc][kb + t + 4];
                    mma16816(o[nf], ph, vhf);
                    mma16816(o[nf], ph, vlf);
                    mma16816(o[nf], pl, vhf);
                }
            }
        }
        __syncthreads();
    }
    #undef ISSUE_TILE

    rs0 += __shfl_xor_sync(0xffffffffu, rs0, 1);
    rs0 += __shfl_xor_sync(0xffffffffu, rs0, 2);
    rs1 += __shfl_xor_sync(0xffffffffu, rs1, 1);
    rs1 += __shfl_xor_sync(0xffffffffu, rs1, 2);
    float i0 = 1.f / (rs0 + 1e-10f);
    float i1 = 1.f / (rs1 + 1e-10f);
    size_t r0 = (size_t)(b * TT + row0);
    #pragma unroll
    for (int nf = 0; nf < 4; nf++) {
        int vd = h * DKk + nf * 8 + 2 * t;
        *(float2*)(ov + r0 * DM + vd)       = make_float2(o[nf][0] * i0, o[nf][1] * i0);
        *(float2*)(ov + (r0 + 8) * DM + vd) = make_float2(o[nf][2] * i1, o[nf][3] * i1);
    }
}

// -------------------- launch --------------------------------------------------
extern "C" void kernel_launch(void* const* d_in, const int* in_sizes, int n_in,
                              void* d_out, int out_size) {
    const int*   x     = (const int*)  d_in[0];
    const float* emb   = (const float*)d_in[1];
    const float* pos   = (const float*)d_in[2];
    const float* wq    = (const float*)d_in[3];
    const float* wk    = (const float*)d_in[4];
    const float* wv    = (const float*)d_in[5];
    const float* wo    = (const float*)d_in[6];
    const float* mlp0  = (const float*)d_in[7];
    const float* mlpb  = (const float*)d_in[8];
    const float* mlp1  = (const float*)d_in[9];
    const float* unemb = (const float*)d_in[10];
    const float* bias  = (const float*)d_in[11];
    float* out = (float*)d_out;

    unsigned *hh_, *hl_, *qh_, *ql_, *kh_, *kl_, *yh_, *yl_, *wh_, *wl_, *vth_, *vtl_;
    float *ov_, *tmp_, *wos_;
    cudaGetSymbolAddress((void**)&hh_, g_hh);
    cudaGetSymbolAddress((void**)&hl_, g_hl);
    cudaGetSymbolAddress((void**)&qh_, g_qh);
    cudaGetSymbolAddress((void**)&ql_, g_ql);
    cudaGetSymbolAddress((void**)&kh_, g_kh);
    cudaGetSymbolAddress((void**)&kl_, g_kl);
    cudaGetSymbolAddress((void**)&yh_, g_yh);
    cudaGetSymbolAddress((void**)&yl_, g_yl);
    cudaGetSymbolAddress((void**)&wh_, g_wh);
    cudaGetSymbolAddress((void**)&wl_, g_wl);
    cudaGetSymbolAddress((void**)&vth_, g_vth);
    cudaGetSymbolAddress((void**)&vtl_, g_vtl);
    cudaGetSymbolAddress((void**)&ov_,  g_ov);
    cudaGetSymbolAddress((void**)&tmp_, g_tmp);
    cudaGetSymbolAddress((void**)&wos_, g_wosum);

    // dyn smem: A 2*2560*2 u32 + B 2*16*(BN+4)*2 u32
    const int SM128 = (10240 + 2 * 16 * 132 * 2) * 4;   // 74752 B
    const int SM64  = (10240 + 2 * 16 * 68  * 2) * 4;   // 58368 B
    cudaFuncSetAttribute(mgemm_db<4, 128>, cudaFuncAttributeMaxDynamicSharedMemorySize, SM128);
    cudaFuncSetAttribute(mgemm_db<1, 128>, cudaFuncAttributeMaxDynamicSharedMemorySize, SM128);
    cudaFuncSetAttribute(mgemm_db<2, 128>, cudaFuncAttributeMaxDynamicSharedMemorySize, SM128);
    cudaFuncSetAttribute(mgemm_db<0, 64>,  cudaFuncAttributeMaxDynamicSharedMemorySize, SM64);

    detect_idx<<<1, 64>>>(x);
    convert_weights<<<(W_TOT + 255) / 256, 256>>>(wq, wk, wv, mlp0, mlp1, unemb);
    compute_wosum_all<<<(NL * DKk * DM + 255) / 256, 256>>>(wo);
    embed_ln_w<<<BT / 8, 256>>>(x, emb, pos);

    for (int l = 0; l < NL; l++) {
        const unsigned* wqkv_h = wh_ + (size_t)(l * 3) * DM * KP_DM;
        const unsigned* wqkv_l = wl_ + (size_t)(l * 3) * DM * KP_DM;
        const unsigned* m0h = wh_ + W_M0 + (size_t)l * DHid * KP_DM;
        const unsigned* m0l = wl_ + W_M0 + (size_t)l * DHid * KP_DM;
        const unsigned* m1h = wh_ + W_M1 + (size_t)l * DM * KP_HID;
        const unsigned* m1l = wl_ + W_M1 + (size_t)l * DM * KP_HID;

        mgemm_db<4, 128><<<dim3(6, BT / 128), 256, SM128>>>(
            hh_, hl_, wqkv_h, wqkv_l, nullptr, qh_, ql_, kh_, kl_, vth_, vtl_,
            nullptr, BT, DM, KP_DM);

        attention_mma2<<<dim3(TT / 128, BB * HH), 256>>>(qh_, ql_, kh_, kl_, vth_, vtl_, ov_);
        attn_out_ln_w<<<BT / 8, 256>>>(ov_, wos_ + (size_t)l * DKk * DM);

        mgemm_db<1, 128><<<dim3(DHid / 128, BT / 128), 256, SM128>>>(
            hh_, hl_, m0h, m0l, nullptr, yh_, yl_, nullptr, nullptr, nullptr, nullptr,
            mlpb + (size_t)l * DHid, BT, DHid, KP_DM);
        mgemm_db<0, 64><<<dim3(DM / 64, BT / 128), 256, SM64>>>(
            yh_, yl_, m1h, m1l, tmp_, nullptr, nullptr, nullptr, nullptr, nullptr, nullptr,
            nullptr, BT, DM, KP_HID);
        ln_residual_w<<<BT / 8, 256>>>(tmp_);
    }

    mgemm_db<2, 128><<<dim3(ND / 128, BT / 128), 256, SM128>>>(
        hh_, hl_, wh_ + W_UE, wl_ + W_UE, out, nullptr, nullptr, nullptr, nullptr,
        nullptr, nullptr, bias, BT, ND, KP_DM);
}

// round 11
// speedup vs baseline: 1.1048x; 1.0565x over previous
#include <cuda_runtime.h>
#include <cuda_bf16.h>
#include <math.h>

#define BB 4
#define TT 2048
#define BT (BB*TT)
#define DM 256
#define HH 8
#define DKk 32
#define DHid 1024
#define ND 8192
#define NL 4

#define KP_DM (DM/2)      // 128 pairs
#define KP_HID (DHid/2)   // 512 pairs

// packed-weight regions (u32). All B operands stored FRAGMENT-MAJOR:
// tile = 8n x 8kp; u32 index = ((n>>3)*(KP>>3) + (kp>>3))*64
//                             + (4*(n&7)+(kp&3))*2 + ((kp>>2)&1)
#define W_M0 (NL*3*DM*KP_DM)
#define W_M1 (W_M0 + NL*DHid*KP_DM)
#define W_UE (W_M1 + NL*DM*KP_HID)
#define W_TOT (W_UE + ND*KP_DM)

// -------------------- scratch (device globals) ---------------------------------
__device__ float    g_h  [BT*DM];
__device__ unsigned g_hh [BT*KP_DM];
__device__ unsigned g_hl [BT*KP_DM];
__device__ unsigned g_qh [BT*KP_DM];
__device__ unsigned g_ql [BT*KP_DM];
__device__ unsigned g_kh [BT*KP_DM];
__device__ unsigned g_kl [BT*KP_DM];
__device__ unsigned g_vth[BT*KP_DM];   // V transposed+packed: [bh][vd0..31][kp]
__device__ unsigned g_vtl[BT*KP_DM];
__device__ float    g_ov [BT*DM];
__device__ unsigned g_yh [BT*KP_HID];
__device__ unsigned g_yl [BT*KP_HID];
__device__ float    g_tmp[BT*DM];
__device__ unsigned g_wh [W_TOT];
__device__ unsigned g_wl [W_TOT];
__device__ float    g_wosum[NL*DKk*DM];
__device__ int      g_is64;

// -------------------- helpers -------------------------------------------------
__device__ __forceinline__ void pack_hilo(float x, float y, unsigned& hi, unsigned& lo) {
    unsigned h;
    asm("cvt.rn.bf16x2.f32 %0, %1, %2;" : "=r"(h) : "f"(y), "f"(x));
    float xr = x - __uint_as_float(h << 16);
    float yr = y - __uint_as_float(h & 0xffff0000u);
    asm("cvt.rn.bf16x2.f32 %0, %1, %2;" : "=r"(lo) : "f"(yr), "f"(xr));
    hi = h;
}

__device__ __forceinline__ void mma16816(float* c, const unsigned* a, const unsigned* b) {
    asm volatile(
        "mma.sync.aligned.m16n8k16.row.col.f32.bf16.bf16.f32 "
        "{%0,%1,%2,%3}, {%4,%5,%6,%7}, {%8,%9}, {%0,%1,%2,%3};\n"
        : "+f"(c[0]), "+f"(c[1]), "+f"(c[2]), "+f"(c[3])
        : "r"(a[0]), "r"(a[1]), "r"(a[2]), "r"(a[3]), "r"(b[0]), "r"(b[1]));
}

__device__ __forceinline__ void cp16(void* sdst, const void* gsrc) {
    unsigned sa = (unsigned)__cvta_generic_to_shared(sdst);
    asm volatile("cp.async.cg.shared.global [%0], [%1], 16;\n" :: "r"(sa), "l"(gsrc));
}
#define CP_COMMIT() asm volatile("cp.async.commit_group;\n" ::: "memory")
template <int N> __device__ __forceinline__ void cp_wait() {
    asm volatile("cp.async.wait_group %0;\n" :: "n"(N) : "memory");
}

__device__ __forceinline__ float warp_sum(float v) {
    #pragma unroll
    for (int o = 16; o; o >>= 1) v += __shfl_xor_sync(0xffffffffu, v, o);
    return v;
}

__device__ __forceinline__ float fast_exp(float x) {
    float t = x * 1.44269504f;
    float fi = rintf(t);
    float f = t - fi;
    int ei = __float2int_rn(fi);
    float p = 1.33336e-3f;
    p = fmaf(p, f, 9.61813e-3f);
    p = fmaf(p, f, 5.55041e-2f);
    p = fmaf(p, f, 2.40227e-1f);
    p = fmaf(p, f, 6.93147e-1f);
    p = fmaf(p, f, 1.0f);
    return __uint_as_float((unsigned)((ei + 127) << 23)) * p;
}

// -------------------- index dtype probe ---------------------------------------
__global__ void detect_idx(const int* __restrict__ xi) {
    __shared__ int ok;
    if (threadIdx.x == 0) ok = 1;
    __syncthreads();
    if (xi[2 * threadIdx.x + 1] != 0) atomicAnd(&ok, 0);
    __syncthreads();
    if (threadIdx.x == 0) g_is64 = ok;
}

// -------------------- one-shot weight pre-conversion (fragment-major) ----------
__device__ __forceinline__ size_t frag_idx(int n, int kp, int kpt) {
    return ((size_t)(n >> 3) * kpt + (kp >> 3)) * 64
         + (size_t)((4 * (n & 7) + (kp & 3)) * 2 + ((kp >> 2) & 1));
}

__global__ __launch_bounds__(256) void convert_weights(
    const float* __restrict__ wq, const float* __restrict__ wk,
    const float* __restrict__ wv, const float* __restrict__ m0,
    const float* __restrict__ m1, const float* __restrict__ ue) {
    int i = blockIdx.x * 256 + threadIdx.x;
    if (i >= W_TOT) return;
    float a, b;
    size_t out;
    if (i < W_M0) {                       // QKV per-head [n/32][k][n%32] source
        int l3 = i >> 15;
        int r  = i & 32767;
        int kp = r >> 8;
        int n  = r & 255;
        int l = l3 / 3, mi = l3 % 3;
        const float* W = (mi == 0) ? wq : (mi == 1) ? wk : wv;
        size_t base = (size_t)l * HH * DM * DKk + (size_t)(n >> 5) * DM * DKk + (n & 31);
        a = W[base + (size_t)(2 * kp)     * DKk];
        b = W[base + (size_t)(2 * kp + 1) * DKk];
        out = (size_t)l3 * 32768 + frag_idx(n, kp, KP_DM / 8);
    } else if (i < W_M1) {                // mlp0 [k][1024]
        int r = i - W_M0;
        int l = r >> 17;
        int rr = r & 131071;
        int kp = rr >> 10;
        int n  = rr & 1023;
        const float* W = m0 + (size_t)l * DM * DHid;
        a = W[(size_t)(2 * kp)     * DHid + n];
        b = W[(size_t)(2 * kp + 1) * DHid + n];
        out = W_M0 + (size_t)l * 131072 + frag_idx(n, kp, KP_DM / 8);
    } else if (i < W_UE) {                // mlp1 [k][256]
        int r = i - W_M1;
        int l = r >> 17;
        int rr = r & 131071;
        int kp = rr >> 8;
        int n  = rr & 255;
        const float* W = m1 + (size_t)l * DHid * DM;
        a = W[(size_t)(2 * kp)     * DM + n];
        b = W[(size_t)(2 * kp + 1) * DM + n];
        out = W_M1 + (size_t)l * 131072 + frag_idx(n, kp, KP_HID / 8);
    } else {                              // unembedding [k][8192]
        int r = i - W_UE;
        int kp = r >> 13;
        int n  = r & 8191;
        a = ue[(size_t)(2 * kp)     * ND + n];
        b = ue[(size_t)(2 * kp + 1) * ND + n];
        out = W_UE + frag_idx(n, kp, KP_DM / 8);
    }
    unsigned hi, lo;
    pack_hilo(a, b, hi, lo);
    g_wh[out] = hi;
    g_wl[out] = lo;
}

// -------------------- wo summed over heads --------------------------------------
__global__ void compute_wosum_all(const float* __restrict__ wo) {
    int i = blockIdx.x * 256 + threadIdx.x;
    if (i < NL * DKk * DM) {
        int l = i / (DKk * DM);
        int r = i % (DKk * DM);
        float s = 0.f;
        #pragma unroll
        for (int hh = 0; hh < HH; hh++)
            s += wo[(size_t)l * HH * DKk * DM + (size_t)hh * DKk * DM + r];
        g_wosum[i] = s;
    }
}

// -------------------- warp-per-token LN ------------------------------------------
__device__ __forceinline__ void ln_store_warp(int token, int lane, float* val) {
    float s = 0.f;
    #pragma unroll
    for (int j = 0; j < 8; j++) s += val[j];
    s = warp_sum(s);
    float m = s * (1.f / DM);
    float vv = 0.f;
    #pragma unroll
    for (int j = 0; j < 8; j++) { val[j] -= m; vv += val[j] * val[j]; }
    vv = warp_sum(vv);
    float inv = rsqrtf(vv * (1.f / DM) + 1e-5f);
    #pragma unroll
    for (int j = 0; j < 8; j++) {
        float out = val[j] * inv;
        int d = j * 32 + lane;
        g_h[(size_t)token * DM + d] = out;
        float other = __shfl_xor_sync(0xffffffffu, out, 1);
        if (!(lane & 1)) {
            unsigned hi, lo;
            pack_hilo(out, other, hi, lo);
            g_hh[(size_t)token * KP_DM + j * 16 + (lane >> 1)] = hi;
            g_hl[(size_t)token * KP_DM + j * 16 + (lane >> 1)] = lo;
        }
    }
}

__global__ __launch_bounds__(256) void embed_ln_w(const int* __restrict__ xi,
                                                  const float* __restrict__ emb,
                                                  const float* __restrict__ pos) {
    int token = blockIdx.x * 8 + (threadIdx.x >> 5);
    int lane = threadIdx.x & 31;
    int t = token % TT;
    int idx = g_is64 ? xi[2 * token] : xi[token];
    float val[8];
    #pragma unroll
    for (int j = 0; j < 8; j++) {
        int d = j * 32 + lane;
        val[j] = emb[(size_t)idx * DM + d] + pos[(size_t)t * DM + d];
    }
    ln_store_warp(token, lane, val);
}

__global__ __launch_bounds__(256) void attn_out_ln_w(const float* __restrict__ ov,
                                                     const float* __restrict__ wos) {
    int token = blockIdx.x * 8 + (threadIdx.x >> 5);
    int lane = threadIdx.x & 31;
    float vs = 0.f;
    float val[8];
    #pragma unroll
    for (int j = 0; j < 8; j++) {
        float o = ov[(size_t)token * DM + j * 32 + lane];
        vs += o;
        val[j] = g_h[(size_t)token * DM + j * 32 + lane];
    }
    #pragma unroll
    for (int v = 0; v < DKk; v++) {
        float sv = __shfl_sync(0xffffffffu, vs, v);
        #pragma unroll
        for (int j = 0; j < 8; j++) val[j] += sv * wos[v * DM + j * 32 + lane];
    }
    ln_store_warp(token, lane, val);
}

__global__ __launch_bounds__(256) void ln_residual_w(const float* __restrict__ add) {
    int token = blockIdx.x * 8 + (threadIdx.x >> 5);
    int lane = threadIdx.x & 31;
    float val[8];
    #pragma unroll
    for (int j = 0; j < 8; j++) {
        int d = j * 32 + lane;
        val[j] = g_h[(size_t)token * DM + d] + add[(size_t)token * DM + d];
    }
    ln_store_warp(token, lane, val);
}

// -------------------- packed GEMM: scalar-LDS A, fragment-major B ----------------
// 256 threads, 8 warps (4 in m x 2 in n), 32x(BN/2) warp tiles.
// A [M][KP] hi/lo.  B fragment-major (8n x 8kp tiles of 64 u32).
// EPI 0: fp32. 1: relu(acc+bias)->packed. 2: acc+bias fp32.
// EPI 4: fused QKV; q->Ch/Cl, k->Ch2/Cl2, v-> packed transposed Vh/Vl.
template <int EPI, int BN>
__global__ __launch_bounds__(256, 2) void mgemm_db(
    const unsigned* __restrict__ Ah, const unsigned* __restrict__ Al,
    const unsigned* __restrict__ Bh, const unsigned* __restrict__ Bl,
    float* __restrict__ C, unsigned* __restrict__ Ch, unsigned* __restrict__ Cl,
    unsigned* __restrict__ Ch2, unsigned* __restrict__ Cl2,
    unsigned* __restrict__ Vh, unsigned* __restrict__ Vl,
    const float* __restrict__ bias, int M, int N, int KP) {
    constexpr int NT = BN / 16;
    constexpr int BS = 16 * BN;             // one B buffer (u32): BN/8 ntiles x 2 kc x 64
    extern __shared__ unsigned smq[];
    unsigned* AsH = smq;                    // [2][128][20]
    unsigned* AsL = smq + 5120;
    unsigned* BsH = smq + 10240;            // [2][BS]
    unsigned* BsL = BsH + 2 * BS;

    const int bm = blockIdx.y * 128;
    int bn, mat = 0;
    if (EPI == 4) {
        mat = blockIdx.x >> 1;
        bn = (blockIdx.x & 1) * 128;
        Bh += (size_t)mat * DM * KP_DM;
        Bl += (size_t)mat * DM * KP_DM;
    } else {
        bn = blockIdx.x * BN;
    }
    const int tid  = threadIdx.x;
    const int lane = tid & 31;
    const int wid  = tid >> 5;
    const int g = lane >> 2;
    const int t = lane & 3;
    const int wm = (wid & 3) * 32;
    const int wn = (wid >> 2) * (BN / 2);
    const int kpt = KP >> 3;                // kp-tiles per n-tile row

    float acc[2][NT][4];
    #pragma unroll
    for (int mt = 0; mt < 2; mt++)
        #pragma unroll
        for (int nt = 0; nt < NT; nt++)
            #pragma unroll
            for (int r = 0; r < 4; r++) acc[mt][nt][r] = 0.f;

    // fill: A 128 rows x 16 kp row-major[20]; B fragment tiles, fully linear copy.
    #define FILL_TILE(s, kp0)                                                       \
        do {                                                                         \
            _Pragma("unroll")                                                        \
            for (int it_ = 0; it_ < 2; it_++) {                                      \
                int i_ = it_ * 256 + tid;                                            \
                int m_ = i_ >> 2, c4_ = (i_ & 3) * 4;                                \
                size_t ga_ = (size_t)(bm + m_) * KP + (kp0) + c4_;                   \
                cp16(&AsH[(s) * 2560 + m_ * 20 + c4_], Ah + ga_);                    \
                cp16(&AsL[(s) * 2560 + m_ * 20 + c4_], Al + ga_);                    \
            }                                                                        \
            _Pragma("unroll")                                                        \
            for (int it_ = 0; it_ < BN / 64; it_++) {                                \
                int f_ = it_ * 256 + tid;                                            \
                size_t gb_ = ((size_t)((bn >> 3) + (f_ >> 5)) * kpt                  \
                              + ((kp0) >> 3) + ((f_ >> 4) & 1)) * 64 + (f_ & 15) * 4;\
                cp16(&BsH[(s) * BS + f_ * 4], Bh + gb_);                             \
                cp16(&BsL[(s) * BS + f_ * 4], Bl + gb_);                             \
            }                                                                        \
        } while (0)

    const int NKT = KP / 16;
    FILL_TILE(0, 0);
    CP_COMMIT();

    for (int kt = 0; kt < NKT; kt++) {
        const int s = kt & 1;
        if (kt + 1 < NKT) {
            FILL_TILE(s ^ 1, (kt + 1) * 16);
            CP_COMMIT();
            cp_wait<1>();
        } else {
            cp_wait<0>();
        }
        __syncthreads();

        #pragma unroll
        for (int ks = 0; ks < 2; ks++) {
            const int cb = ks * 8 + t;
            unsigned ah[2][4], al[2][4];
            #pragma unroll
            for (int mt = 0; mt < 2; mt++) {
                int r = wm + mt * 16;
                const unsigned* aH = AsH + s * 2560;
                const unsigned* aL = AsL + s * 2560;
                ah[mt][0] = aH[(r + g    ) * 20 + cb];
                ah[mt][1] = aH[(r + g + 8) * 20 + cb];
                ah[mt][2] = aH[(r + g    ) * 20 + cb + 4];
                ah[mt][3] = aH[(r + g + 8) * 20 + cb + 4];
                al[mt][0] = aL[(r + g    ) * 20 + cb];
                al[mt][1] = aL[(r + g + 8) * 20 + cb];
                al[mt][2] = aL[(r + g    ) * 20 + cb + 4];
                al[mt][3] = aL[(r + g + 8) * 20 + cb + 4];
            }
            const unsigned* bH = BsH + s * BS + ks * 64 + lane * 2;
            const unsigned* bL = BsL + s * BS + ks * 64 + lane * 2;
            #pragma unroll
            for (int nt = 0; nt < NT; nt++) {
                int nti = (wn >> 3) + nt;
                uint2 u2h = *(const uint2*)&bH[nti * 128];
                uint2 u2l = *(const uint2*)&bL[nti * 128];
                unsigned bh[2] = {u2h.x, u2h.y};
                unsigned bl[2] = {u2l.x, u2l.y};
                #pragma unroll
                for (int mt = 0; mt < 2; mt++) {
                    mma16816(acc[mt][nt], ah[mt], bh);
                    mma16816(acc[mt][nt], ah[mt], bl);
                    mma16816(acc[mt][nt], al[mt], bh);
                }
            }
        }
        __syncthreads();
    }
    #undef FILL_TILE

    #pragma unroll
    for (int mt = 0; mt < 2; mt++) {
        #pragma unroll
        for (int nt = 0; nt < NT; nt++) {
            int row0 = bm + wm + mt * 16 + g;
            int col  = bn + wn + nt * 8 + 2 * t;
            float v0 = acc[mt][nt][0], v1 = acc[mt][nt][1];
            float v2 = acc[mt][nt][2], v3 = acc[mt][nt][3];
            if (EPI == 1) {
                float b0 = bias[col], b1 = bias[col + 1];
                v0 = fmaxf(v0 + b0, 0.f); v1 = fmaxf(v1 + b1, 0.f);
                v2 = fmaxf(v2 + b0, 0.f); v3 = fmaxf(v3 + b1, 0.f);
            }
            if (EPI == 2) {
                float b0 = bias[col], b1 = bias[col + 1];
                v0 += b0; v1 += b1; v2 += b0; v3 += b1;
            }
            if (EPI == 4 && mat == 2) {
                float p0 = __shfl_xor_sync(0xffffffffu, v0, 4);
                float p1 = __shfl_xor_sync(0xffffffffu, v1, 4);
                float p2 = __shfl_xor_sync(0xffffffffu, v2, 4);
                float p3 = __shfl_xor_sync(0xffffffffu, v3, 4);
                if (!(g & 1)) {
                    int bb = row0 >> 11;
                    int tt = row0 & (TT - 1);
                    int h  = col >> 5, vd = col & 31;
                    size_t base = ((size_t)(bb * HH + h) * DKk + vd) * (TT / 2) + (tt >> 1);
                    unsigned hi, lo;
                    pack_hilo(v0, p0, hi, lo);
                    Vh[base] = hi;                    Vl[base] = lo;
                    pack_hilo(v1, p1, hi, lo);
                    Vh[base + TT / 2] = hi;           Vl[base + TT / 2] = lo;
                    pack_hilo(v2, p2, hi, lo);
                    Vh[base + 4] = hi;                Vl[base + 4] = lo;
                    pack_hilo(v3, p3, hi, lo);
                    Vh[base + TT / 2 + 4] = hi;       Vl[base + TT / 2 + 4] = lo;
                }
            } else if (EPI == 0 || EPI == 2) {
                *(float2*)(C + (size_t)row0 * N + col)       = make_float2(v0, v1);
                *(float2*)(C + (size_t)(row0 + 8) * N + col) = make_float2(v2, v3);
            } else {
                unsigned* Dh = (EPI == 4 && mat == 1) ? Ch2 : Ch;
                unsigned* Dl = (EPI == 4 && mat == 1) ? Cl2 : Cl;
                unsigned h0, l0, h1, l1;
                pack_hilo(v0, v1, h0, l0);
                pack_hilo(v2, v3, h1, l1);
                int NP = N >> 1, cp = col >> 1;
                Dh[(size_t)row0 * NP + cp]       = h0;
                Dl[(size_t)row0 * NP + cp]       = l0;
                Dh[(size_t)(row0 + 8) * NP + cp] = h1;
                Dl[(size_t)(row0 + 8) * NP + cp] = l1;
            }
        }
    }
}

// -------------------- tensor-core causal attention (unchanged R9) ---------------
__global__ __launch_bounds__(256, 2) void attention_mma2(
    const unsigned* __restrict__ qh, const unsigned* __restrict__ ql,
    const unsigned* __restrict__ kh, const unsigned* __restrict__ kl,
    const unsigned* __restrict__ vth, const unsigned* __restrict__ vtl,
    float* __restrict__ ov) {
    __shared__ unsigned Ks_hi[2][64][20];
    __shared__ unsigned Ks_lo[2][64][20];
    __shared__ unsigned Vs_hi[2][32][36];
    __shared__ unsigned Vs_lo[2][32][36];

    const int bh = blockIdx.y;
    const int b  = bh >> 3, h = bh & 7;
    const int t0 = (gridDim.x - 1 - blockIdx.x) * 128;
    const int tid  = threadIdx.x;
    const int lane = tid & 31;
    const int wid  = tid >> 5;
    const int g = lane >> 2;
    const int t = lane & 3;
    const int wm = wid * 16;

    unsigned qfh[2][4], qfl[2][4];
    {
        size_t base = (size_t)(b * TT + t0 + wm) * KP_DM + h * 16;
        #pragma unroll
        for (int ks = 0; ks < 2; ks++) {
            qfh[ks][0] = qh[base + (size_t)g * KP_DM + ks * 8 + t];
            qfh[ks][1] = qh[base + (size_t)(g + 8) * KP_DM + ks * 8 + t];
            qfh[ks][2] = qh[base + (size_t)g * KP_DM + ks * 8 + t + 4];
            qfh[ks][3] = qh[base + (size_t)(g + 8) * KP_DM + ks * 8 + t + 4];
            qfl[ks][0] = ql[base + (size_t)g * KP_DM + ks * 8 + t];
            qfl[ks][1] = ql[base + (size_t)(g + 8) * KP_DM + ks * 8 + t];
            qfl[ks][2] = ql[base + (size_t)g * KP_DM + ks * 8 + t + 4];
            qfl[ks][3] = ql[base + (size_t)(g + 8) * KP_DM + ks * 8 + t + 4];
        }
    }

    float o[4][4];
    #pragma unroll
    for (int nf = 0; nf < 4; nf++)
        #pragma unroll
        for (int r = 0; r < 4; r++) o[nf][r] = 0.f;
    float rs0 = 0.f, rs1 = 0.f;

    const int row0 = t0 + wm + g;
    const int row1 = row0 + 8;
    const int nit = t0 / 64 + 2;

    const int kkey = tid >> 2, kseg = tid & 3;
    const int vvd  = tid >> 3, vseg = tid & 7;

    #define ISSUE_TILE(s, o0)                                                        \
        do {                                                                          \
            size_t kgi = (size_t)(b * TT + (o0) + kkey) * KP_DM + h * 16 + kseg * 4;  \
            cp16(&Ks_hi[s][kkey][kseg * 4], kh + kgi);                                \
            cp16(&Ks_lo[s][kkey][kseg * 4], kl + kgi);                                \
            size_t vgi = ((size_t)bh * DKk + vvd) * (TT / 2) + ((o0) >> 1) + vseg * 4;\
            cp16(&Vs_hi[s][vvd][vseg * 4], vth + vgi);                                \
            cp16(&Vs_lo[s][vvd][vseg * 4], vtl + vgi);                                \
        } while (0)

    ISSUE_TILE(0, 0);
    CP_COMMIT();

    for (int it = 0; it < nit; it++) {
        const int o0 = it * 64;
        const int s = it & 1;
        if (it + 1 < nit) {
            ISSUE_TILE(s ^ 1, o0 + 64);
            CP_COMMIT();
            cp_wait<1>();
        } else {
            cp_wait<0>();
        }
        __syncthreads();

        if (o0 <= t0 + wm + 15) {
            float c[8][4];
            #pragma unroll
            for (int j = 0; j < 8; j++)
                #pragma unroll
                for (int r = 0; r < 4; r++) c[j][r] = 0.f;
            #pragma unroll
            for (int j = 0; j < 8; j++) {
                int col = j * 8 + g;
                #pragma unroll
                for (int ks = 0; ks < 2; ks++) {
                    unsigned bhf[2], blf[2];
                    bhf[0] = Ks_hi[s][col][ks * 8 + t];
                    bhf[1] = Ks_hi[s][col][ks * 8 + t + 4];
                    blf[0] = Ks_lo[s][col][ks * 8 + t];
                    blf[1] = Ks_lo[s][col][ks * 8 + t + 4];
                    mma16816(c[j], qfh[ks], bhf);
                    mma16816(c[j], qfh[ks], blf);
                    mma16816(c[j], qfl[ks], bhf);
                }
            }
            if (o0 + 63 <= t0 + wm) {
                #pragma unroll
                for (int j = 0; j < 8; j++) {
                    if (j < 2) {
                        c[j][0] = fast_exp(fmaxf(fminf(c[j][0], 50.f), -80.f));
                        c[j][1] = fast_exp(fmaxf(fminf(c[j][1], 50.f), -80.f));
                        c[j][2] = fast_exp(fmaxf(fminf(c[j][2], 50.f), -80.f));
                        c[j][3] = fast_exp(fmaxf(fminf(c[j][3], 50.f), -80.f));
                    } else {
                        c[j][0] = __expf(fminf(c[j][0], 50.f));
                        c[j][1] = __expf(fminf(c[j][1], 50.f));
                        c[j][2] = __expf(fminf(c[j][2], 50.f));
                        c[j][3] = __expf(fminf(c[j][3], 50.f));
                    }
                    rs0 += c[j][0] + c[j][1];
                    rs1 += c[j][2] + c[j][3];
                }
            } else {
                #pragma unroll
                for (int j = 0; j < 8; j++) {
                    int cb = o0 + j * 8 + 2 * t;
                    float e0, e1, e2, e3;
                    if (j < 2) {
                        e0 = fast_exp(fmaxf(fminf(c[j][0], 50.f), -80.f));
                        e1 = fast_exp(fmaxf(fminf(c[j][1], 50.f), -80.f));
                        e2 = fast_exp(fmaxf(fminf(c[j][2], 50.f), -80.f));
                        e3 = fast_exp(fmaxf(fminf(c[j][3], 50.f), -80.f));
                    } else {
                        e0 = __expf(fminf(c[j][0], 50.f));
                        e1 = __expf(fminf(c[j][1], 50.f));
                        e2 = __expf(fminf(c[j][2], 50.f));
                        e3 = __expf(fminf(c[j][3], 50.f));
                    }
                    c[j][0] = (cb     <= row0) ? e0 : 0.f;
                    c[j][1] = (cb + 1 <= row0) ? e1 : 0.f;
                    c[j][2] = (cb     <= row1) ? e2 : 0.f;
                    c[j][3] = (cb + 1 <= row1) ? e3 : 0.f;
                    rs0 += c[j][0] + c[j][1];
                    rs1 += c[j][2] + c[j][3];
                }
            }
            #pragma unroll
            for (int klq = 0; klq < 4; klq++) {
                unsigned ph[4], pl[4];
                pack_hilo(c[2 * klq][0],     c[2 * klq][1],     ph[0], pl[0]);
                pack_hilo(c[2 * klq][2],     c[2 * klq][3],     ph[1], pl[1]);
                pack_hilo(c[2 * klq + 1][0], c[2 * klq + 1][1], ph[2], pl[2]);
                pack_hilo(c[2 * klq + 1][2], c[2 * klq + 1][3], ph[3], pl[3]);
                int kb = klq * 8;
                #pragma unroll
                for (int nf = 0; nf < 4; nf++) {
                    int vc = nf * 8 + g;
                    unsigned vhf[2], vlf[2];
                    vhf[0] = Vs_hi[s][vc][kb + t];
                    vhf[1] = Vs_hi[s][vc][kb + t + 4];
                    vlf[0] = Vs_lo[s][vc][kb + t];
                    vlf[1] = Vs_lo[s][vc][kb + t + 4];
                    mma16816(o[nf], ph, vhf);
                    mma16816(o[nf], ph, vlf);
                    mma16816(o[nf], pl, vhf);
                }
            }
        }
        __syncthreads();
    }
    #undef ISSUE_TILE

    rs0 += __shfl_xor_sync(0xffffffffu, rs0, 1);
    rs0 += __shfl_xor_sync(0xffffffffu, rs0, 2);
    rs1 += __shfl_xor_sync(0xffffffffu, rs1, 1);
    rs1 += __shfl_xor_sync(0xffffffffu, rs1, 2);
    float i0 = 1.f / (rs0 + 1e-10f);
    float i1 = 1.f / (rs1 + 1e-10f);
    size_t r0 = (size_t)(b * TT + row0);
    #pragma unroll
    for (int nf = 0; nf < 4; nf++) {
        int vd = h * DKk + nf * 8 + 2 * t;
        *(float2*)(ov + r0 * DM + vd)       = make_float2(o[nf][0] * i0, o[nf][1] * i0);
        *(float2*)(ov + (r0 + 8) * DM + vd) = make_float2(o[nf][2] * i1, o[nf][3] * i1);
    }
}

// -------------------- launch --------------------------------------------------
extern "C" void kernel_launch(void* const* d_in, const int* in_sizes, int n_in,
                              void* d_out, int out_size) {
    const int*   x     = (const int*)  d_in[0];
    const float* emb   = (const float*)d_in[1];
    const float* pos   = (const float*)d_in[2];
    const float* wq    = (const float*)d_in[3];
    const float* wk    = (const float*)d_in[4];
    const float* wv    = (const float*)d_in[5];
    const float* wo    = (const float*)d_in[6];
    const float* mlp0  = (const float*)d_in[7];
    const float* mlpb  = (const float*)d_in[8];
    const float* mlp1  = (const float*)d_in[9];
    const float* unemb = (const float*)d_in[10];
    const float* bias  = (const float*)d_in[11];
    float* out = (float*)d_out;

    unsigned *hh_, *hl_, *qh_, *ql_, *kh_, *kl_, *yh_, *yl_, *wh_, *wl_, *vth_, *vtl_;
    float *ov_, *tmp_, *wos_;
    cudaGetSymbolAddress((void**)&hh_, g_hh);
    cudaGetSymbolAddress((void**)&hl_, g_hl);
    cudaGetSymbolAddress((void**)&qh_, g_qh);
    cudaGetSymbolAddress((void**)&ql_, g_ql);
    cudaGetSymbolAddress((void**)&kh_, g_kh);
    cudaGetSymbolAddress((void**)&kl_, g_kl);
    cudaGetSymbolAddress((void**)&yh_, g_yh);
    cudaGetSymbolAddress((void**)&yl_, g_yl);
    cudaGetSymbolAddress((void**)&wh_, g_wh);
    cudaGetSymbolAddress((void**)&wl_, g_wl);
    cudaGetSymbolAddress((void**)&vth_, g_vth);
    cudaGetSymbolAddress((void**)&vtl_, g_vtl);
    cudaGetSymbolAddress((void**)&ov_,  g_ov);
    cudaGetSymbolAddress((void**)&tmp_, g_tmp);
    cudaGetSymbolAddress((void**)&wos_, g_wosum);

    // dyn smem: A 2*2560*2 u32 + B 2*(16*BN)*2 u32
    const int SM128 = (10240 + 4 * 16 * 128) * 4;   // 73728 B
    const int SM64  = (10240 + 4 * 16 * 64)  * 4;   // 57344 B
    cudaFuncSetAttribute(mgemm_db<4, 128>, cudaFuncAttributeMaxDynamicSharedMemorySize, SM128);
    cudaFuncSetAttribute(mgemm_db<1, 128>, cudaFuncAttributeMaxDynamicSharedMemorySize, SM128);
    cudaFuncSetAttribute(mgemm_db<2, 128>, cudaFuncAttributeMaxDynamicSharedMemorySize, SM128);
    cudaFuncSetAttribute(mgemm_db<0, 64>,  cudaFuncAttributeMaxDynamicSharedMemorySize, SM64);

    detect_idx<<<1, 64>>>(x);
    convert_weights<<<(W_TOT + 255) / 256, 256>>>(wq, wk, wv, mlp0, mlp1, unemb);
    compute_wosum_all<<<(NL * DKk * DM + 255) / 256, 256>>>(wo);
    embed_ln_w<<<BT / 8, 256>>>(x, emb, pos);

    for (int l = 0; l < NL; l++) {
        const unsigned* wqkv_h = wh_ + (size_t)(l * 3) * DM * KP_DM;
        const unsigned* wqkv_l = wl_ + (size_t)(l * 3) * DM * KP_DM;
        const unsigned* m0h = wh_ + W_M0 + (size_t)l * DHid * KP_DM;
        const unsigned* m0l = wl_ + W_M0 + (size_t)l * DHid * KP_DM;
        const unsigned* m1h = wh_ + W_M1 + (size_t)l * DM * KP_HID;
        const unsigned* m1l = wl_ + W_M1 + (size_t)l * DM * KP_HID;

        mgemm_db<4, 128><<<dim3(6, BT / 128), 256, SM128>>>(
            hh_, hl_, wqkv_h, wqkv_l, nullptr, qh_, ql_, kh_, kl_, vth_, vtl_,
            nullptr, BT, DM, KP_DM);

        attention_mma2<<<dim3(TT / 128, BB * HH), 256>>>(qh_, ql_, kh_, kl_, vth_, vtl_, ov_);
        attn_out_ln_w<<<BT / 8, 256>>>(ov_, wos_ + (size_t)l * DKk * DM);

        mgemm_db<1, 128><<<dim3(DHid / 128, BT / 128), 256, SM128>>>(
            hh_, hl_, m0h, m0l, nullptr, yh_, yl_, nullptr, nullptr, nullptr, nullptr,
            mlpb + (size_t)l * DHid, BT, DHid, KP_DM);
        mgemm_db<0, 64><<<dim3(DM / 64, BT / 128), 256, SM64>>>(
            yh_, yl_, m1h, m1l, tmp_, nullptr, nullptr, nullptr, nullptr, nullptr, nullptr,
            nullptr, BT, DM, KP_HID);
        ln_residual_w<<<BT / 8, 256>>>(tmp_);
    }

    mgemm_db<2, 128><<<dim3(ND / 128, BT / 128), 256, SM128>>>(
        hh_, hl_, wh_ + W_UE, wl_ + W_UE, out, nullptr, nullptr, nullptr, nullptr,
        nullptr, nullptr, bias, BT, ND, KP_DM);
}

// round 12
// speedup vs baseline: 1.1759x; 1.0643x over previous
#include <cuda_runtime.h>
#include <cuda_bf16.h>
#include <math.h>

#define BB 4
#define TT 2048
#define BT (BB*TT)
#define DM 256
#define HH 8
#define DKk 32
#define DHid 1024
#define ND 8192
#define NL 4

#define KP_DM (DM/2)      // 128 pairs
#define KP_HID (DHid/2)   // 512 pairs

// packed-weight regions (u32). B operands FRAGMENT-MAJOR (8n x 8kp tiles, 64 u32).
#define W_M0 (NL*3*DM*KP_DM)
#define W_M1 (W_M0 + NL*DHid*KP_DM)
#define W_UE (W_M1 + NL*DM*KP_HID)
#define W_TOT (W_UE + ND*KP_DM)

// -------------------- scratch (device globals) ---------------------------------
__device__ float    g_h  [BT*DM];
__device__ unsigned g_hh [BT*KP_DM];   // A-fragment-major (16m x 8kp tiles)
__device__ unsigned g_hl [BT*KP_DM];
__device__ unsigned g_qh [BT*KP_DM];   // row-major [token][kp] (attention consumes)
__device__ unsigned g_ql [BT*KP_DM];
__device__ unsigned g_kh [BT*KP_DM];
__device__ unsigned g_kl [BT*KP_DM];
__device__ unsigned g_vth[BT*KP_DM];   // V transposed+packed: [bh][vd0..31][kp]
__device__ unsigned g_vtl[BT*KP_DM];
__device__ float    g_ov [BT*DM];
__device__ unsigned g_yh [BT*KP_HID];  // A-fragment-major
__device__ unsigned g_yl [BT*KP_HID];
__device__ float    g_tmp[BT*DM];
__device__ unsigned g_wh [W_TOT];
__device__ unsigned g_wl [W_TOT];
__device__ float    g_wosum[NL*DKk*DM];
__device__ int      g_is64;

// -------------------- helpers -------------------------------------------------
__device__ __forceinline__ void pack_hilo(float x, float y, unsigned& hi, unsigned& lo) {
    unsigned h;
    asm("cvt.rn.bf16x2.f32 %0, %1, %2;" : "=r"(h) : "f"(y), "f"(x));
    float xr = x - __uint_as_float(h << 16);
    float yr = y - __uint_as_float(h & 0xffff0000u);
    asm("cvt.rn.bf16x2.f32 %0, %1, %2;" : "=r"(lo) : "f"(yr), "f"(xr));
    hi = h;
}

__device__ __forceinline__ void mma16816(float* c, const unsigned* a, const unsigned* b) {
    asm volatile(
        "mma.sync.aligned.m16n8k16.row.col.f32.bf16.bf16.f32 "
        "{%0,%1,%2,%3}, {%4,%5,%6,%7}, {%8,%9}, {%0,%1,%2,%3};\n"
        : "+f"(c[0]), "+f"(c[1]), "+f"(c[2]), "+f"(c[3])
        : "r"(a[0]), "r"(a[1]), "r"(a[2]), "r"(a[3]), "r"(b[0]), "r"(b[1]));
}

__device__ __forceinline__ void cp16(void* sdst, const void* gsrc) {
    unsigned sa = (unsigned)__cvta_generic_to_shared(sdst);
    asm volatile("cp.async.cg.shared.global [%0], [%1], 16;\n" :: "r"(sa), "l"(gsrc));
}
#define CP_COMMIT() asm volatile("cp.async.commit_group;\n" ::: "memory")
template <int N> __device__ __forceinline__ void cp_wait() {
    asm volatile("cp.async.wait_group %0;\n" :: "n"(N) : "memory");
}

__device__ __forceinline__ float warp_sum(float v) {
    #pragma unroll
    for (int o = 16; o; o >>= 1) v += __shfl_xor_sync(0xffffffffu, v, o);
    return v;
}

__device__ __forceinline__ float fast_exp(float x) {
    float t = x * 1.44269504f;
    float fi = rintf(t);
    float f = t - fi;
    int ei = __float2int_rn(fi);
    float p = 1.33336e-3f;
    p = fmaf(p, f, 9.61813e-3f);
    p = fmaf(p, f, 5.55041e-2f);
    p = fmaf(p, f, 2.40227e-1f);
    p = fmaf(p, f, 6.93147e-1f);
    p = fmaf(p, f, 1.0f);
    return __uint_as_float((unsigned)((ei + 127) << 23)) * p;
}

// A-fragment-major index: tile = 16m x 8kp (128 u32); lane (g*4+t) owns
// words l*4+{0,1,2,3} = {(g,t),(g+8,t),(g,t+4),(g+8,t+4)}.
__device__ __forceinline__ size_t afrag_idx(int m, int kp, int kpt8) {
    int quad = (m & 7) * 4 + (kp & 3);
    int word = ((m >> 3) & 1) + (((kp >> 2) & 1) << 1);
    return ((size_t)(m >> 4) * kpt8 + (kp >> 3)) * 128 + quad * 4 + word;
}

// -------------------- index dtype probe ---------------------------------------
__global__ void detect_idx(const int* __restrict__ xi) {
    __shared__ int ok;
    if (threadIdx.x == 0) ok = 1;
    __syncthreads();
    if (xi[2 * threadIdx.x + 1] != 0) atomicAnd(&ok, 0);
    __syncthreads();
    if (threadIdx.x == 0) g_is64 = ok;
}

// -------------------- one-shot weight pre-conversion (B fragment-major) --------
__device__ __forceinline__ size_t frag_idx(int n, int kp, int kpt) {
    return ((size_t)(n >> 3) * kpt + (kp >> 3)) * 64
         + (size_t)((4 * (n & 7) + (kp & 3)) * 2 + ((kp >> 2) & 1));
}

__global__ __launch_bounds__(256) void convert_weights(
    const float* __restrict__ wq, const float* __restrict__ wk,
    const float* __restrict__ wv, const float* __restrict__ m0,
    const float* __restrict__ m1, const float* __restrict__ ue) {
    int i = blockIdx.x * 256 + threadIdx.x;
    if (i >= W_TOT) return;
    float a, b;
    size_t out;
    if (i < W_M0) {                       // QKV per-head [n/32][k][n%32] source
        int l3 = i >> 15;
        int r  = i & 32767;
        int kp = r >> 8;
        int n  = r & 255;
        int l = l3 / 3, mi = l3 % 3;
        const float* W = (mi == 0) ? wq : (mi == 1) ? wk : wv;
        size_t base = (size_t)l * HH * DM * DKk + (size_t)(n >> 5) * DM * DKk + (n & 31);
        a = W[base + (size_t)(2 * kp)     * DKk];
        b = W[base + (size_t)(2 * kp + 1) * DKk];
        out = (size_t)l3 * 32768 + frag_idx(n, kp, KP_DM / 8);
    } else if (i < W_M1) {                // mlp0 [k][1024]
        int r = i - W_M0;
        int l = r >> 17;
        int rr = r & 131071;
        int kp = rr >> 10;
        int n  = rr & 1023;
        const float* W = m0 + (size_t)l * DM * DHid;
        a = W[(size_t)(2 * kp)     * DHid + n];
        b = W[(size_t)(2 * kp + 1) * DHid + n];
        out = W_M0 + (size_t)l * 131072 + frag_idx(n, kp, KP_DM / 8);
    } else if (i < W_UE) {                // mlp1 [k][256]
        int r = i - W_M1;
        int l = r >> 17;
        int rr = r & 131071;
        int kp = rr >> 8;
        int n  = rr & 255;
        const float* W = m1 + (size_t)l * DHid * DM;
        a = W[(size_t)(2 * kp)     * DM + n];
        b = W[(size_t)(2 * kp + 1) * DM + n];
        out = W_M1 + (size_t)l * 131072 + frag_idx(n, kp, KP_HID / 8);
    } else {                              // unembedding [k][8192]
        int r = i - W_UE;
        int kp = r >> 13;
        int n  = r & 8191;
        a = ue[(size_t)(2 * kp)     * ND + n];
        b = ue[(size_t)(2 * kp + 1) * ND + n];
        out = W_UE + frag_idx(n, kp, KP_DM / 8);
    }
    unsigned hi, lo;
    pack_hilo(a, b, hi, lo);
    g_wh[out] = hi;
    g_wl[out] = lo;
}

// -------------------- wo summed over heads --------------------------------------
__global__ void compute_wosum_all(const float* __restrict__ wo) {
    int i = blockIdx.x * 256 + threadIdx.x;
    if (i < NL * DKk * DM) {
        int l = i / (DKk * DM);
        int r = i % (DKk * DM);
        float s = 0.f;
        #pragma unroll
        for (int hh = 0; hh < HH; hh++)
            s += wo[(size_t)l * HH * DKk * DM + (size_t)hh * DKk * DM + r];
        g_wosum[i] = s;
    }
}

// -------------------- warp-per-token LN (A-fragment-major packed out) -----------
__device__ __forceinline__ void ln_store_warp(int token, int lane, float* val) {
    float s = 0.f;
    #pragma unroll
    for (int j = 0; j < 8; j++) s += val[j];
    s = warp_sum(s);
    float m = s * (1.f / DM);
    float vv = 0.f;
    #pragma unroll
    for (int j = 0; j < 8; j++) { val[j] -= m; vv += val[j] * val[j]; }
    vv = warp_sum(vv);
    float inv = rsqrtf(vv * (1.f / DM) + 1e-5f);
    #pragma unroll
    for (int j = 0; j < 8; j++) {
        float out = val[j] * inv;
        int d = j * 32 + lane;
        g_h[(size_t)token * DM + d] = out;
        float other = __shfl_xor_sync(0xffffffffu, out, 1);
        if (!(lane & 1)) {
            unsigned hi, lo;
            pack_hilo(out, other, hi, lo);
            int kp = j * 16 + (lane >> 1);
            size_t o = afrag_idx(token & 15, kp, KP_DM / 8)
                     + (size_t)(token >> 4) * (16 * KP_DM / 8 * 8);  // = (token>>4)*KP_DM*... tiles per 16 tokens = KP_DM/8, each 128 u32
            g_hh[o] = hi;
            g_hl[o] = lo;
        }
    }
}

__global__ __launch_bounds__(256) void embed_ln_w(const int* __restrict__ xi,
                                                  const float* __restrict__ emb,
                                                  const float* __restrict__ pos) {
    int token = blockIdx.x * 8 + (threadIdx.x >> 5);
    int lane = threadIdx.x & 31;
    int t = token % TT;
    int idx = g_is64 ? xi[2 * token] : xi[token];
    float val[8];
    #pragma unroll
    for (int j = 0; j < 8; j++) {
        int d = j * 32 + lane;
        val[j] = emb[(size_t)idx * DM + d] + pos[(size_t)t * DM + d];
    }
    ln_store_warp(token, lane, val);
}

__global__ __launch_bounds__(256) void attn_out_ln_w(const float* __restrict__ ov,
                                                     const float* __restrict__ wos) {
    int token = blockIdx.x * 8 + (threadIdx.x >> 5);
    int lane = threadIdx.x & 31;
    float vs = 0.f;
    float val[8];
    #pragma unroll
    for (int j = 0; j < 8; j++) {
        float o = ov[(size_t)token * DM + j * 32 + lane];
        vs += o;
        val[j] = g_h[(size_t)token * DM + j * 32 + lane];
    }
    #pragma unroll
    for (int v = 0; v < DKk; v++) {
        float sv = __shfl_sync(0xffffffffu, vs, v);
        #pragma unroll
        for (int j = 0; j < 8; j++) val[j] += sv * wos[v * DM + j * 32 + lane];
    }
    ln_store_warp(token, lane, val);
}

__global__ __launch_bounds__(256) void ln_residual_w(const float* __restrict__ add) {
    int token = blockIdx.x * 8 + (threadIdx.x >> 5);
    int lane = threadIdx.x & 31;
    float val[8];
    #pragma unroll
    for (int j = 0; j < 8; j++) {
        int d = j * 32 + lane;
        val[j] = g_h[(size_t)token * DM + d] + add[(size_t)token * DM + d];
    }
    ln_store_warp(token, lane, val);
}

// -------------------- packed GEMM: fragment-major A AND B ------------------------
// 256 threads, 8 warps (4 in m x 2 in n), 32x(BN/2) warp tiles.
// A fragment-major (16m x 8kp tiles of 128 u32): one LDS.128 per fragment.
// B fragment-major (8n x 8kp tiles of 64 u32): one LDS.64 per fragment.
// EPI 0: fp32. 1: relu(acc+bias)->A-fragment-major packed. 2: acc+bias fp32.
// EPI 4: fused QKV; q->Ch/Cl, k->Ch2/Cl2 row-major, v->transposed Vh/Vl.
template <int EPI, int BN>
__global__ __launch_bounds__(256, 2) void mgemm_db(
    const unsigned* __restrict__ Ah, const unsigned* __restrict__ Al,
    const unsigned* __restrict__ Bh, const unsigned* __restrict__ Bl,
    float* __restrict__ C, unsigned* __restrict__ Ch, unsigned* __restrict__ Cl,
    unsigned* __restrict__ Ch2, unsigned* __restrict__ Cl2,
    unsigned* __restrict__ Vh, unsigned* __restrict__ Vl,
    const float* __restrict__ bias, int M, int N, int KP) {
    constexpr int NT = BN / 16;
    constexpr int BS = 16 * BN;             // one B buffer (u32)
    constexpr int AS = 2048;                // one A buffer (u32): 16 tiles x 128
    extern __shared__ unsigned smq[];
    unsigned* AsH = smq;                    // [2][AS]
    unsigned* AsL = smq + 2 * AS;
    unsigned* BsH = smq + 4 * AS;           // [2][BS]
    unsigned* BsL = BsH + 2 * BS;

    const int bm = blockIdx.y * 128;
    int bn, mat = 0;
    if (EPI == 4) {
        mat = blockIdx.x >> 1;
        bn = (blockIdx.x & 1) * 128;
        Bh += (size_t)mat * DM * KP_DM;
        Bl += (size_t)mat * DM * KP_DM;
    } else {
        bn = blockIdx.x * BN;
    }
    const int tid  = threadIdx.x;
    const int lane = tid & 31;
    const int wid  = tid >> 5;
    const int g = lane >> 2;
    const int t = lane & 3;
    const int wm = (wid & 3) * 32;
    const int wn = (wid >> 2) * (BN / 2);
    const int kpt  = KP >> 3;               // kp-tiles per n/m-tile row

    float acc[2][NT][4];
    #pragma unroll
    for (int mt = 0; mt < 2; mt++)
        #pragma unroll
        for (int nt = 0; nt < NT; nt++)
            #pragma unroll
            for (int r = 0; r < 4; r++) acc[mt][nt][r] = 0.f;

    // fill: A 16 fragment tiles (8 m16 x 2 kp8) linear; B fragment tiles linear.
    #define FILL_TILE(s, kp0)                                                       \
        do {                                                                         \
            _Pragma("unroll")                                                        \
            for (int it_ = 0; it_ < 2; it_++) {                                      \
                int i_ = it_ * 256 + tid;                                            \
                int tl_ = i_ >> 5;                                                   \
                size_t ga_ = ((size_t)((bm >> 4) + (tl_ >> 1)) * kpt                 \
                              + ((kp0) >> 3) + (tl_ & 1)) * 128 + (i_ & 31) * 4;     \
                cp16(&AsH[(s) * AS + i_ * 4], Ah + ga_);                             \
                cp16(&AsL[(s) * AS + i_ * 4], Al + ga_);                             \
            }                                                                        \
            _Pragma("unroll")                                                        \
            for (int it_ = 0; it_ < BN / 64; it_++) {                                \
                int f_ = it_ * 256 + tid;                                            \
                size_t gb_ = ((size_t)((bn >> 3) + (f_ >> 5)) * kpt                  \
                              + ((kp0) >> 3) + ((f_ >> 4) & 1)) * 64 + (f_ & 15) * 4;\
                cp16(&BsH[(s) * BS + f_ * 4], Bh + gb_);                             \
                cp16(&BsL[(s) * BS + f_ * 4], Bl + gb_);                             \
            }                                                                        \
        } while (0)

    const int NKT = KP / 16;
    FILL_TILE(0, 0);
    CP_COMMIT();

    for (int kt = 0; kt < NKT; kt++) {
        const int s = kt & 1;
        if (kt + 1 < NKT) {
            FILL_TILE(s ^ 1, (kt + 1) * 16);
            CP_COMMIT();
            cp_wait<1>();
        } else {
            cp_wait<0>();
        }
        __syncthreads();

        #pragma unroll
        for (int ks = 0; ks < 2; ks++) {
            unsigned ah[2][4], al[2][4];
            #pragma unroll
            for (int mt = 0; mt < 2; mt++) {
                int atile = (((wid & 3) * 2 + mt) * 2 + ks) * 128 + lane * 4;
                uint4 uh = *(const uint4*)&AsH[s * AS + atile];
                uint4 ul = *(const uint4*)&AsL[s * AS + atile];
                ah[mt][0] = uh.x; ah[mt][1] = uh.y; ah[mt][2] = uh.z; ah[mt][3] = uh.w;
                al[mt][0] = ul.x; al[mt][1] = ul.y; al[mt][2] = ul.z; al[mt][3] = ul.w;
            }
            const unsigned* bH = BsH + s * BS + ks * 64 + lane * 2;
            const unsigned* bL = BsL + s * BS + ks * 64 + lane * 2;
            #pragma unroll
            for (int nt = 0; nt < NT; nt++) {
                int nti = (wn >> 3) + nt;
                uint2 u2h = *(const uint2*)&bH[nti * 128];
                uint2 u2l = *(const uint2*)&bL[nti * 128];
                unsigned bh[2] = {u2h.x, u2h.y};
                unsigned bl[2] = {u2l.x, u2l.y};
                #pragma unroll
                for (int mt = 0; mt < 2; mt++) {
                    mma16816(acc[mt][nt], ah[mt], bh);
                    mma16816(acc[mt][nt], ah[mt], bl);
                    mma16816(acc[mt][nt], al[mt], bh);
                }
            }
        }
        __syncthreads();
    }
    #undef FILL_TILE

    const int opt = N >> 4;   // output kp-tiles per 16-row block when EPI==1 (kp dim = N/2)
    #pragma unroll
    for (int mt = 0; mt < 2; mt++) {
        #pragma unroll
        for (int nt = 0; nt < NT; nt++) {
            int row0 = bm + wm + mt * 16 + g;
            int col  = bn + wn + nt * 8 + 2 * t;
            float v0 = acc[mt][nt][0], v1 = acc[mt][nt][1];
            float v2 = acc[mt][nt][2], v3 = acc[mt][nt][3];
            if (EPI == 1) {
                float b0 = bias[col], b1 = bias[col + 1];
                v0 = fmaxf(v0 + b0, 0.f); v1 = fmaxf(v1 + b1, 0.f);
                v2 = fmaxf(v2 + b0, 0.f); v3 = fmaxf(v3 + b1, 0.f);
            }
            if (EPI == 2) {
                float b0 = bias[col], b1 = bias[col + 1];
                v0 += b0; v1 += b1; v2 += b0; v3 += b1;
            }
            if (EPI == 4 && mat == 2) {
                float p0 = __shfl_xor_sync(0xffffffffu, v0, 4);
                float p1 = __shfl_xor_sync(0xffffffffu, v1, 4);
                float p2 = __shfl_xor_sync(0xffffffffu, v2, 4);
                float p3 = __shfl_xor_sync(0xffffffffu, v3, 4);
                if (!(g & 1)) {
                    int bb = row0 >> 11;
                    int tt = row0 & (TT - 1);
                    int h  = col >> 5, vd = col & 31;
                    size_t base = ((size_t)(bb * HH + h) * DKk + vd) * (TT / 2) + (tt >> 1);
                    unsigned hi, lo;
                    pack_hilo(v0, p0, hi, lo);
                    Vh[base] = hi;                    Vl[base] = lo;
                    pack_hilo(v1, p1, hi, lo);
                    Vh[base + TT / 2] = hi;           Vl[base + TT / 2] = lo;
                    pack_hilo(v2, p2, hi, lo);
                    Vh[base + 4] = hi;                Vl[base + 4] = lo;
                    pack_hilo(v3, p3, hi, lo);
                    Vh[base + TT / 2 + 4] = hi;       Vl[base + TT / 2 + 4] = lo;
                }
            } else if (EPI == 0 || EPI == 2) {
                *(float2*)(C + (size_t)row0 * N + col)       = make_float2(v0, v1);
                *(float2*)(C + (size_t)(row0 + 8) * N + col) = make_float2(v2, v3);
            } else if (EPI == 1) {
                // A-fragment-major output (kp = col>>1, rows g / g+8 in same tile)
                unsigned h0, l0, h1, l1;
                pack_hilo(v0, v1, h0, l0);
                pack_hilo(v2, v3, h1, l1);
                int cp = col >> 1;
                size_t tb = ((size_t)(row0 >> 4) * opt + (cp >> 3)) * 128
                          + (size_t)(((g & 7) * 4 + (cp & 3)) * 4 + (((cp >> 2) & 1) << 1));
                Ch[tb]     = h0;  Cl[tb]     = l0;   // row g   (word bit 0)
                Ch[tb + 1] = h1;  Cl[tb + 1] = l1;   // row g+8 (word bit 1)
            } else {
                unsigned* Dh = (EPI == 4 && mat == 1) ? Ch2 : Ch;
                unsigned* Dl = (EPI == 4 && mat == 1) ? Cl2 : Cl;
                unsigned h0, l0, h1, l1;
                pack_hilo(v0, v1, h0, l0);
                pack_hilo(v2, v3, h1, l1);
                int NP = N >> 1, cp = col >> 1;
                Dh[(size_t)row0 * NP + cp]       = h0;
                Dl[(size_t)row0 * NP + cp]       = l0;
                Dh[(size_t)(row0 + 8) * NP + cp] = h1;
                Dl[(size_t)(row0 + 8) * NP + cp] = l1;
            }
        }
    }
}

// -------------------- tensor-core causal attention (unchanged R11) --------------
__global__ __launch_bounds__(256, 2) void attention_mma2(
    const unsigned* __restrict__ qh, const unsigned* __restrict__ ql,
    const unsigned* __restrict__ kh, const unsigned* __restrict__ kl,
    const unsigned* __restrict__ vth, const unsigned* __restrict__ vtl,
    float* __restrict__ ov) {
    __shared__ unsigned Ks_hi[2][64][20];
    __shared__ unsigned Ks_lo[2][64][20];
    __shared__ unsigned Vs_hi[2][32][36];
    __shared__ unsigned Vs_lo[2][32][36];

    const int bh = blockIdx.y;
    const int b  = bh >> 3, h = bh & 7;
    const int t0 = (gridDim.x - 1 - blockIdx.x) * 128;
    const int tid  = threadIdx.x;
    const int lane = tid & 31;
    const int wid  = tid >> 5;
    const int g = lane >> 2;
    const int t = lane & 3;
    const int wm = wid * 16;

    unsigned qfh[2][4], qfl[2][4];
    {
        size_t base = (size_t)(b * TT + t0 + wm) * KP_DM + h * 16;
        #pragma unroll
        for (int ks = 0; ks < 2; ks++) {
            qfh[ks][0] = qh[base + (size_t)g * KP_DM + ks * 8 + t];
            qfh[ks][1] = qh[base + (size_t)(g + 8) * KP_DM + ks * 8 + t];
            qfh[ks][2] = qh[base + (size_t)g * KP_DM + ks * 8 + t + 4];
            qfh[ks][3] = qh[base + (size_t)(g + 8) * KP_DM + ks * 8 + t + 4];
            qfl[ks][0] = ql[base + (size_t)g * KP_DM + ks * 8 + t];
            qfl[ks][1] = ql[base + (size_t)(g + 8) * KP_DM + ks * 8 + t];
            qfl[ks][2] = ql[base + (size_t)g * KP_DM + ks * 8 + t + 4];
            qfl[ks][3] = ql[base + (size_t)(g + 8) * KP_DM + ks * 8 + t + 4];
        }
    }

    float o[4][4];
    #pragma unroll
    for (int nf = 0; nf < 4; nf++)
        #pragma unroll
        for (int r = 0; r < 4; r++) o[nf][r] = 0.f;
    float rs0 = 0.f, rs1 = 0.f;

    const int row0 = t0 + wm + g;
    const int row1 = row0 + 8;
    const int nit = t0 / 64 + 2;

    const int kkey = tid >> 2, kseg = tid & 3;
    const int vvd  = tid >> 3, vseg = tid & 7;

    #define ISSUE_TILE(s, o0)                                                        \
        do {                                                                          \
            size_t kgi = (size_t)(b * TT + (o0) + kkey) * KP_DM + h * 16 + kseg * 4;  \
            cp16(&Ks_hi[s][kkey][kseg * 4], kh + kgi);                                \
            cp16(&Ks_lo[s][kkey][kseg * 4], kl + kgi);                                \
            size_t vgi = ((size_t)bh * DKk + vvd) * (TT / 2) + ((o0) >> 1) + vseg * 4;\
            cp16(&Vs_hi[s][vvd][vseg * 4], vth + vgi);                                \
            cp16(&Vs_lo[s][vvd][vseg * 4], vtl + vgi);                                \
        } while (0)

    ISSUE_TILE(0, 0);
    CP_COMMIT();

    for (int it = 0; it < nit; it++) {
        const int o0 = it * 64;
        const int s = it & 1;
        if (it + 1 < nit) {
            ISSUE_TILE(s ^ 1, o0 + 64);
            CP_COMMIT();
            cp_wait<1>();
        } else {
            cp_wait<0>();
        }
        __syncthreads();

        if (o0 <= t0 + wm + 15) {
            float c[8][4];
            #pragma unroll
            for (int j = 0; j < 8; j++)
                #pragma unroll
                for (int r = 0; r < 4; r++) c[j][r] = 0.f;
            #pragma unroll
            for (int j = 0; j < 8; j++) {
                int col = j * 8 + g;
                #pragma unroll
                for (int ks = 0; ks < 2; ks++) {
                    unsigned bhf[2], blf[2];
                    bhf[0] = Ks_hi[s][col][ks * 8 + t];
                    bhf[1] = Ks_hi[s][col][ks * 8 + t + 4];
                    blf[0] = Ks_lo[s][col][ks * 8 + t];
                    blf[1] = Ks_lo[s][col][ks * 8 + t + 4];
                    mma16816(c[j], qfh[ks], bhf);
                    mma16816(c[j], qfh[ks], blf);
                    mma16816(c[j], qfl[ks], bhf);
                }
            }
            if (o0 + 63 <= t0 + wm) {
                #pragma unroll
                for (int j = 0; j < 8; j++) {
                    if (j < 2) {
                        c[j][0] = fast_exp(fmaxf(fminf(c[j][0], 50.f), -80.f));
                        c[j][1] = fast_exp(fmaxf(fminf(c[j][1], 50.f), -80.f));
                        c[j][2] = fast_exp(fmaxf(fminf(c[j][2], 50.f), -80.f));
                        c[j][3] = fast_exp(fmaxf(fminf(c[j][3], 50.f), -80.f));
                    } else {
                        c[j][0] = __expf(fminf(c[j][0], 50.f));
                        c[j][1] = __expf(fminf(c[j][1], 50.f));
                        c[j][2] = __expf(fminf(c[j][2], 50.f));
                        c[j][3] = __expf(fminf(c[j][3], 50.f));
                    }
                    rs0 += c[j][0] + c[j][1];
                    rs1 += c[j][2] + c[j][3];
                }
            } else {
                #pragma unroll
                for (int j = 0; j < 8; j++) {
                    int cb = o0 + j * 8 + 2 * t;
                    float e0, e1, e2, e3;
                    if (j < 2) {
                        e0 = fast_exp(fmaxf(fminf(c[j][0], 50.f), -80.f));
                        e1 = fast_exp(fmaxf(fminf(c[j][1], 50.f), -80.f));
                        e2 = fast_exp(fmaxf(fminf(c[j][2], 50.f), -80.f));
                        e3 = fast_exp(fmaxf(fminf(c[j][3], 50.f), -80.f));
                    } else {
                        e0 = __expf(fminf(c[j][0], 50.f));
                        e1 = __expf(fminf(c[j][1], 50.f));
                        e2 = __expf(fminf(c[j][2], 50.f));
                        e3 = __expf(fminf(c[j][3], 50.f));
                    }
                    c[j][0] = (cb     <= row0) ? e0 : 0.f;
                    c[j][1] = (cb + 1 <= row0) ? e1 : 0.f;
                    c[j][2] = (cb     <= row1) ? e2 : 0.f;
                    c[j][3] = (cb + 1 <= row1) ? e3 : 0.f;
                    rs0 += c[j][0] + c[j][1];
                    rs1 += c[j][2] + c[j][3];
                }
            }
            #pragma unroll
            for (int klq = 0; klq < 4; klq++) {
                unsigned ph[4], pl[4];
                pack_hilo(c[2 * klq][0],     c[2 * klq][1],     ph[0], pl[0]);
                pack_hilo(c[2 * klq][2],     c[2 * klq][3],     ph[1], pl[1]);
                pack_hilo(c[2 * klq + 1][0], c[2 * klq + 1][1], ph[2], pl[2]);
                pack_hilo(c[2 * klq + 1][2], c[2 * klq + 1][3], ph[3], pl[3]);
                int kb = klq * 8;
                #pragma unroll
                for (int nf = 0; nf < 4; nf++) {
                    int vc = nf * 8 + g;
                    unsigned vhf[2], vlf[2];
                    vhf[0] = Vs_hi[s][vc][kb + t];
                    vhf[1] = Vs_hi[s][vc][kb + t + 4];
                    vlf[0] = Vs_lo[s][vc][kb + t];
                    vlf[1] = Vs_lo[s][vc][kb + t + 4];
                    mma16816(o[nf], ph, vhf);
                    mma16816(o[nf], ph, vlf);
                    mma16816(o[nf], pl, vhf);
                }
            }
        }
        __syncthreads();
    }
    #undef ISSUE_TILE

    rs0 += __shfl_xor_sync(0xffffffffu, rs0, 1);
    rs0 += __shfl_xor_sync(0xffffffffu, rs0, 2);
    rs1 += __shfl_xor_sync(0xffffffffu, rs1, 1);
    rs1 += __shfl_xor_sync(0xffffffffu, rs1, 2);
    float i0 = 1.f / (rs0 + 1e-10f);
    float i1 = 1.f / (rs1 + 1e-10f);
    size_t r0 = (size_t)(b * TT + row0);
    #pragma unroll
    for (int nf = 0; nf < 4; nf++) {
        int vd = h * DKk + nf * 8 + 2 * t;
        *(float2*)(ov + r0 * DM + vd)       = make_float2(o[nf][0] * i0, o[nf][1] * i0);
        *(float2*)(ov + (r0 + 8) * DM + vd) = make_float2(o[nf][2] * i1, o[nf][3] * i1);
    }
}

// -------------------- launch --------------------------------------------------
extern "C" void kernel_launch(void* const* d_in, const int* in_sizes, int n_in,
                              void* d_out, int out_size) {
    const int*   x     = (const int*)  d_in[0];
    const float* emb   = (const float*)d_in[1];
    const float* pos   = (const float*)d_in[2];
    const float* wq    = (const float*)d_in[3];
    const float* wk    = (const float*)d_in[4];
    const float* wv    = (const float*)d_in[5];
    const float* wo    = (const float*)d_in[6];
    const float* mlp0  = (const float*)d_in[7];
    const float* mlpb  = (const float*)d_in[8];
    const float* mlp1  = (const float*)d_in[9];
    const float* unemb = (const float*)d_in[10];
    const float* bias  = (const float*)d_in[11];
    float* out = (float*)d_out;

    unsigned *hh_, *hl_, *qh_, *ql_, *kh_, *kl_, *yh_, *yl_, *wh_, *wl_, *vth_, *vtl_;
    float *ov_, *tmp_, *wos_;
    cudaGetSymbolAddress((void**)&hh_, g_hh);
    cudaGetSymbolAddress((void**)&hl_, g_hl);
    cudaGetSymbolAddress((void**)&qh_, g_qh);
    cudaGetSymbolAddress((void**)&ql_, g_ql);
    cudaGetSymbolAddress((void**)&kh_, g_kh);
    cudaGetSymbolAddress((void**)&kl_, g_kl);
    cudaGetSymbolAddress((void**)&yh_, g_yh);
    cudaGetSymbolAddress((void**)&yl_, g_yl);
    cudaGetSymbolAddress((void**)&wh_, g_wh);
    cudaGetSymbolAddress((void**)&wl_, g_wl);
    cudaGetSymbolAddress((void**)&vth_, g_vth);
    cudaGetSymbolAddress((void**)&vtl_, g_vtl);
    cudaGetSymbolAddress((void**)&ov_,  g_ov);
    cudaGetSymbolAddress((void**)&tmp_, g_tmp);
    cudaGetSymbolAddress((void**)&wos_, g_wosum);

    // dyn smem: A 2*2048*2 u32 + B 2*(16*BN)*2 u32
    const int SM128 = (8192 + 4 * 16 * 128) * 4;   // 65536 B
    const int SM64  = (8192 + 4 * 16 * 64)  * 4;   // 49152 B
    cudaFuncSetAttribute(mgemm_db<4, 128>, cudaFuncAttributeMaxDynamicSharedMemorySize, SM128);
    cudaFuncSetAttribute(mgemm_db<1, 128>, cudaFuncAttributeMaxDynamicSharedMemorySize, SM128);
    cudaFuncSetAttribute(mgemm_db<2, 128>, cudaFuncAttributeMaxDynamicSharedMemorySize, SM128);
    cudaFuncSetAttribute(mgemm_db<0, 64>,  cudaFuncAttributeMaxDynamicSharedMemorySize, SM64);

    detect_idx<<<1, 64>>>(x);
    convert_weights<<<(W_TOT + 255) / 256, 256>>>(wq, wk, wv, mlp0, mlp1, unemb);
    compute_wosum_all<<<(NL * DKk * DM + 255) / 256, 256>>>(wo);
    embed_ln_w<<<BT / 8, 256>>>(x, emb, pos);

    for (int l = 0; l < NL; l++) {
        const unsigned* wqkv_h = wh_ + (size_t)(l * 3) * DM * KP_DM;
        const unsigned* wqkv_l = wl_ + (size_t)(l * 3) * DM * KP_DM;
        const unsigned* m0h = wh_ + W_M0 + (size_t)l * DHid * KP_DM;
        const unsigned* m0l = wl_ + W_M0 + (size_t)l * DHid * KP_DM;
        const unsigned* m1h = wh_ + W_M1 + (size_t)l * DM * KP_HID;
        const unsigned* m1l = wl_ + W_M1 + (size_t)l * DM * KP_HID;

        mgemm_db<4, 128><<<dim3(6, BT / 128), 256, SM128>>>(
            hh_, hl_, wqkv_h, wqkv_l, nullptr, qh_, ql_, kh_, kl_, vth_, vtl_,
            nullptr, BT, DM, KP_DM);

        attention_mma2<<<dim3(TT / 128, BB * HH), 256>>>(qh_, ql_, kh_, kl_, vth_, vtl_, ov_);
        attn_out_ln_w<<<BT / 8, 256>>>(ov_, wos_ + (size_t)l * DKk * DM);

        mgemm_db<1, 128><<<dim3(DHid / 128, BT / 128), 256, SM128>>>(
            hh_, hl_, m0h, m0l, nullptr, yh_, yl_, nullptr, nullptr, nullptr, nullptr,
            mlpb + (size_t)l * DHid, BT, DHid, KP_DM);
        mgemm_db<0, 64><<<dim3(DM / 64, BT / 128), 256, SM64>>>(
            yh_, yl_, m1h, m1l, tmp_, nullptr, nullptr, nullptr, nullptr, nullptr, nullptr,
            nullptr, BT, DM, KP_HID);
        ln_residual_w<<<BT / 8, 256>>>(tmp_);
    }

    mgemm_db<2, 128><<<dim3(ND / 128, BT / 128), 256, SM128>>>(
        hh_, hl_, wh_ + W_UE, wl_ + W_UE, out, nullptr, nullptr, nullptr, nullptr,
        nullptr, nullptr, bias, BT, ND, KP_DM);
}

// round 14
// speedup vs baseline: 1.2126x; 1.0312x over previous
#include <cuda_runtime.h>
#include <cuda_bf16.h>
#include <math.h>

#define BB 4
#define TT 2048
#define BT (BB*TT)
#define DM 256
#define HH 8
#define DKk 32
#define DHid 1024
#define ND 8192
#define NL 4

#define KP_DM (DM/2)      // 128 pairs
#define KP_HID (DHid/2)   // 512 pairs

// packed-weight regions (u32). B operands FRAGMENT-MAJOR (8n x 8kp tiles, 64 u32).
#define W_M0 (NL*3*DM*KP_DM)
#define W_M1 (W_M0 + NL*DHid*KP_DM)
#define W_UE (W_M1 + NL*DM*KP_HID)
#define W_TOT (W_UE + ND*KP_DM)

// -------------------- scratch (device globals) ---------------------------------
__device__ float    g_h  [BT*DM];
__device__ unsigned g_hh [BT*KP_DM];   // A-fragment-major (16m x 8kp tiles)
__device__ unsigned g_hl [BT*KP_DM];
__device__ unsigned g_qh [BT*KP_DM];   // row-major [token][kp]
__device__ unsigned g_ql [BT*KP_DM];
__device__ unsigned g_kh [BT*KP_DM];   // K fragment-major: [bh][keyT(256)][kpT(2)][64]
__device__ unsigned g_kl [BT*KP_DM];
__device__ unsigned g_vth[BT*KP_DM];   // V fragment-major: [bh][kpT(128)][vdT(4)][64]
__device__ unsigned g_vtl[BT*KP_DM];
__device__ float    g_ov [BT*DM];
__device__ unsigned g_yh [BT*KP_HID];  // A-fragment-major
__device__ unsigned g_yl [BT*KP_HID];
__device__ float    g_tmp[BT*DM];
__device__ unsigned g_wh [W_TOT];
__device__ unsigned g_wl [W_TOT];
__device__ float    g_wosum[NL*DKk*DM];
__device__ int      g_is64;

// -------------------- helpers -------------------------------------------------
__device__ __forceinline__ void pack_hilo(float x, float y, unsigned& hi, unsigned& lo) {
    unsigned h;
    asm("cvt.rn.bf16x2.f32 %0, %1, %2;" : "=r"(h) : "f"(y), "f"(x));
    float xr = x - __uint_as_float(h << 16);
    float yr = y - __uint_as_float(h & 0xffff0000u);
    asm("cvt.rn.bf16x2.f32 %0, %1, %2;" : "=r"(lo) : "f"(yr), "f"(xr));
    hi = h;
}

__device__ __forceinline__ void mma16816(float* c, const unsigned* a, const unsigned* b) {
    asm volatile(
        "mma.sync.aligned.m16n8k16.row.col.f32.bf16.bf16.f32 "
        "{%0,%1,%2,%3}, {%4,%5,%6,%7}, {%8,%9}, {%0,%1,%2,%3};\n"
        : "+f"(c[0]), "+f"(c[1]), "+f"(c[2]), "+f"(c[3])
        : "r"(a[0]), "r"(a[1]), "r"(a[2]), "r"(a[3]), "r"(b[0]), "r"(b[1]));
}

__device__ __forceinline__ void cp16(void* sdst, const void* gsrc) {
    unsigned sa = (unsigned)__cvta_generic_to_shared(sdst);
    asm volatile("cp.async.cg.shared.global [%0], [%1], 16;\n" :: "r"(sa), "l"(gsrc));
}
#define CP_COMMIT() asm volatile("cp.async.commit_group;\n" ::: "memory")
template <int N> __device__ __forceinline__ void cp_wait() {
    asm volatile("cp.async.wait_group %0;\n" :: "n"(N) : "memory");
}

__device__ __forceinline__ float warp_sum(float v) {
    #pragma unroll
    for (int o = 16; o; o >>= 1) v += __shfl_xor_sync(0xffffffffu, v, o);
    return v;
}

__device__ __forceinline__ float fast_exp(float x) {
    float t = x * 1.44269504f;
    float fi = rintf(t);
    float f = t - fi;
    int ei = __float2int_rn(fi);
    float p = 1.33336e-3f;
    p = fmaf(p, f, 9.61813e-3f);
    p = fmaf(p, f, 5.55041e-2f);
    p = fmaf(p, f, 2.40227e-1f);
    p = fmaf(p, f, 6.93147e-1f);
    p = fmaf(p, f, 1.0f);
    return __uint_as_float((unsigned)((ei + 127) << 23)) * p;
}

// A-fragment-major index: tile = 16m x 8kp (128 u32)
__device__ __forceinline__ size_t afrag_idx(int m, int kp, int kpt8) {
    int quad = (m & 7) * 4 + (kp & 3);
    int word = ((m >> 3) & 1) + (((kp >> 2) & 1) << 1);
    return ((size_t)(m >> 4) * kpt8 + (kp >> 3)) * 128 + quad * 4 + word;
}

// -------------------- index dtype probe ---------------------------------------
__global__ void detect_idx(const int* __restrict__ xi) {
    __shared__ int ok;
    if (threadIdx.x == 0) ok = 1;
    __syncthreads();
    if (xi[2 * threadIdx.x + 1] != 0) atomicAnd(&ok, 0);
    __syncthreads();
    if (threadIdx.x == 0) g_is64 = ok;
}

// -------------------- one-shot weight pre-conversion (B fragment-major) --------
__device__ __forceinline__ size_t frag_idx(int n, int kp, int kpt) {
    return ((size_t)(n >> 3) * kpt + (kp >> 3)) * 64
         + (size_t)((4 * (n & 7) + (kp & 3)) * 2 + ((kp >> 2) & 1));
}

__global__ __launch_bounds__(256) void convert_weights(
    const float* __restrict__ wq, const float* __restrict__ wk,
    const float* __restrict__ wv, const float* __restrict__ m0,
    const float* __restrict__ m1, const float* __restrict__ ue) {
    int i = blockIdx.x * 256 + threadIdx.x;
    if (i >= W_TOT) return;
    float a, b;
    size_t out;
    if (i < W_M0) {                       // QKV per-head [n/32][k][n%32] source
        int l3 = i >> 15;
        int r  = i & 32767;
        int kp = r >> 8;
        int n  = r & 255;
        int l = l3 / 3, mi = l3 % 3;
        const float* W = (mi == 0) ? wq : (mi == 1) ? wk : wv;
        size_t base = (size_t)l * HH * DM * DKk + (size_t)(n >> 5) * DM * DKk + (n & 31);
        a = W[base + (size_t)(2 * kp)     * DKk];
        b = W[base + (size_t)(2 * kp + 1) * DKk];
        out = (size_t)l3 * 32768 + frag_idx(n, kp, KP_DM / 8);
    } else if (i < W_M1) {                // mlp0 [k][1024]
        int r = i - W_M0;
        int l = r >> 17;
        int rr = r & 131071;
        int kp = rr >> 10;
        int n  = rr & 1023;
        const float* W = m0 + (size_t)l * DM * DHid;
        a = W[(size_t)(2 * kp)     * DHid + n];
        b = W[(size_t)(2 * kp + 1) * DHid + n];
        out = W_M0 + (size_t)l * 131072 + frag_idx(n, kp, KP_DM / 8);
    } else if (i < W_UE) {                // mlp1 [k][256]
        int r = i - W_M1;
        int l = r >> 17;
        int rr = r & 131071;
        int kp = rr >> 8;
        int n  = rr & 255;
        const float* W = m1 + (size_t)l * DHid * DM;
        a = W[(size_t)(2 * kp)     * DM + n];
        b = W[(size_t)(2 * kp + 1) * DM + n];
        out = W_M1 + (size_t)l * 131072 + frag_idx(n, kp, KP_HID / 8);
    } else {                              // unembedding [k][8192]
        int r = i - W_UE;
        int kp = r >> 13;
        int n  = r & 8191;
        a = ue[(size_t)(2 * kp)     * ND + n];
        b = ue[(size_t)(2 * kp + 1) * ND + n];
        out = W_UE + frag_idx(n, kp, KP_DM / 8);
    }
    unsigned hi, lo;
    pack_hilo(a, b, hi, lo);
    g_wh[out] = hi;
    g_wl[out] = lo;
}

// -------------------- wo summed over heads --------------------------------------
__global__ void compute_wosum_all(const float* __restrict__ wo) {
    int i = blockIdx.x * 256 + threadIdx.x;
    if (i < NL * DKk * DM) {
        int l = i / (DKk * DM);
        int r = i % (DKk * DM);
        float s = 0.f;
        #pragma unroll
        for (int hh = 0; hh < HH; hh++)
            s += wo[(size_t)l * HH * DKk * DM + (size_t)hh * DKk * DM + r];
        g_wosum[i] = s;
    }
}

// -------------------- warp-per-token LN (A-fragment-major packed out) -----------
__device__ __forceinline__ void ln_store_warp(int token, int lane, float* val) {
    float s = 0.f;
    #pragma unroll
    for (int j = 0; j < 8; j++) s += val[j];
    s = warp_sum(s);
    float m = s * (1.f / DM);
    float vv = 0.f;
    #pragma unroll
    for (int j = 0; j < 8; j++) { val[j] -= m; vv += val[j] * val[j]; }
    vv = warp_sum(vv);
    float inv = rsqrtf(vv * (1.f / DM) + 1e-5f);
    #pragma unroll
    for (int j = 0; j < 8; j++) {
        float out = val[j] * inv;
        int d = j * 32 + lane;
        g_h[(size_t)token * DM + d] = out;
        float other = __shfl_xor_sync(0xffffffffu, out, 1);
        if (!(lane & 1)) {
            unsigned hi, lo;
            pack_hilo(out, other, hi, lo);
            int kp = j * 16 + (lane >> 1);
            size_t o = afrag_idx(token & 15, kp, KP_DM / 8)
                     + (size_t)(token >> 4) * (size_t)(16 * KP_DM);
            g_hh[o] = hi;
            g_hl[o] = lo;
        }
    }
}

__global__ __launch_bounds__(256) void embed_ln_w(const int* __restrict__ xi,
                                                  const float* __restrict__ emb,
                                                  const float* __restrict__ pos) {
    int token = blockIdx.x * 8 + (threadIdx.x >> 5);
    int lane = threadIdx.x & 31;
    int t = token % TT;
    int idx = g_is64 ? xi[2 * token] : xi[token];
    float val[8];
    #pragma unroll
    for (int j = 0; j < 8; j++) {
        int d = j * 32 + lane;
        val[j] = emb[(size_t)idx * DM + d] + pos[(size_t)t * DM + d];
    }
    ln_store_warp(token, lane, val);
}

__global__ __launch_bounds__(256) void attn_out_ln_w(const float* __restrict__ ov,
                                                     const float* __restrict__ wos) {
    int token = blockIdx.x * 8 + (threadIdx.x >> 5);
    int lane = threadIdx.x & 31;
    float vs = 0.f;
    float val[8];
    #pragma unroll
    for (int j = 0; j < 8; j++) {
        float o = ov[(size_t)token * DM + j * 32 + lane];
        vs += o;
        val[j] = g_h[(size_t)token * DM + j * 32 + lane];
    }
    #pragma unroll
    for (int v = 0; v < DKk; v++) {
        float sv = __shfl_sync(0xffffffffu, vs, v);
        #pragma unroll
        for (int j = 0; j < 8; j++) val[j] += sv * wos[v * DM + j * 32 + lane];
    }
    ln_store_warp(token, lane, val);
}

__global__ __launch_bounds__(256) void ln_residual_w(const float* __restrict__ add) {
    int token = blockIdx.x * 8 + (threadIdx.x >> 5);
    int lane = threadIdx.x & 31;
    float val[8];
    #pragma unroll
    for (int j = 0; j < 8; j++) {
        int d = j * 32 + lane;
        val[j] = g_h[(size_t)token * DM + d] + add[(size_t)token * DM + d];
    }
    ln_store_warp(token, lane, val);
}

// -------------------- packed GEMM: fragment-major A AND B ------------------------
// EPI 0: fp32. 1: relu(acc+bias)->A-fragment-major packed. 2: acc+bias fp32.
// EPI 4: fused QKV; q->row-major Ch/Cl, k->K-fragment-major Ch2/Cl2,
//        v->V-fragment-major Vh/Vl.
template <int EPI, int BN>
__global__ __launch_bounds__(256, 2) void mgemm_db(
    const unsigned* __restrict__ Ah, const unsigned* __restrict__ Al,
    const unsigned* __restrict__ Bh, const unsigned* __restrict__ Bl,
    float* __restrict__ C, unsigned* __restrict__ Ch, unsigned* __restrict__ Cl,
    unsigned* __restrict__ Ch2, unsigned* __restrict__ Cl2,
    unsigned* __restrict__ Vh, unsigned* __restrict__ Vl,
    const float* __restrict__ bias, int M, int N, int KP) {
    constexpr int NT = BN / 16;
    constexpr int BS = 16 * BN;             // one B buffer (u32)
    constexpr int AS = 2048;                // one A buffer (u32)
    extern __shared__ unsigned smq[];
    unsigned* AsH = smq;
    unsigned* AsL = smq + 2 * AS;
    unsigned* BsH = smq + 4 * AS;
    unsigned* BsL = BsH + 2 * BS;

    const int bm = blockIdx.y * 128;
    int bn, mat = 0;
    if (EPI == 4) {
        mat = blockIdx.x >> 1;
        bn = (blockIdx.x & 1) * 128;
        Bh += (size_t)mat * DM * KP_DM;
        Bl += (size_t)mat * DM * KP_DM;
    } else {
        bn = blockIdx.x * BN;
    }
    const int tid  = threadIdx.x;
    const int lane = tid & 31;
    const int wid  = tid >> 5;
    const int g = lane >> 2;
    const int t = lane & 3;
    const int wm = (wid & 3) * 32;
    const int wn = (wid >> 2) * (BN / 2);
    const int kpt  = KP >> 3;

    float acc[2][NT][4];
    #pragma unroll
    for (int mt = 0; mt < 2; mt++)
        #pragma unroll
        for (int nt = 0; nt < NT; nt++)
            #pragma unroll
            for (int r = 0; r < 4; r++) acc[mt][nt][r] = 0.f;

    #define FILL_TILE(s, kp0)                                                       \
        do {                                                                         \
            _Pragma("unroll")                                                        \
            for (int it_ = 0; it_ < 2; it_++) {                                      \
                int i_ = it_ * 256 + tid;                                            \
                int tl_ = i_ >> 5;                                                   \
                size_t ga_ = ((size_t)((bm >> 4) + (tl_ >> 1)) * kpt                 \
                              + ((kp0) >> 3) + (tl_ & 1)) * 128 + (i_ & 31) * 4;     \
                cp16(&AsH[(s) * AS + i_ * 4], Ah + ga_);                             \
                cp16(&AsL[(s) * AS + i_ * 4], Al + ga_);                             \
            }                                                                        \
            _Pragma("unroll")                                                        \
            for (int it_ = 0; it_ < BN / 64; it_++) {                                \
                int f_ = it_ * 256 + tid;                                            \
                size_t gb_ = ((size_t)((bn >> 3) + (f_ >> 5)) * kpt                  \
                              + ((kp0) >> 3) + ((f_ >> 4) & 1)) * 64 + (f_ & 15) * 4;\
                cp16(&BsH[(s) * BS + f_ * 4], Bh + gb_);                             \
                cp16(&BsL[(s) * BS + f_ * 4], Bl + gb_);                             \
            }                                                                        \
        } while (0)

    const int NKT = KP / 16;
    FILL_TILE(0, 0);
    CP_COMMIT();

    for (int kt = 0; kt < NKT; kt++) {
        const int s = kt & 1;
        if (kt + 1 < NKT) {
            FILL_TILE(s ^ 1, (kt + 1) * 16);
            CP_COMMIT();
            cp_wait<1>();
        } else {
            cp_wait<0>();
        }
        __syncthreads();

        #pragma unroll
        for (int ks = 0; ks < 2; ks++) {
            unsigned ah[2][4], al[2][4];
            #pragma unroll
            for (int mt = 0; mt < 2; mt++) {
                int atile = (((wid & 3) * 2 + mt) * 2 + ks) * 128 + lane * 4;
                uint4 uh = *(const uint4*)&AsH[s * AS + atile];
                uint4 ul = *(const uint4*)&AsL[s * AS + atile];
                ah[mt][0] = uh.x; ah[mt][1] = uh.y; ah[mt][2] = uh.z; ah[mt][3] = uh.w;
                al[mt][0] = ul.x; al[mt][1] = ul.y; al[mt][2] = ul.z; al[mt][3] = ul.w;
            }
            const unsigned* bH = BsH + s * BS + ks * 64 + lane * 2;
            const unsigned* bL = BsL + s * BS + ks * 64 + lane * 2;
            #pragma unroll
            for (int nt = 0; nt < NT; nt++) {
                int nti = (wn >> 3) + nt;
                uint2 u2h = *(const uint2*)&bH[nti * 128];
                uint2 u2l = *(const uint2*)&bL[nti * 128];
                unsigned bh[2] = {u2h.x, u2h.y};
                unsigned bl[2] = {u2l.x, u2l.y};
                #pragma unroll
                for (int mt = 0; mt < 2; mt++) {
                    mma16816(acc[mt][nt], ah[mt], bh);
                    mma16816(acc[mt][nt], ah[mt], bl);
                    mma16816(acc[mt][nt], al[mt], bh);
                }
            }
        }
        __syncthreads();
    }
    #undef FILL_TILE

    const int opt = N >> 4;
    #pragma unroll
    for (int mt = 0; mt < 2; mt++) {
        #pragma unroll
        for (int nt = 0; nt < NT; nt++) {
            int row0 = bm + wm + mt * 16 + g;
            int col  = bn + wn + nt * 8 + 2 * t;
            float v0 = acc[mt][nt][0], v1 = acc[mt][nt][1];
            float v2 = acc[mt][nt][2], v3 = acc[mt][nt][3];
            if (EPI == 1) {
                float b0 = bias[col], b1 = bias[col + 1];
                v0 = fmaxf(v0 + b0, 0.f); v1 = fmaxf(v1 + b1, 0.f);
                v2 = fmaxf(v2 + b0, 0.f); v3 = fmaxf(v3 + b1, 0.f);
            }
            if (EPI == 2) {
                float b0 = bias[col], b1 = bias[col + 1];
                v0 += b0; v1 += b1; v2 += b0; v3 += b1;
            }
            if (EPI == 4 && mat == 2) {
                // V fragment-major [bh][kpT][vdT][64]. Thread (g even) produces
                // (vd,kp),(vd,kp+4) -> words 2q,2q+1 and (vd+1,kp),(vd+1,kp+4)
                // -> words 2q+8,2q+9 (q = 4*(vd&7)+(kp&3), b=0 for these threads).
                float p0 = __shfl_xor_sync(0xffffffffu, v0, 4);
                float p1 = __shfl_xor_sync(0xffffffffu, v1, 4);
                float p2 = __shfl_xor_sync(0xffffffffu, v2, 4);
                float p3 = __shfl_xor_sync(0xffffffffu, v3, 4);
                if (!(g & 1)) {
                    int bb = row0 >> 11;
                    int tt = row0 & (TT - 1);
                    int h  = col >> 5, vd = col & 31;
                    int kp = tt >> 1;
                    int q  = 4 * (vd & 7) + (kp & 3);
                    size_t base = (size_t)(bb * HH + h) * 32768
                                + (size_t)(kp >> 3) * 256 + (size_t)(vd >> 3) * 64
                                + (size_t)(2 * q);
                    unsigned w0, x0, w1, x1, w2, x2, w3, x3;
                    pack_hilo(v0, p0, w0, x0);   // (vd,   kp)
                    pack_hilo(v2, p2, w1, x1);   // (vd,   kp+4)
                    pack_hilo(v1, p1, w2, x2);   // (vd+1, kp)
                    pack_hilo(v3, p3, w3, x3);   // (vd+1, kp+4)
                    *(uint2*)&Vh[base]     = make_uint2(w0, w1);
                    *(uint2*)&Vl[base]     = make_uint2(x0, x1);
                    *(uint2*)&Vh[base + 8] = make_uint2(w2, w3);
                    *(uint2*)&Vl[base + 8] = make_uint2(x2, x3);
                }
            } else if (EPI == 0 || EPI == 2) {
                *(float2*)(C + (size_t)row0 * N + col)       = make_float2(v0, v1);
                *(float2*)(C + (size_t)(row0 + 8) * N + col) = make_float2(v2, v3);
            } else if (EPI == 1) {
                unsigned h0, l0, h1, l1;
                pack_hilo(v0, v1, h0, l0);
                pack_hilo(v2, v3, h1, l1);
                int cp = col >> 1;
                size_t tb = ((size_t)(row0 >> 4) * opt + (cp >> 3)) * 128
                          + (size_t)(((g & 7) * 4 + (cp & 3)) * 4 + (((cp >> 2) & 1) << 1));
                Ch[tb]     = h0;  Cl[tb]     = l0;
                Ch[tb + 1] = h1;  Cl[tb + 1] = l1;
            } else if (EPI == 4 && mat == 1) {
                // K fragment-major: [bh][keyT][kpT][64]
                unsigned h0, l0, h1, l1;
                pack_hilo(v0, v1, h0, l0);
                pack_hilo(v2, v3, h1, l1);
                int bb = row0 >> 11;
                int tt = row0 & (TT - 1);
                int h  = col >> 5;
                int kph = (col >> 1) & 15;
                size_t kb = (size_t)(bb * HH + h) * 32768
                          + ((size_t)(tt >> 3) * 2 + (kph >> 3)) * 64
                          + (size_t)((4 * (tt & 7) + (kph & 3)) * 2 + ((kph >> 2) & 1));
                Ch2[kb]       = h0;  Cl2[kb]       = l0;   // key tt
                Ch2[kb + 128] = h1;  Cl2[kb + 128] = l1;   // key tt+8
            } else {
                // EPI==4 mat==0 (Q): row-major packed
                unsigned h0, l0, h1, l1;
                pack_hilo(v0, v1, h0, l0);
                pack_hilo(v2, v3, h1, l1);
                int NP = N >> 1, cp = col >> 1;
                Ch[(size_t)row0 * NP + cp]       = h0;
                Cl[(size_t)row0 * NP + cp]       = l0;
                Ch[(size_t)(row0 + 8) * NP + cp] = h1;
                Cl[(size_t)(row0 + 8) * NP + cp] = l1;
            }
        }
    }
}

// -------------------- tensor-core causal attention (fragment-major K/V) ---------
__global__ __launch_bounds__(256, 2) void attention_mma2(
    const unsigned* __restrict__ qh, const unsigned* __restrict__ ql,
    const unsigned* __restrict__ kh, const unsigned* __restrict__ kl,
    const unsigned* __restrict__ vth, const unsigned* __restrict__ vtl,
    float* __restrict__ ov) {
    __shared__ unsigned Ks_hi[2][1024];
    __shared__ unsigned Ks_lo[2][1024];
    __shared__ unsigned Vs_hi[2][1024];
    __shared__ unsigned Vs_lo[2][1024];

    const int bh = blockIdx.y;
    const int b  = bh >> 3, h = bh & 7;
    const int t0 = (gridDim.x - 1 - blockIdx.x) * 128;
    const int tid  = threadIdx.x;
    const int lane = tid & 31;
    const int wid  = tid >> 5;
    const int g = lane >> 2;
    const int t = lane & 3;
    const int wm = wid * 16;

    unsigned qfh[2][4], qfl[2][4];
    {
        size_t base = (size_t)(b * TT + t0 + wm) * KP_DM + h * 16;
        #pragma unroll
        for (int ks = 0; ks < 2; ks++) {
            qfh[ks][0] = qh[base + (size_t)g * KP_DM + ks * 8 + t];
            qfh[ks][1] = qh[base + (size_t)(g + 8) * KP_DM + ks * 8 + t];
            qfh[ks][2] = qh[base + (size_t)g * KP_DM + ks * 8 + t + 4];
            qfh[ks][3] = qh[base + (size_t)(g + 8) * KP_DM + ks * 8 + t + 4];
            qfl[ks][0] = ql[base + (size_t)g * KP_DM + ks * 8 + t];
            qfl[ks][1] = ql[base + (size_t)(g + 8) * KP_DM + ks * 8 + t];
            qfl[ks][2] = ql[base + (size_t)g * KP_DM + ks * 8 + t + 4];
            qfl[ks][3] = ql[base + (size_t)(g + 8) * KP_DM + ks * 8 + t + 4];
        }
    }

    float o[4][4];
    #pragma unroll
    for (int nf = 0; nf < 4; nf++)
        #pragma unroll
        for (int r = 0; r < 4; r++) o[nf][r] = 0.f;
    float rs0 = 0.f, rs1 = 0.f;

    const int row0 = t0 + wm + g;
    const int row1 = row0 + 8;
    const int nit = t0 / 64 + 2;

    #define ISSUE_TILE(s, o0)                                                        \
        do {                                                                          \
            size_t gi = (size_t)bh * 32768 + (size_t)(o0) * 16 + tid * 4;             \
            cp16(&Ks_hi[s][tid * 4], kh + gi);                                        \
            cp16(&Ks_lo[s][tid * 4], kl + gi);                                        \
            cp16(&Vs_hi[s][tid * 4], vth + gi);                                       \
            cp16(&Vs_lo[s][tid * 4], vtl + gi);                                       \
        } while (0)

    ISSUE_TILE(0, 0);
    CP_COMMIT();

    for (int it = 0; it < nit; it++) {
        const int o0 = it * 64;
        const int s = it & 1;
        if (it + 1 < nit) {
            ISSUE_TILE(s ^ 1, o0 + 64);
            CP_COMMIT();
            cp_wait<1>();
        } else {
            cp_wait<0>();
        }
        __syncthreads();

        if (o0 <= t0 + wm + 15) {
            float c[8][4];
            #pragma unroll
            for (int j = 0; j < 8; j++)
                #pragma unroll
                for (int r = 0; r < 4; r++) c[j][r] = 0.f;
            #pragma unroll
            for (int j = 0; j < 8; j++) {
                #pragma unroll
                for (int ks = 0; ks < 2; ks++) {
                    uint2 uh = *(const uint2*)&Ks_hi[s][(j * 2 + ks) * 64 + lane * 2];
                    uint2 ul = *(const uint2*)&Ks_lo[s][(j * 2 + ks) * 64 + lane * 2];
                    unsigned bhf[2] = {uh.x, uh.y};
                    unsigned blf[2] = {ul.x, ul.y};
                    mma16816(c[j], qfh[ks], bhf);
                    mma16816(c[j], qfh[ks], blf);
                    mma16816(c[j], qfl[ks], bhf);
                }
            }
            if (o0 + 63 <= t0 + wm) {
                #pragma unroll
                for (int j = 0; j < 8; j++) {
                    if (j < 2) {
                        c[j][0] = fast_exp(fmaxf(fminf(c[j][0], 50.f), -80.f));
                        c[j][1] = fast_exp(fmaxf(fminf(c[j][1], 50.f), -80.f));
                        c[j][2] = fast_exp(fmaxf(fminf(c[j][2], 50.f), -80.f));
                        c[j][3] = fast_exp(fmaxf(fminf(c[j][3], 50.f), -80.f));
                    } else {
                        c[j][0] = __expf(fminf(c[j][0], 50.f));
                        c[j][1] = __expf(fminf(c[j][1], 50.f));
                        c[j][2] = __expf(fminf(c[j][2], 50.f));
                        c[j][3] = __expf(fminf(c[j][3], 50.f));
                    }
                    rs0 += c[j][0] + c[j][1];
                    rs1 += c[j][2] + c[j][3];
                }
            } else {
                #pragma unroll
                for (int j = 0; j < 8; j++) {
                    int cb = o0 + j * 8 + 2 * t;
                    float e0, e1, e2, e3;
                    if (j < 2) {
                        e0 = fast_exp(fmaxf(fminf(c[j][0], 50.f), -80.f));
                        e1 = fast_exp(fmaxf(fminf(c[j][1], 50.f), -80.f));
                        e2 = fast_exp(fmaxf(fminf(c[j][2], 50.f), -80.f));
                        e3 = fast_exp(fmaxf(fminf(c[j][3], 50.f), -80.f));
                    } else {
                        e0 = __expf(fminf(c[j][0], 50.f));
                        e1 = __expf(fminf(c[j][1], 50.f));
                        e2 = __expf(fminf(c[j][2], 50.f));
                        e3 = __expf(fminf(c[j][3], 50.f));
                    }
                    c[j][0] = (cb     <= row0) ? e0 : 0.f;
                    c[j][1] = (cb + 1 <= row0) ? e1 : 0.f;
                    c[j][2] = (cb     <= row1) ? e2 : 0.f;
                    c[j][3] = (cb + 1 <= row1) ? e3 : 0.f;
                    rs0 += c[j][0] + c[j][1];
                    rs1 += c[j][2] + c[j][3];
                }
            }
            #pragma unroll
            for (int klq = 0; klq < 4; klq++) {
                unsigned ph[4], pl[4];
                pack_hilo(c[2 * klq][0],     c[2 * klq][1],     ph[0], pl[0]);
                pack_hilo(c[2 * klq][2],     c[2 * klq][3],     ph[1], pl[1]);
                pack_hilo(c[2 * klq + 1][0], c[2 * klq + 1][1], ph[2], pl[2]);
                pack_hilo(c[2 * klq + 1][2], c[2 * klq + 1][3], ph[3], pl[3]);
                #pragma unroll
                for (int nf = 0; nf < 4; nf++) {
                    uint2 vh2 = *(const uint2*)&Vs_hi[s][(klq * 4 + nf) * 64 + lane * 2];
                    uint2 vl2 = *(const uint2*)&Vs_lo[s][(klq * 4 + nf) * 64 + lane * 2];
                    unsigned vhf[2] = {vh2.x, vh2.y};
                    unsigned vlf[2] = {vl2.x, vl2.y};
                    mma16816(o[nf], ph, vhf);
                    mma16816(o[nf], ph, vlf);
                    mma16816(o[nf], pl, vhf);
                }
            }
        }
        __syncthreads();
    }
    #undef ISSUE_TILE

    rs0 += __shfl_xor_sync(0xffffffffu, rs0, 1);
    rs0 += __shfl_xor_sync(0xffffffffu, rs0, 2);
    rs1 += __shfl_xor_sync(0xffffffffu, rs1, 1);
    rs1 += __shfl_xor_sync(0xffffffffu, rs1, 2);
    float i0 = 1.f / (rs0 + 1e-10f);
    float i1 = 1.f / (rs1 + 1e-10f);
    size_t r0 = (size_t)(b * TT + row0);
    #pragma unroll
    for (int nf = 0; nf < 4; nf++) {
        int vd = h * DKk + nf * 8 + 2 * t;
        *(float2*)(ov + r0 * DM + vd)       = make_float2(o[nf][0] * i0, o[nf][1] * i0);
        *(float2*)(ov + (r0 + 8) * DM + vd) = make_float2(o[nf][2] * i1, o[nf][3] * i1);
    }
}

// -------------------- launch --------------------------------------------------
extern "C" void kernel_launch(void* const* d_in, const int* in_sizes, int n_in,
                              void* d_out, int out_size) {
    const int*   x     = (const int*)  d_in[0];
    const float* emb   = (const float*)d_in[1];
    const float* pos   = (const float*)d_in[2];
    const float* wq    = (const float*)d_in[3];
    const float* wk    = (const float*)d_in[4];
    const float* wv    = (const float*)d_in[5];
    const float* wo    = (const float*)d_in[6];
    const float* mlp0  = (const float*)d_in[7];
    const float* mlpb  = (const float*)d_in[8];
    const float* mlp1  = (const float*)d_in[9];
    const float* unemb = (const float*)d_in[10];
    const float* bias  = (const float*)d_in[11];
    float* out = (float*)d_out;

    unsigned *hh_, *hl_, *qh_, *ql_, *kh_, *kl_, *yh_, *yl_, *wh_, *wl_, *vth_, *vtl_;
    float *ov_, *tmp_, *wos_;
    cudaGetSymbolAddress((void**)&hh_, g_hh);
    cudaGetSymbolAddress((void**)&hl_, g_hl);
    cudaGetSymbolAddress((void**)&qh_, g_qh);
    cudaGetSymbolAddress((void**)&ql_, g_ql);
    cudaGetSymbolAddress((void**)&kh_, g_kh);
    cudaGetSymbolAddress((void**)&kl_, g_kl);
    cudaGetSymbolAddress((void**)&yh_, g_yh);
    cudaGetSymbolAddress((void**)&yl_, g_yl);
    cudaGetSymbolAddress((void**)&wh_, g_wh);
    cudaGetSymbolAddress((void**)&wl_, g_wl);
    cudaGetSymbolAddress((void**)&vth_, g_vth);
    cudaGetSymbolAddress((void**)&vtl_, g_vtl);
    cudaGetSymbolAddress((void**)&ov_,  g_ov);
    cudaGetSymbolAddress((void**)&tmp_, g_tmp);
    cudaGetSymbolAddress((void**)&wos_, g_wosum);

    const int SM128 = (8192 + 4 * 16 * 128) * 4;   // 65536 B
    const int SM64  = (8192 + 4 * 16 * 64)  * 4;   // 49152 B
    cudaFuncSetAttribute(mgemm_db<4, 128>, cudaFuncAttributeMaxDynamicSharedMemorySize, SM128);
    cudaFuncSetAttribute(mgemm_db<1, 128>, cudaFuncAttributeMaxDynamicSharedMemorySize, SM128);
    cudaFuncSetAttribute(mgemm_db<2, 128>, cudaFuncAttributeMaxDynamicSharedMemorySize, SM128);
    cudaFuncSetAttribute(mgemm_db<0, 64>,  cudaFuncAttributeMaxDynamicSharedMemorySize, SM64);

    detect_idx<<<1, 64>>>(x);
    convert_weights<<<(W_TOT + 255) / 256, 256>>>(wq, wk, wv, mlp0, mlp1, unemb);
    compute_wosum_all<<<(NL * DKk * DM + 255) / 256, 256>>>(wo);
    embed_ln_w<<<BT / 8, 256>>>(x, emb, pos);

    for (int l = 0; l < NL; l++) {
        const unsigned* wqkv_h = wh_ + (size_t)(l * 3) * DM * KP_DM;
        const unsigned* wqkv_l = wl_ + (size_t)(l * 3) * DM * KP_DM;
        const unsigned* m0h = wh_ + W_M0 + (size_t)l * DHid * KP_DM;
        const unsigned* m0l = wl_ + W_M0 + (size_t)l * DHid * KP_DM;
        const unsigned* m1h = wh_ + W_M1 + (size_t)l * DM * KP_HID;
        const unsigned* m1l = wl_ + W_M1 + (size_t)l * DM * KP_HID;

        mgemm_db<4, 128><<<dim3(6, BT / 128), 256, SM128>>>(
            hh_, hl_, wqkv_h, wqkv_l, nullptr, qh_, ql_, kh_, kl_, vth_, vtl_,
            nullptr, BT, DM, KP_DM);

        attention_mma2<<<dim3(TT / 128, BB * HH), 256>>>(qh_, ql_, kh_, kl_, vth_, vtl_, ov_);
        attn_out_ln_w<<<BT / 8, 256>>>(ov_, wos_ + (size_t)l * DKk * DM);

        mgemm_db<1, 128><<<dim3(DHid / 128, BT / 128), 256, SM128>>>(
            hh_, hl_, m0h, m0l, nullptr, yh_, yl_, nullptr, nullptr, nullptr, nullptr,
            mlpb + (size_t)l * DHid, BT, DHid, KP_DM);
        mgemm_db<0, 64><<<dim3(DM / 64, BT / 128), 256, SM64>>>(
            yh_, yl_, m1h, m1l, tmp_, nullptr, nullptr, nullptr, nullptr, nullptr, nullptr,
            nullptr, BT, DM, KP_HID);
        ln_residual_w<<<BT / 8, 256>>>(tmp_);
    }

    mgemm_db<2, 128><<<dim3(ND / 128, BT / 128), 256, SM128>>>(
        hh_, hl_, wh_ + W_UE, wl_ + W_UE, out, nullptr, nullptr, nullptr, nullptr,
        nullptr, nullptr, bias, BT, ND, KP_DM);
}

// round 15
// speedup vs baseline: 1.3283x; 1.0954x over previous
#include <cuda_runtime.h>
#include <cuda_bf16.h>
#include <math.h>

#define BB 4
#define TT 2048
#define BT (BB*TT)
#define DM 256
#define HH 8
#define DKk 32
#define DHid 1024
#define ND 8192
#define NL 4

#define KP_DM (DM/2)      // 128 pairs
#define KP_HID (DHid/2)   // 512 pairs

// packed-weight regions (u32). B operands FRAGMENT-MAJOR (8n x 8kp tiles, 64 u32).
// UE region holds fp16x2 single-precision-pass weights (hi array only).
#define W_M0 (NL*3*DM*KP_DM)
#define W_M1 (W_M0 + NL*DHid*KP_DM)
#define W_UE (W_M1 + NL*DM*KP_HID)
#define W_TOT (W_UE + ND*KP_DM)

// -------------------- scratch (device globals) ---------------------------------
__device__ float    g_h  [BT*DM];
__device__ unsigned g_hh [BT*KP_DM];   // A-fragment-major bf16x2 hi
__device__ unsigned g_hl [BT*KP_DM];   // A-fragment-major bf16x2 lo
__device__ unsigned g_hf [BT*KP_DM];   // A-fragment-major fp16x2 (unembed path)
__device__ unsigned g_qh [BT*KP_DM];   // row-major [token][kp]
__device__ unsigned g_ql [BT*KP_DM];
__device__ unsigned g_kh [BT*KP_DM];   // K fragment-major: [bh][keyT(256)][kpT(2)][64]
__device__ unsigned g_kl [BT*KP_DM];
__device__ unsigned g_vth[BT*KP_DM];   // V fragment-major: [bh][kpT(128)][vdT(4)][64]
__device__ unsigned g_vtl[BT*KP_DM];
__device__ float    g_ov [BT*DM];
__device__ unsigned g_yh [BT*KP_HID];  // A-fragment-major
__device__ unsigned g_yl [BT*KP_HID];
__device__ float    g_tmp[BT*DM];
__device__ unsigned g_wh [W_TOT];
__device__ unsigned g_wl [W_TOT];
__device__ float    g_wosum[NL*DKk*DM];
__device__ int      g_is64;

// -------------------- helpers -------------------------------------------------
__device__ __forceinline__ void pack_hilo(float x, float y, unsigned& hi, unsigned& lo) {
    unsigned h;
    asm("cvt.rn.bf16x2.f32 %0, %1, %2;" : "=r"(h) : "f"(y), "f"(x));
    float xr = x - __uint_as_float(h << 16);
    float yr = y - __uint_as_float(h & 0xffff0000u);
    asm("cvt.rn.bf16x2.f32 %0, %1, %2;" : "=r"(lo) : "f"(yr), "f"(xr));
    hi = h;
}

__device__ __forceinline__ unsigned pack_f16(float x, float y) {
    unsigned r;
    asm("cvt.rn.f16x2.f32 %0, %1, %2;" : "=r"(r) : "f"(y), "f"(x));
    return r;
}

__device__ __forceinline__ void mma16816(float* c, const unsigned* a, const unsigned* b) {
    asm volatile(
        "mma.sync.aligned.m16n8k16.row.col.f32.bf16.bf16.f32 "
        "{%0,%1,%2,%3}, {%4,%5,%6,%7}, {%8,%9}, {%0,%1,%2,%3};\n"
        : "+f"(c[0]), "+f"(c[1]), "+f"(c[2]), "+f"(c[3])
        : "r"(a[0]), "r"(a[1]), "r"(a[2]), "r"(a[3]), "r"(b[0]), "r"(b[1]));
}

__device__ __forceinline__ void mma16816h(float* c, const unsigned* a, const unsigned* b) {
    asm volatile(
        "mma.sync.aligned.m16n8k16.row.col.f32.f16.f16.f32 "
        "{%0,%1,%2,%3}, {%4,%5,%6,%7}, {%8,%9}, {%0,%1,%2,%3};\n"
        : "+f"(c[0]), "+f"(c[1]), "+f"(c[2]), "+f"(c[3])
        : "r"(a[0]), "r"(a[1]), "r"(a[2]), "r"(a[3]), "r"(b[0]), "r"(b[1]));
}

__device__ __forceinline__ void cp16(void* sdst, const void* gsrc) {
    unsigned sa = (unsigned)__cvta_generic_to_shared(sdst);
    asm volatile("cp.async.cg.shared.global [%0], [%1], 16;\n" :: "r"(sa), "l"(gsrc));
}
#define CP_COMMIT() asm volatile("cp.async.commit_group;\n" ::: "memory")
template <int N> __device__ __forceinline__ void cp_wait() {
    asm volatile("cp.async.wait_group %0;\n" :: "n"(N) : "memory");
}

__device__ __forceinline__ float warp_sum(float v) {
    #pragma unroll
    for (int o = 16; o; o >>= 1) v += __shfl_xor_sync(0xffffffffu, v, o);
    return v;
}

__device__ __forceinline__ float fast_exp(float x) {
    float t = x * 1.44269504f;
    float fi = rintf(t);
    float f = t - fi;
    int ei = __float2int_rn(fi);
    float p = 1.33336e-3f;
    p = fmaf(p, f, 9.61813e-3f);
    p = fmaf(p, f, 5.55041e-2f);
    p = fmaf(p, f, 2.40227e-1f);
    p = fmaf(p, f, 6.93147e-1f);
    p = fmaf(p, f, 1.0f);
    return __uint_as_float((unsigned)((ei + 127) << 23)) * p;
}

// A-fragment-major index: tile = 16m x 8kp (128 u32)
__device__ __forceinline__ size_t afrag_idx(int m, int kp, int kpt8) {
    int quad = (m & 7) * 4 + (kp & 3);
    int word = ((m >> 3) & 1) + (((kp >> 2) & 1) << 1);
    return ((size_t)(m >> 4) * kpt8 + (kp >> 3)) * 128 + quad * 4 + word;
}

// -------------------- index dtype probe ---------------------------------------
__global__ void detect_idx(const int* __restrict__ xi) {
    __shared__ int ok;
    if (threadIdx.x == 0) ok = 1;
    __syncthreads();
    if (xi[2 * threadIdx.x + 1] != 0) atomicAnd(&ok, 0);
    __syncthreads();
    if (threadIdx.x == 0) g_is64 = ok;
}

// -------------------- one-shot weight pre-conversion (B fragment-major) --------
__device__ __forceinline__ size_t frag_idx(int n, int kp, int kpt) {
    return ((size_t)(n >> 3) * kpt + (kp >> 3)) * 64
         + (size_t)((4 * (n & 7) + (kp & 3)) * 2 + ((kp >> 2) & 1));
}

__global__ __launch_bounds__(256) void convert_weights(
    const float* __restrict__ wq, const float* __restrict__ wk,
    const float* __restrict__ wv, const float* __restrict__ m0,
    const float* __restrict__ m1, const float* __restrict__ ue) {
    int i = blockIdx.x * 256 + threadIdx.x;
    if (i >= W_TOT) return;
    float a, b;
    size_t out;
    if (i < W_M0) {                       // QKV per-head [n/32][k][n%32] source
        int l3 = i >> 15;
        int r  = i & 32767;
        int kp = r >> 8;
        int n  = r & 255;
        int l = l3 / 3, mi = l3 % 3;
        const float* W = (mi == 0) ? wq : (mi == 1) ? wk : wv;
        size_t base = (size_t)l * HH * DM * DKk + (size_t)(n >> 5) * DM * DKk + (n & 31);
        a = W[base + (size_t)(2 * kp)     * DKk];
        b = W[base + (size_t)(2 * kp + 1) * DKk];
        out = (size_t)l3 * 32768 + frag_idx(n, kp, KP_DM / 8);
    } else if (i < W_M1) {                // mlp0 [k][1024]
        int r = i - W_M0;
        int l = r >> 17;
        int rr = r & 131071;
        int kp = rr >> 10;
        int n  = rr & 1023;
        const float* W = m0 + (size_t)l * DM * DHid;
        a = W[(size_t)(2 * kp)     * DHid + n];
        b = W[(size_t)(2 * kp + 1) * DHid + n];
        out = W_M0 + (size_t)l * 131072 + frag_idx(n, kp, KP_DM / 8);
    } else if (i < W_UE) {                // mlp1 [k][256]
        int r = i - W_M1;
        int l = r >> 17;
        int rr = r & 131071;
        int kp = rr >> 8;
        int n  = rr & 255;
        const float* W = m1 + (size_t)l * DHid * DM;
        a = W[(size_t)(2 * kp)     * DM + n];
        b = W[(size_t)(2 * kp + 1) * DM + n];
        out = W_M1 + (size_t)l * 131072 + frag_idx(n, kp, KP_HID / 8);
    } else {                              // unembedding [k][8192] -> fp16x2 single
        int r = i - W_UE;
        int kp = r >> 13;
        int n  = r & 8191;
        a = ue[(size_t)(2 * kp)     * ND + n];
        b = ue[(size_t)(2 * kp + 1) * ND + n];
        out = W_UE + frag_idx(n, kp, KP_DM / 8);
        g_wh[out] = pack_f16(a, b);
        return;
    }
    unsigned hi, lo;
    pack_hilo(a, b, hi, lo);
    g_wh[out] = hi;
    g_wl[out] = lo;
}

// -------------------- wo summed over heads --------------------------------------
__global__ void compute_wosum_all(const float* __restrict__ wo) {
    int i = blockIdx.x * 256 + threadIdx.x;
    if (i < NL * DKk * DM) {
        int l = i / (DKk * DM);
        int r = i % (DKk * DM);
        float s = 0.f;
        #pragma unroll
        for (int hh = 0; hh < HH; hh++)
            s += wo[(size_t)l * HH * DKk * DM + (size_t)hh * DKk * DM + r];
        g_wosum[i] = s;
    }
}

// -------------------- warp-per-token LN (A-fragment-major packed out) -----------
__device__ __forceinline__ void ln_store_warp(int token, int lane, float* val) {
    float s = 0.f;
    #pragma unroll
    for (int j = 0; j < 8; j++) s += val[j];
    s = warp_sum(s);
    float m = s * (1.f / DM);
    float vv = 0.f;
    #pragma unroll
    for (int j = 0; j < 8; j++) { val[j] -= m; vv += val[j] * val[j]; }
    vv = warp_sum(vv);
    float inv = rsqrtf(vv * (1.f / DM) + 1e-5f);
    #pragma unroll
    for (int j = 0; j < 8; j++) {
        float out = val[j] * inv;
        int d = j * 32 + lane;
        g_h[(size_t)token * DM + d] = out;
        float other = __shfl_xor_sync(0xffffffffu, out, 1);
        if (!(lane & 1)) {
            unsigned hi, lo;
            pack_hilo(out, other, hi, lo);
            int kp = j * 16 + (lane >> 1);
            size_t o = afrag_idx(token & 15, kp, KP_DM / 8)
                     + (size_t)(token >> 4) * (size_t)(16 * KP_DM);
            g_hh[o] = hi;
            g_hl[o] = lo;
            g_hf[o] = pack_f16(out, other);
        }
    }
}

__global__ __launch_bounds__(256) void embed_ln_w(const int* __restrict__ xi,
                                                  const float* __restrict__ emb,
                                                  const float* __restrict__ pos) {
    int token = blockIdx.x * 8 + (threadIdx.x >> 5);
    int lane = threadIdx.x & 31;
    int t = token % TT;
    int idx = g_is64 ? xi[2 * token] : xi[token];
    float val[8];
    #pragma unroll
    for (int j = 0; j < 8; j++) {
        int d = j * 32 + lane;
        val[j] = emb[(size_t)idx * DM + d] + pos[(size_t)t * DM + d];
    }
    ln_store_warp(token, lane, val);
}

__global__ __launch_bounds__(256) void attn_out_ln_w(const float* __restrict__ ov,
                                                     const float* __restrict__ wos) {
    int token = blockIdx.x * 8 + (threadIdx.x >> 5);
    int lane = threadIdx.x & 31;
    float vs = 0.f;
    float val[8];
    #pragma unroll
    for (int j = 0; j < 8; j++) {
        float o = ov[(size_t)token * DM + j * 32 + lane];
        vs += o;
        val[j] = g_h[(size_t)token * DM + j * 32 + lane];
    }
    #pragma unroll
    for (int v = 0; v < DKk; v++) {
        float sv = __shfl_sync(0xffffffffu, vs, v);
        #pragma unroll
        for (int j = 0; j < 8; j++) val[j] += sv * wos[v * DM + j * 32 + lane];
    }
    ln_store_warp(token, lane, val);
}

__global__ __launch_bounds__(256) void ln_residual_w(const float* __restrict__ add) {
    int token = blockIdx.x * 8 + (threadIdx.x >> 5);
    int lane = threadIdx.x & 31;
    float val[8];
    #pragma unroll
    for (int j = 0; j < 8; j++) {
        int d = j * 32 + lane;
        val[j] = g_h[(size_t)token * DM + d] + add[(size_t)token * DM + d];
    }
    ln_store_warp(token, lane, val);
}

// -------------------- packed GEMM: fragment-major A AND B (bf16 3-term) ----------
// EPI 0: fp32. 1: relu(acc+bias)->A-fragment-major packed. 2: acc+bias fp32.
// EPI 4: fused QKV; q->row-major Ch/Cl, k->K-fragment-major Ch2/Cl2,
//        v->V-fragment-major Vh/Vl.
template <int EPI, int BN>
__global__ __launch_bounds__(256, 2) void mgemm_db(
    const unsigned* __restrict__ Ah, const unsigned* __restrict__ Al,
    const unsigned* __restrict__ Bh, const unsigned* __restrict__ Bl,
    float* __restrict__ C, unsigned* __restrict__ Ch, unsigned* __restrict__ Cl,
    unsigned* __restrict__ Ch2, unsigned* __restrict__ Cl2,
    unsigned* __restrict__ Vh, unsigned* __restrict__ Vl,
    const float* __restrict__ bias, int M, int N, int KP) {
    constexpr int NT = BN / 16;
    constexpr int BS = 16 * BN;
    constexpr int AS = 2048;
    extern __shared__ unsigned smq[];
    unsigned* AsH = smq;
    unsigned* AsL = smq + 2 * AS;
    unsigned* BsH = smq + 4 * AS;
    unsigned* BsL = BsH + 2 * BS;

    const int bm = blockIdx.y * 128;
    int bn, mat = 0;
    if (EPI == 4) {
        mat = blockIdx.x >> 1;
        bn = (blockIdx.x & 1) * 128;
        Bh += (size_t)mat * DM * KP_DM;
        Bl += (size_t)mat * DM * KP_DM;
    } else {
        bn = blockIdx.x * BN;
    }
    const int tid  = threadIdx.x;
    const int lane = tid & 31;
    const int wid  = tid >> 5;
    const int g = lane >> 2;
    const int t = lane & 3;
    const int wm = (wid & 3) * 32;
    const int wn = (wid >> 2) * (BN / 2);
    const int kpt  = KP >> 3;

    float acc[2][NT][4];
    #pragma unroll
    for (int mt = 0; mt < 2; mt++)
        #pragma unroll
        for (int nt = 0; nt < NT; nt++)
            #pragma unroll
            for (int r = 0; r < 4; r++) acc[mt][nt][r] = 0.f;

    #define FILL_TILE(s, kp0)                                                       \
        do {                                                                         \
            _Pragma("unroll")                                                        \
            for (int it_ = 0; it_ < 2; it_++) {                                      \
                int i_ = it_ * 256 + tid;                                            \
                int tl_ = i_ >> 5;                                                   \
                size_t ga_ = ((size_t)((bm >> 4) + (tl_ >> 1)) * kpt                 \
                              + ((kp0) >> 3) + (tl_ & 1)) * 128 + (i_ & 31) * 4;     \
                cp16(&AsH[(s) * AS + i_ * 4], Ah + ga_);                             \
                cp16(&AsL[(s) * AS + i_ * 4], Al + ga_);                             \
            }                                                                        \
            _Pragma("unroll")                                                        \
            for (int it_ = 0; it_ < BN / 64; it_++) {                                \
                int f_ = it_ * 256 + tid;                                            \
                size_t gb_ = ((size_t)((bn >> 3) + (f_ >> 5)) * kpt                  \
                              + ((kp0) >> 3) + ((f_ >> 4) & 1)) * 64 + (f_ & 15) * 4;\
                cp16(&BsH[(s) * BS + f_ * 4], Bh + gb_);                             \
                cp16(&BsL[(s) * BS + f_ * 4], Bl + gb_);                             \
            }                                                                        \
        } while (0)

    const int NKT = KP / 16;
    FILL_TILE(0, 0);
    CP_COMMIT();

    for (int kt = 0; kt < NKT; kt++) {
        const int s = kt & 1;
        if (kt + 1 < NKT) {
            FILL_TILE(s ^ 1, (kt + 1) * 16);
            CP_COMMIT();
            cp_wait<1>();
        } else {
            cp_wait<0>();
        }
        __syncthreads();

        #pragma unroll
        for (int ks = 0; ks < 2; ks++) {
            unsigned ah[2][4], al[2][4];
            #pragma unroll
            for (int mt = 0; mt < 2; mt++) {
                int atile = (((wid & 3) * 2 + mt) * 2 + ks) * 128 + lane * 4;
                uint4 uh = *(const uint4*)&AsH[s * AS + atile];
                uint4 ul = *(const uint4*)&AsL[s * AS + atile];
                ah[mt][0] = uh.x; ah[mt][1] = uh.y; ah[mt][2] = uh.z; ah[mt][3] = uh.w;
                al[mt][0] = ul.x; al[mt][1] = ul.y; al[mt][2] = ul.z; al[mt][3] = ul.w;
            }
            const unsigned* bH = BsH + s * BS + ks * 64 + lane * 2;
            const unsigned* bL = BsL + s * BS + ks * 64 + lane * 2;
            #pragma unroll
            for (int nt = 0; nt < NT; nt++) {
                int nti = (wn >> 3) + nt;
                uint2 u2h = *(const uint2*)&bH[nti * 128];
                uint2 u2l = *(const uint2*)&bL[nti * 128];
                unsigned bh[2] = {u2h.x, u2h.y};
                unsigned bl[2] = {u2l.x, u2l.y};
                #pragma unroll
                for (int mt = 0; mt < 2; mt++) {
                    mma16816(acc[mt][nt], ah[mt], bh);
                    mma16816(acc[mt][nt], ah[mt], bl);
                    mma16816(acc[mt][nt], al[mt], bh);
                }
            }
        }
        __syncthreads();
    }
    #undef FILL_TILE

    const int opt = N >> 4;
    #pragma unroll
    for (int mt = 0; mt < 2; mt++) {
        #pragma unroll
        for (int nt = 0; nt < NT; nt++) {
            int row0 = bm + wm + mt * 16 + g;
            int col  = bn + wn + nt * 8 + 2 * t;
            float v0 = acc[mt][nt][0], v1 = acc[mt][nt][1];
            float v2 = acc[mt][nt][2], v3 = acc[mt][nt][3];
            if (EPI == 1) {
                float b0 = bias[col], b1 = bias[col + 1];
                v0 = fmaxf(v0 + b0, 0.f); v1 = fmaxf(v1 + b1, 0.f);
                v2 = fmaxf(v2 + b0, 0.f); v3 = fmaxf(v3 + b1, 0.f);
            }
            if (EPI == 2) {
                float b0 = bias[col], b1 = bias[col + 1];
                v0 += b0; v1 += b1; v2 += b0; v3 += b1;
            }
            if (EPI == 4 && mat == 2) {
                float p0 = __shfl_xor_sync(0xffffffffu, v0, 4);
                float p1 = __shfl_xor_sync(0xffffffffu, v1, 4);
                float p2 = __shfl_xor_sync(0xffffffffu, v2, 4);
                float p3 = __shfl_xor_sync(0xffffffffu, v3, 4);
                if (!(g & 1)) {
                    int bb = row0 >> 11;
                    int tt = row0 & (TT - 1);
                    int h  = col >> 5, vd = col & 31;
                    int kp = tt >> 1;
                    int q  = 4 * (vd & 7) + (kp & 3);
                    size_t base = (size_t)(bb * HH + h) * 32768
                                + (size_t)(kp >> 3) * 256 + (size_t)(vd >> 3) * 64
                                + (size_t)(2 * q);
                    unsigned w0, x0, w1, x1, w2, x2, w3, x3;
                    pack_hilo(v0, p0, w0, x0);
                    pack_hilo(v2, p2, w1, x1);
                    pack_hilo(v1, p1, w2, x2);
                    pack_hilo(v3, p3, w3, x3);
                    *(uint2*)&Vh[base]     = make_uint2(w0, w1);
                    *(uint2*)&Vl[base]     = make_uint2(x0, x1);
                    *(uint2*)&Vh[base + 8] = make_uint2(w2, w3);
                    *(uint2*)&Vl[base + 8] = make_uint2(x2, x3);
                }
            } else if (EPI == 0 || EPI == 2) {
                *(float2*)(C + (size_t)row0 * N + col)       = make_float2(v0, v1);
                *(float2*)(C + (size_t)(row0 + 8) * N + col) = make_float2(v2, v3);
            } else if (EPI == 1) {
                unsigned h0, l0, h1, l1;
                pack_hilo(v0, v1, h0, l0);
                pack_hilo(v2, v3, h1, l1);
                int cp = col >> 1;
                size_t tb = ((size_t)(row0 >> 4) * opt + (cp >> 3)) * 128
                          + (size_t)(((g & 7) * 4 + (cp & 3)) * 4 + (((cp >> 2) & 1) << 1));
                Ch[tb]     = h0;  Cl[tb]     = l0;
                Ch[tb + 1] = h1;  Cl[tb + 1] = l1;
            } else if (EPI == 4 && mat == 1) {
                unsigned h0, l0, h1, l1;
                pack_hilo(v0, v1, h0, l0);
                pack_hilo(v2, v3, h1, l1);
                int bb = row0 >> 11;
                int tt = row0 & (TT - 1);
                int h  = col >> 5;
                int kph = (col >> 1) & 15;
                size_t kb = (size_t)(bb * HH + h) * 32768
                          + ((size_t)(tt >> 3) * 2 + (kph >> 3)) * 64
                          + (size_t)((4 * (tt & 7) + (kph & 3)) * 2 + ((kph >> 2) & 1));
                Ch2[kb]       = h0;  Cl2[kb]       = l0;
                Ch2[kb + 128] = h1;  Cl2[kb + 128] = l1;
            } else {
                unsigned h0, l0, h1, l1;
                pack_hilo(v0, v1, h0, l0);
                pack_hilo(v2, v3, h1, l1);
                int NP = N >> 1, cp = col >> 1;
                Ch[(size_t)row0 * NP + cp]       = h0;
                Cl[(size_t)row0 * NP + cp]       = l0;
                Ch[(size_t)(row0 + 8) * NP + cp] = h1;
                Cl[(size_t)(row0 + 8) * NP + cp] = l1;
            }
        }
    }
}

// -------------------- fp16 single-pass GEMM (unembedding) ------------------------
// A fp16x2 A-fragment-major; B fp16x2 B-fragment-major; C = acc + bias (fp32).
__global__ __launch_bounds__(256, 2) void hgemm(
    const unsigned* __restrict__ Af, const unsigned* __restrict__ Bf,
    float* __restrict__ C, const float* __restrict__ bias, int M, int N, int KP) {
    constexpr int BN = 128;
    constexpr int NT = 8;
    constexpr int AS = 2048;
    constexpr int BS = 2048;
    extern __shared__ unsigned smh[];
    unsigned* Asf = smh;            // [2][AS]
    unsigned* Bsf = smh + 2 * AS;   // [2][BS]

    const int bm = blockIdx.y * 128;
    const int bn = blockIdx.x * BN;
    const int tid  = threadIdx.x;
    const int lane = tid & 31;
    const int wid  = tid >> 5;
    const int g = lane >> 2;
    const int t = lane & 3;
    const int wm = (wid & 3) * 32;
    const int wn = (wid >> 2) * (BN / 2);
    const int kpt = KP >> 3;

    float acc[2][NT][4];
    #pragma unroll
    for (int mt = 0; mt < 2; mt++)
        #pragma unroll
        for (int nt = 0; nt < NT; nt++)
            #pragma unroll
            for (int r = 0; r < 4; r++) acc[mt][nt][r] = 0.f;

    #define HFILL(s, kp0)                                                           \
        do {                                                                         \
            _Pragma("unroll")                                                        \
            for (int it_ = 0; it_ < 2; it_++) {                                      \
                int i_ = it_ * 256 + tid;                                            \
                int tl_ = i_ >> 5;                                                   \
                size_t ga_ = ((size_t)((bm >> 4) + (tl_ >> 1)) * kpt                 \
                              + ((kp0) >> 3) + (tl_ & 1)) * 128 + (i_ & 31) * 4;     \
                cp16(&Asf[(s) * AS + i_ * 4], Af + ga_);                             \
            }                                                                        \
            _Pragma("unroll")                                                        \
            for (int it_ = 0; it_ < 2; it_++) {                                      \
                int f_ = it_ * 256 + tid;                                            \
                size_t gb_ = ((size_t)((bn >> 3) + (f_ >> 5)) * kpt                  \
                              + ((kp0) >> 3) + ((f_ >> 4) & 1)) * 64 + (f_ & 15) * 4;\
                cp16(&Bsf[(s) * BS + f_ * 4], Bf + gb_);                             \
            }                                                                        \
        } while (0)

    const int NKT = KP / 16;
    HFILL(0, 0);
    CP_COMMIT();

    for (int kt = 0; kt < NKT; kt++) {
        const int s = kt & 1;
        if (kt + 1 < NKT) {
            HFILL(s ^ 1, (kt + 1) * 16);
            CP_COMMIT();
            cp_wait<1>();
        } else {
            cp_wait<0>();
        }
        __syncthreads();

        #pragma unroll
        for (int ks = 0; ks < 2; ks++) {
            unsigned af[2][4];
            #pragma unroll
            for (int mt = 0; mt < 2; mt++) {
                int atile = (((wid & 3) * 2 + mt) * 2 + ks) * 128 + lane * 4;
                uint4 u = *(const uint4*)&Asf[s * AS + atile];
                af[mt][0] = u.x; af[mt][1] = u.y; af[mt][2] = u.z; af[mt][3] = u.w;
            }
            const unsigned* bF = Bsf + s * BS + ks * 64 + lane * 2;
            #pragma unroll
            for (int nt = 0; nt < NT; nt++) {
                int nti = (wn >> 3) + nt;
                uint2 u2 = *(const uint2*)&bF[nti * 128];
                unsigned bf2[2] = {u2.x, u2.y};
                #pragma unroll
                for (int mt = 0; mt < 2; mt++)
                    mma16816h(acc[mt][nt], af[mt], bf2);
            }
        }
        __syncthreads();
    }
    #undef HFILL

    #pragma unroll
    for (int mt = 0; mt < 2; mt++) {
        #pragma unroll
        for (int nt = 0; nt < NT; nt++) {
            int row0 = bm + wm + mt * 16 + g;
            int col  = bn + wn + nt * 8 + 2 * t;
            float b0 = bias[col], b1 = bias[col + 1];
            *(float2*)(C + (size_t)row0 * N + col) =
                make_float2(acc[mt][nt][0] + b0, acc[mt][nt][1] + b1);
            *(float2*)(C + (size_t)(row0 + 8) * N + col) =
                make_float2(acc[mt][nt][2] + b0, acc[mt][nt][3] + b1);
        }
    }
}

// -------------------- tensor-core causal attention (fragment-major K/V) ---------
__global__ __launch_bounds__(256, 2) void attention_mma2(
    const unsigned* __restrict__ qh, const unsigned* __restrict__ ql,
    const unsigned* __restrict__ kh, const unsigned* __restrict__ kl,
    const unsigned* __restrict__ vth, const unsigned* __restrict__ vtl,
    float* __restrict__ ov) {
    __shared__ unsigned Ks_hi[2][1024];
    __shared__ unsigned Ks_lo[2][1024];
    __shared__ unsigned Vs_hi[2][1024];
    __shared__ unsigned Vs_lo[2][1024];

    const int bh = blockIdx.y;
    const int b  = bh >> 3, h = bh & 7;
    const int t0 = (gridDim.x - 1 - blockIdx.x) * 128;
    const int tid  = threadIdx.x;
    const int lane = tid & 31;
    const int wid  = tid >> 5;
    const int g = lane >> 2;
    const int t = lane & 3;
    const int wm = wid * 16;

    unsigned qfh[2][4], qfl[2][4];
    {
        size_t base = (size_t)(b * TT + t0 + wm) * KP_DM + h * 16;
        #pragma unroll
        for (int ks = 0; ks < 2; ks++) {
            qfh[ks][0] = qh[base + (size_t)g * KP_DM + ks * 8 + t];
            qfh[ks][1] = qh[base + (size_t)(g + 8) * KP_DM + ks * 8 + t];
            qfh[ks][2] = qh[base + (size_t)g * KP_DM + ks * 8 + t + 4];
            qfh[ks][3] = qh[base + (size_t)(g + 8) * KP_DM + ks * 8 + t + 4];
            qfl[ks][0] = ql[base + (size_t)g * KP_DM + ks * 8 + t];
            qfl[ks][1] = ql[base + (size_t)(g + 8) * KP_DM + ks * 8 + t];
            qfl[ks][2] = ql[base + (size_t)g * KP_DM + ks * 8 + t + 4];
            qfl[ks][3] = ql[base + (size_t)(g + 8) * KP_DM + ks * 8 + t + 4];
        }
    }

    float o[4][4];
    #pragma unroll
    for (int nf = 0; nf < 4; nf++)
        #pragma unroll
        for (int r = 0; r < 4; r++) o[nf][r] = 0.f;
    float rs0 = 0.f, rs1 = 0.f;

    const int row0 = t0 + wm + g;
    const int row1 = row0 + 8;
    const int nit = t0 / 64 + 2;

    #define ISSUE_TILE(s, o0)                                                        \
        do {                                                                          \
            size_t gi = (size_t)bh * 32768 + (size_t)(o0) * 16 + tid * 4;             \
            cp16(&Ks_hi[s][tid * 4], kh + gi);                                        \
            cp16(&Ks_lo[s][tid * 4], kl + gi);                                        \
            cp16(&Vs_hi[s][tid * 4], vth + gi);                                       \
            cp16(&Vs_lo[s][tid * 4], vtl + gi);                                       \
        } while (0)

    ISSUE_TILE(0, 0);
    CP_COMMIT();

    for (int it = 0; it < nit; it++) {
        const int o0 = it * 64;
        const int s = it & 1;
        if (it + 1 < nit) {
            ISSUE_TILE(s ^ 1, o0 + 64);
            CP_COMMIT();
            cp_wait<1>();
        } else {
            cp_wait<0>();
        }
        __syncthreads();

        if (o0 <= t0 + wm + 15) {
            float c[8][4];
            #pragma unroll
            for (int j = 0; j < 8; j++)
                #pragma unroll
                for (int r = 0; r < 4; r++) c[j][r] = 0.f;
            #pragma unroll
            for (int j = 0; j < 8; j++) {
                #pragma unroll
                for (int ks = 0; ks < 2; ks++) {
                    uint2 uh = *(const uint2*)&Ks_hi[s][(j * 2 + ks) * 64 + lane * 2];
                    uint2 ul = *(const uint2*)&Ks_lo[s][(j * 2 + ks) * 64 + lane * 2];
                    unsigned bhf[2] = {uh.x, uh.y};
                    unsigned blf[2] = {ul.x, ul.y};
                    mma16816(c[j], qfh[ks], bhf);
                    mma16816(c[j], qfh[ks], blf);
                    mma16816(c[j], qfl[ks], bhf);
                }
            }
            if (o0 + 63 <= t0 + wm) {
                #pragma unroll
                for (int j = 0; j < 8; j++) {
                    if (j < 2) {
                        c[j][0] = fast_exp(fmaxf(fminf(c[j][0], 50.f), -80.f));
                        c[j][1] = fast_exp(fmaxf(fminf(c[j][1], 50.f), -80.f));
                        c[j][2] = fast_exp(fmaxf(fminf(c[j][2], 50.f), -80.f));
                        c[j][3] = fast_exp(fmaxf(fminf(c[j][3], 50.f), -80.f));
                    } else {
                        c[j][0] = __expf(fminf(c[j][0], 50.f));
                        c[j][1] = __expf(fminf(c[j][1], 50.f));
                        c[j][2] = __expf(fminf(c[j][2], 50.f));
                        c[j][3] = __expf(fminf(c[j][3], 50.f));
                    }
                    rs0 += c[j][0] + c[j][1];
                    rs1 += c[j][2] + c[j][3];
                }
            } else {
                #pragma unroll
                for (int j = 0; j < 8; j++) {
                    int cb = o0 + j * 8 + 2 * t;
                    float e0, e1, e2, e3;
                    if (j < 2) {
                        e0 = fast_exp(fmaxf(fminf(c[j][0], 50.f), -80.f));
                        e1 = fast_exp(fmaxf(fminf(c[j][1], 50.f), -80.f));
                        e2 = fast_exp(fmaxf(fminf(c[j][2], 50.f), -80.f));
                        e3 = fast_exp(fmaxf(fminf(c[j][3], 50.f), -80.f));
                    } else {
                        e0 = __expf(fminf(c[j][0], 50.f));
                        e1 = __expf(fminf(c[j][1], 50.f));
                        e2 = __expf(fminf(c[j][2], 50.f));
                        e3 = __expf(fminf(c[j][3], 50.f));
                    }
                    c[j][0] = (cb     <= row0) ? e0 : 0.f;
                    c[j][1] = (cb + 1 <= row0) ? e1 : 0.f;
                    c[j][2] = (cb     <= row1) ? e2 : 0.f;
                    c[j][3] = (cb + 1 <= row1) ? e3 : 0.f;
                    rs0 += c[j][0] + c[j][1];
                    rs1 += c[j][2] + c[j][3];
                }
            }
            #pragma unroll
            for (int klq = 0; klq < 4; klq++) {
                unsigned ph[4], pl[4];
                pack_hilo(c[2 * klq][0],     c[2 * klq][1],     ph[0], pl[0]);
                pack_hilo(c[2 * klq][2],     c[2 * klq][3],     ph[1], pl[1]);
                pack_hilo(c[2 * klq + 1][0], c[2 * klq + 1][1], ph[2], pl[2]);
                pack_hilo(c[2 * klq + 1][2], c[2 * klq + 1][3], ph[3], pl[3]);
                #pragma unroll
                for (int nf = 0; nf < 4; nf++) {
                    uint2 vh2 = *(const uint2*)&Vs_hi[s][(klq * 4 + nf) * 64 + lane * 2];
                    uint2 vl2 = *(const uint2*)&Vs_lo[s][(klq * 4 + nf) * 64 + lane * 2];
                    unsigned vhf[2] = {vh2.x, vh2.y};
                    unsigned vlf[2] = {vl2.x, vl2.y};
                    mma16816(o[nf], ph, vhf);
                    mma16816(o[nf], ph, vlf);
                    mma16816(o[nf], pl, vhf);
                }
            }
        }
        __syncthreads();
    }
    #undef ISSUE_TILE

    rs0 += __shfl_xor_sync(0xffffffffu, rs0, 1);
    rs0 += __shfl_xor_sync(0xffffffffu, rs0, 2);
    rs1 += __shfl_xor_sync(0xffffffffu, rs1, 1);
    rs1 += __shfl_xor_sync(0xffffffffu, rs1, 2);
    float i0 = 1.f / (rs0 + 1e-10f);
    float i1 = 1.f / (rs1 + 1e-10f);
    size_t r0 = (size_t)(b * TT + row0);
    #pragma unroll
    for (int nf = 0; nf < 4; nf++) {
        int vd = h * DKk + nf * 8 + 2 * t;
        *(float2*)(ov + r0 * DM + vd)       = make_float2(o[nf][0] * i0, o[nf][1] * i0);
        *(float2*)(ov + (r0 + 8) * DM + vd) = make_float2(o[nf][2] * i1, o[nf][3] * i1);
    }
}

// -------------------- launch --------------------------------------------------
extern "C" void kernel_launch(void* const* d_in, const int* in_sizes, int n_in,
                              void* d_out, int out_size) {
    const int*   x     = (const int*)  d_in[0];
    const float* emb   = (const float*)d_in[1];
    const float* pos   = (const float*)d_in[2];
    const float* wq    = (const float*)d_in[3];
    const float* wk    = (const float*)d_in[4];
    const float* wv    = (const float*)d_in[5];
    const float* wo    = (const float*)d_in[6];
    const float* mlp0  = (const float*)d_in[7];
    const float* mlpb  = (const float*)d_in[8];
    const float* mlp1  = (const float*)d_in[9];
    const float* unemb = (const float*)d_in[10];
    const float* bias  = (const float*)d_in[11];
    float* out = (float*)d_out;

    unsigned *hh_, *hl_, *hf_, *qh_, *ql_, *kh_, *kl_, *yh_, *yl_, *wh_, *wl_, *vth_, *vtl_;
    float *ov_, *tmp_, *wos_;
    cudaGetSymbolAddress((void**)&hh_, g_hh);
    cudaGetSymbolAddress((void**)&hl_, g_hl);
    cudaGetSymbolAddress((void**)&hf_, g_hf);
    cudaGetSymbolAddress((void**)&qh_, g_qh);
    cudaGetSymbolAddress((void**)&ql_, g_ql);
    cudaGetSymbolAddress((void**)&kh_, g_kh);
    cudaGetSymbolAddress((void**)&kl_, g_kl);
    cudaGetSymbolAddress((void**)&yh_, g_yh);
    cudaGetSymbolAddress((void**)&yl_, g_yl);
    cudaGetSymbolAddress((void**)&wh_, g_wh);
    cudaGetSymbolAddress((void**)&wl_, g_wl);
    cudaGetSymbolAddress((void**)&vth_, g_vth);
    cudaGetSymbolAddress((void**)&vtl_, g_vtl);
    cudaGetSymbolAddress((void**)&ov_,  g_ov);
    cudaGetSymbolAddress((void**)&tmp_, g_tmp);
    cudaGetSymbolAddress((void**)&wos_, g_wosum);

    const int SM128 = (8192 + 4 * 16 * 128) * 4;   // 65536 B
    const int SM64  = (8192 + 4 * 16 * 64)  * 4;   // 49152 B
    const int SMH   = (2 * 2048 + 2 * 2048) * 4;   // 32768 B
    cudaFuncSetAttribute(mgemm_db<4, 128>, cudaFuncAttributeMaxDynamicSharedMemorySize, SM128);
    cudaFuncSetAttribute(mgemm_db<1, 128>, cudaFuncAttributeMaxDynamicSharedMemorySize, SM128);
    cudaFuncSetAttribute(mgemm_db<0, 64>,  cudaFuncAttributeMaxDynamicSharedMemorySize, SM64);
    cudaFuncSetAttribute(hgemm,            cudaFuncAttributeMaxDynamicSharedMemorySize, SMH);

    detect_idx<<<1, 64>>>(x);
    convert_weights<<<(W_TOT + 255) / 256, 256>>>(wq, wk, wv, mlp0, mlp1, unemb);
    compute_wosum_all<<<(NL * DKk * DM + 255) / 256, 256>>>(wo);
    embed_ln_w<<<BT / 8, 256>>>(x, emb, pos);

    for (int l = 0; l < NL; l++) {
        const unsigned* wqkv_h = wh_ + (size_t)(l * 3) * DM * KP_DM;
        const unsigned* wqkv_l = wl_ + (size_t)(l * 3) * DM * KP_DM;
        const unsigned* m0h = wh_ + W_M0 + (size_t)l * DHid * KP_DM;
        const unsigned* m0l = wl_ + W_M0 + (size_t)l * DHid * KP_DM;
        const unsigned* m1h = wh_ + W_M1 + (size_t)l * DM * KP_HID;
        const unsigned* m1l = wl_ + W_M1 + (size_t)l * DM * KP_HID;

        mgemm_db<4, 128><<<dim3(6, BT / 128), 256, SM128>>>(
            hh_, hl_, wqkv_h, wqkv_l, nullptr, qh_, ql_, kh_, kl_, vth_, vtl_,
            nullptr, BT, DM, KP_DM);

        attention_mma2<<<dim3(TT / 128, BB * HH), 256>>>(qh_, ql_, kh_, kl_, vth_, vtl_, ov_);
        attn_out_ln_w<<<BT / 8, 256>>>(ov_, wos_ + (size_t)l * DKk * DM);

        mgemm_db<1, 128><<<dim3(DHid / 128, BT / 128), 256, SM128>>>(
            hh_, hl_, m0h, m0l, nullptr, yh_, yl_, nullptr, nullptr, nullptr, nullptr,
            mlpb + (size_t)l * DHid, BT, DHid, KP_DM);
        mgemm_db<0, 64><<<dim3(DM / 64, BT / 128), 256, SM64>>>(
            yh_, yl_, m1h, m1l, tmp_, nullptr, nullptr, nullptr, nullptr, nullptr, nullptr,
            nullptr, BT, DM, KP_HID);
        ln_residual_w<<<BT / 8, 256>>>(tmp_);
    }

    hgemm<<<dim3(ND / 128, BT / 128), 256, SMH>>>(
        hf_, wh_ + W_UE, out, bias, BT, ND, KP_DM);
}

// round 16
// speedup vs baseline: 1.5840x; 1.1925x over previous
#include <cuda_runtime.h>
#include <cuda_bf16.h>
#include <math.h>

#define BB 4
#define TT 2048
#define BT (BB*TT)
#define DM 256
#define HH 8
#define DKk 32
#define DHid 1024
#define ND 8192
#define NL 4

#define KP_DM (DM/2)      // 128 pairs
#define KP_HID (DHid/2)   // 512 pairs

// packed-weight regions (u32). QKV: bf16x2 hi/lo B-fragment-major.
// M0/M1/UE: fp16x2 single-pass B-fragment-major (g_wh only).
#define W_M0 (NL*3*DM*KP_DM)
#define W_M1 (W_M0 + NL*DHid*KP_DM)
#define W_UE (W_M1 + NL*DM*KP_HID)
#define W_TOT (W_UE + ND*KP_DM)

// -------------------- scratch (device globals) ---------------------------------
__device__ float    g_h  [BT*DM];
__device__ unsigned g_hh [BT*KP_DM];   // A-fragment-major bf16x2 hi
__device__ unsigned g_hl [BT*KP_DM];   // A-fragment-major bf16x2 lo
__device__ unsigned g_hf [BT*KP_DM];   // A-fragment-major fp16x2
__device__ unsigned g_qh [BT*KP_DM];   // row-major [token][kp]
__device__ unsigned g_ql [BT*KP_DM];
__device__ unsigned g_kh [BT*KP_DM];   // K fragment-major: [bh][keyT(256)][kpT(2)][64]
__device__ unsigned g_kl [BT*KP_DM];
__device__ unsigned g_vth[BT*KP_DM];   // V fragment-major: [bh][kpT(128)][vdT(4)][64]
__device__ unsigned g_vtl[BT*KP_DM];
__device__ float    g_ov [BT*DM];
__device__ unsigned g_yf [BT*KP_HID];  // MLP hidden, fp16x2 A-fragment-major
__device__ float    g_tmp[BT*DM];
__device__ unsigned g_wh [W_TOT];
__device__ unsigned g_wl [W_TOT];
__device__ float    g_wosum[NL*DKk*DM];
__device__ int      g_is64;

// -------------------- helpers -------------------------------------------------
__device__ __forceinline__ void pack_hilo(float x, float y, unsigned& hi, unsigned& lo) {
    unsigned h;
    asm("cvt.rn.bf16x2.f32 %0, %1, %2;" : "=r"(h) : "f"(y), "f"(x));
    float xr = x - __uint_as_float(h << 16);
    float yr = y - __uint_as_float(h & 0xffff0000u);
    asm("cvt.rn.bf16x2.f32 %0, %1, %2;" : "=r"(lo) : "f"(yr), "f"(xr));
    hi = h;
}

__device__ __forceinline__ unsigned pack_f16(float x, float y) {
    unsigned r;
    asm("cvt.rn.f16x2.f32 %0, %1, %2;" : "=r"(r) : "f"(y), "f"(x));
    return r;
}

__device__ __forceinline__ void mma16816(float* c, const unsigned* a, const unsigned* b) {
    asm volatile(
        "mma.sync.aligned.m16n8k16.row.col.f32.bf16.bf16.f32 "
        "{%0,%1,%2,%3}, {%4,%5,%6,%7}, {%8,%9}, {%0,%1,%2,%3};\n"
        : "+f"(c[0]), "+f"(c[1]), "+f"(c[2]), "+f"(c[3])
        : "r"(a[0]), "r"(a[1]), "r"(a[2]), "r"(a[3]), "r"(b[0]), "r"(b[1]));
}

__device__ __forceinline__ void mma16816h(float* c, const unsigned* a, const unsigned* b) {
    asm volatile(
        "mma.sync.aligned.m16n8k16.row.col.f32.f16.f16.f32 "
        "{%0,%1,%2,%3}, {%4,%5,%6,%7}, {%8,%9}, {%0,%1,%2,%3};\n"
        : "+f"(c[0]), "+f"(c[1]), "+f"(c[2]), "+f"(c[3])
        : "r"(a[0]), "r"(a[1]), "r"(a[2]), "r"(a[3]), "r"(b[0]), "r"(b[1]));
}

__device__ __forceinline__ void cp16(void* sdst, const void* gsrc) {
    unsigned sa = (unsigned)__cvta_generic_to_shared(sdst);
    asm volatile("cp.async.cg.shared.global [%0], [%1], 16;\n" :: "r"(sa), "l"(gsrc));
}
#define CP_COMMIT() asm volatile("cp.async.commit_group;\n" ::: "memory")
template <int N> __device__ __forceinline__ void cp_wait() {
    asm volatile("cp.async.wait_group %0;\n" :: "n"(N) : "memory");
}

__device__ __forceinline__ float warp_sum(float v) {
    #pragma unroll
    for (int o = 16; o; o >>= 1) v += __shfl_xor_sync(0xffffffffu, v, o);
    return v;
}

__device__ __forceinline__ float fast_exp(float x) {
    float t = x * 1.44269504f;
    float fi = rintf(t);
    float f = t - fi;
    int ei = __float2int_rn(fi);
    float p = 1.33336e-3f;
    p = fmaf(p, f, 9.61813e-3f);
    p = fmaf(p, f, 5.55041e-2f);
    p = fmaf(p, f, 2.40227e-1f);
    p = fmaf(p, f, 6.93147e-1f);
    p = fmaf(p, f, 1.0f);
    return __uint_as_float((unsigned)((ei + 127) << 23)) * p;
}

// A-fragment-major index: tile = 16m x 8kp (128 u32)
__device__ __forceinline__ size_t afrag_idx(int m, int kp, int kpt8) {
    int quad = (m & 7) * 4 + (kp & 3);
    int word = ((m >> 3) & 1) + (((kp >> 2) & 1) << 1);
    return ((size_t)(m >> 4) * kpt8 + (kp >> 3)) * 128 + quad * 4 + word;
}

// -------------------- index dtype probe ---------------------------------------
__global__ void detect_idx(const int* __restrict__ xi) {
    __shared__ int ok;
    if (threadIdx.x == 0) ok = 1;
    __syncthreads();
    if (xi[2 * threadIdx.x + 1] != 0) atomicAnd(&ok, 0);
    __syncthreads();
    if (threadIdx.x == 0) g_is64 = ok;
}

// -------------------- one-shot weight pre-conversion (B fragment-major) --------
__device__ __forceinline__ size_t frag_idx(int n, int kp, int kpt) {
    return ((size_t)(n >> 3) * kpt + (kp >> 3)) * 64
         + (size_t)((4 * (n & 7) + (kp & 3)) * 2 + ((kp >> 2) & 1));
}

__global__ __launch_bounds__(256) void convert_weights(
    const float* __restrict__ wq, const float* __restrict__ wk,
    const float* __restrict__ wv, const float* __restrict__ m0,
    const float* __restrict__ m1, const float* __restrict__ ue) {
    int i = blockIdx.x * 256 + threadIdx.x;
    if (i >= W_TOT) return;
    float a, b;
    size_t out;
    if (i < W_M0) {                       // QKV per-head [n/32][k][n%32]: bf16 hi/lo
        int l3 = i >> 15;
        int r  = i & 32767;
        int kp = r >> 8;
        int n  = r & 255;
        int l = l3 / 3, mi = l3 % 3;
        const float* W = (mi == 0) ? wq : (mi == 1) ? wk : wv;
        size_t base = (size_t)l * HH * DM * DKk + (size_t)(n >> 5) * DM * DKk + (n & 31);
        a = W[base + (size_t)(2 * kp)     * DKk];
        b = W[base + (size_t)(2 * kp + 1) * DKk];
        out = (size_t)l3 * 32768 + frag_idx(n, kp, KP_DM / 8);
        unsigned hi, lo;
        pack_hilo(a, b, hi, lo);
        g_wh[out] = hi;
        g_wl[out] = lo;
        return;
    } else if (i < W_M1) {                // mlp0 [k][1024] -> fp16 single
        int r = i - W_M0;
        int l = r >> 17;
        int rr = r & 131071;
        int kp = rr >> 10;
        int n  = rr & 1023;
        const float* W = m0 + (size_t)l * DM * DHid;
        a = W[(size_t)(2 * kp)     * DHid + n];
        b = W[(size_t)(2 * kp + 1) * DHid + n];
        out = W_M0 + (size_t)l * 131072 + frag_idx(n, kp, KP_DM / 8);
    } else if (i < W_UE) {                // mlp1 [k][256] -> fp16 single
        int r = i - W_M1;
        int l = r >> 17;
        int rr = r & 131071;
        int kp = rr >> 8;
        int n  = rr & 255;
        const float* W = m1 + (size_t)l * DHid * DM;
        a = W[(size_t)(2 * kp)     * DM + n];
        b = W[(size_t)(2 * kp + 1) * DM + n];
        out = W_M1 + (size_t)l * 131072 + frag_idx(n, kp, KP_HID / 8);
    } else {                              // unembedding [k][8192] -> fp16 single
        int r = i - W_UE;
        int kp = r >> 13;
        int n  = r & 8191;
        a = ue[(size_t)(2 * kp)     * ND + n];
        b = ue[(size_t)(2 * kp + 1) * ND + n];
        out = W_UE + frag_idx(n, kp, KP_DM / 8);
    }
    g_wh[out] = pack_f16(a, b);
}

// -------------------- wo summed over heads --------------------------------------
__global__ void compute_wosum_all(const float* __restrict__ wo) {
    int i = blockIdx.x * 256 + threadIdx.x;
    if (i < NL * DKk * DM) {
        int l = i / (DKk * DM);
        int r = i % (DKk * DM);
        float s = 0.f;
        #pragma unroll
        for (int hh = 0; hh < HH; hh++)
            s += wo[(size_t)l * HH * DKk * DM + (size_t)hh * DKk * DM + r];
        g_wosum[i] = s;
    }
}

// -------------------- warp-per-token LN (A-fragment-major packed out) -----------
__device__ __forceinline__ void ln_store_warp(int token, int lane, float* val) {
    float s = 0.f;
    #pragma unroll
    for (int j = 0; j < 8; j++) s += val[j];
    s = warp_sum(s);
    float m = s * (1.f / DM);
    float vv = 0.f;
    #pragma unroll
    for (int j = 0; j < 8; j++) { val[j] -= m; vv += val[j] * val[j]; }
    vv = warp_sum(vv);
    float inv = rsqrtf(vv * (1.f / DM) + 1e-5f);
    #pragma unroll
    for (int j = 0; j < 8; j++) {
        float out = val[j] * inv;
        int d = j * 32 + lane;
        g_h[(size_t)token * DM + d] = out;
        float other = __shfl_xor_sync(0xffffffffu, out, 1);
        if (!(lane & 1)) {
            unsigned hi, lo;
            pack_hilo(out, other, hi, lo);
            int kp = j * 16 + (lane >> 1);
            size_t o = afrag_idx(token & 15, kp, KP_DM / 8)
                     + (size_t)(token >> 4) * (size_t)(16 * KP_DM);
            g_hh[o] = hi;
            g_hl[o] = lo;
            g_hf[o] = pack_f16(out, other);
        }
    }
}

__global__ __launch_bounds__(256) void embed_ln_w(const int* __restrict__ xi,
                                                  const float* __restrict__ emb,
                                                  const float* __restrict__ pos) {
    int token = blockIdx.x * 8 + (threadIdx.x >> 5);
    int lane = threadIdx.x & 31;
    int t = token % TT;
    int idx = g_is64 ? xi[2 * token] : xi[token];
    float val[8];
    #pragma unroll
    for (int j = 0; j < 8; j++) {
        int d = j * 32 + lane;
        val[j] = emb[(size_t)idx * DM + d] + pos[(size_t)t * DM + d];
    }
    ln_store_warp(token, lane, val);
}

__global__ __launch_bounds__(256) void attn_out_ln_w(const float* __restrict__ ov,
                                                     const float* __restrict__ wos) {
    int token = blockIdx.x * 8 + (threadIdx.x >> 5);
    int lane = threadIdx.x & 31;
    float vs = 0.f;
    float val[8];
    #pragma unroll
    for (int j = 0; j < 8; j++) {
        float o = ov[(size_t)token * DM + j * 32 + lane];
        vs += o;
        val[j] = g_h[(size_t)token * DM + j * 32 + lane];
    }
    #pragma unroll
    for (int v = 0; v < DKk; v++) {
        float sv = __shfl_sync(0xffffffffu, vs, v);
        #pragma unroll
        for (int j = 0; j < 8; j++) val[j] += sv * wos[v * DM + j * 32 + lane];
    }
    ln_store_warp(token, lane, val);
}

__global__ __launch_bounds__(256) void ln_residual_w(const float* __restrict__ add) {
    int token = blockIdx.x * 8 + (threadIdx.x >> 5);
    int lane = threadIdx.x & 31;
    float val[8];
    #pragma unroll
    for (int j = 0; j < 8; j++) {
        int d = j * 32 + lane;
        val[j] = g_h[(size_t)token * DM + d] + add[(size_t)token * DM + d];
    }
    ln_store_warp(token, lane, val);
}

// -------------------- QKV GEMM: bf16 3-term, fragment-major A AND B --------------
// q->row-major Ch/Cl, k->K-fragment-major Ch2/Cl2, v->V-fragment-major Vh/Vl.
template <int BN>
__global__ __launch_bounds__(256, 2) void mgemm_db(
    const unsigned* __restrict__ Ah, const unsigned* __restrict__ Al,
    const unsigned* __restrict__ Bh, const unsigned* __restrict__ Bl,
    unsigned* __restrict__ Ch, unsigned* __restrict__ Cl,
    unsigned* __restrict__ Ch2, unsigned* __restrict__ Cl2,
    unsigned* __restrict__ Vh, unsigned* __restrict__ Vl,
    int M, int N, int KP) {
    constexpr int NT = BN / 16;
    constexpr int BS = 16 * BN;
    constexpr int AS = 2048;
    extern __shared__ unsigned smq[];
    unsigned* AsH = smq;
    unsigned* AsL = smq + 2 * AS;
    unsigned* BsH = smq + 4 * AS;
    unsigned* BsL = BsH + 2 * BS;

    const int bm = blockIdx.y * 128;
    const int mat = blockIdx.x >> 1;
    const int bn = (blockIdx.x & 1) * 128;
    Bh += (size_t)mat * DM * KP_DM;
    Bl += (size_t)mat * DM * KP_DM;
    const int tid  = threadIdx.x;
    const int lane = tid & 31;
    const int wid  = tid >> 5;
    const int g = lane >> 2;
    const int t = lane & 3;
    const int wm = (wid & 3) * 32;
    const int wn = (wid >> 2) * (BN / 2);
    const int kpt  = KP >> 3;

    float acc[2][NT][4];
    #pragma unroll
    for (int mt = 0; mt < 2; mt++)
        #pragma unroll
        for (int nt = 0; nt < NT; nt++)
            #pragma unroll
            for (int r = 0; r < 4; r++) acc[mt][nt][r] = 0.f;

    #define FILL_TILE(s, kp0)                                                       \
        do {                                                                         \
            _Pragma("unroll")                                                        \
            for (int it_ = 0; it_ < 2; it_++) {                                      \
                int i_ = it_ * 256 + tid;                                            \
                int tl_ = i_ >> 5;                                                   \
                size_t ga_ = ((size_t)((bm >> 4) + (tl_ >> 1)) * kpt                 \
                              + ((kp0) >> 3) + (tl_ & 1)) * 128 + (i_ & 31) * 4;     \
                cp16(&AsH[(s) * AS + i_ * 4], Ah + ga_);                             \
                cp16(&AsL[(s) * AS + i_ * 4], Al + ga_);                             \
            }                                                                        \
            _Pragma("unroll")                                                        \
            for (int it_ = 0; it_ < BN / 64; it_++) {                                \
                int f_ = it_ * 256 + tid;                                            \
                size_t gb_ = ((size_t)((bn >> 3) + (f_ >> 5)) * kpt                  \
                              + ((kp0) >> 3) + ((f_ >> 4) & 1)) * 64 + (f_ & 15) * 4;\
                cp16(&BsH[(s) * BS + f_ * 4], Bh + gb_);                             \
                cp16(&BsL[(s) * BS + f_ * 4], Bl + gb_);                             \
            }                                                                        \
        } while (0)

    const int NKT = KP / 16;
    FILL_TILE(0, 0);
    CP_COMMIT();

    for (int kt = 0; kt < NKT; kt++) {
        const int s = kt & 1;
        if (kt + 1 < NKT) {
            FILL_TILE(s ^ 1, (kt + 1) * 16);
            CP_COMMIT();
            cp_wait<1>();
        } else {
            cp_wait<0>();
        }
        __syncthreads();

        #pragma unroll
        for (int ks = 0; ks < 2; ks++) {
            unsigned ah[2][4], al[2][4];
            #pragma unroll
            for (int mt = 0; mt < 2; mt++) {
                int atile = (((wid & 3) * 2 + mt) * 2 + ks) * 128 + lane * 4;
                uint4 uh = *(const uint4*)&AsH[s * AS + atile];
                uint4 ul = *(const uint4*)&AsL[s * AS + atile];
                ah[mt][0] = uh.x; ah[mt][1] = uh.y; ah[mt][2] = uh.z; ah[mt][3] = uh.w;
                al[mt][0] = ul.x; al[mt][1] = ul.y; al[mt][2] = ul.z; al[mt][3] = ul.w;
            }
            const unsigned* bH = BsH + s * BS + ks * 64 + lane * 2;
            const unsigned* bL = BsL + s * BS + ks * 64 + lane * 2;
            #pragma unroll
            for (int nt = 0; nt < NT; nt++) {
                int nti = (wn >> 3) + nt;
                uint2 u2h = *(const uint2*)&bH[nti * 128];
                uint2 u2l = *(const uint2*)&bL[nti * 128];
                unsigned bh[2] = {u2h.x, u2h.y};
                unsigned bl[2] = {u2l.x, u2l.y};
                #pragma unroll
                for (int mt = 0; mt < 2; mt++) {
                    mma16816(acc[mt][nt], ah[mt], bh);
                    mma16816(acc[mt][nt], ah[mt], bl);
                    mma16816(acc[mt][nt], al[mt], bh);
                }
            }
        }
        __syncthreads();
    }
    #undef FILL_TILE

    #pragma unroll
    for (int mt = 0; mt < 2; mt++) {
        #pragma unroll
        for (int nt = 0; nt < NT; nt++) {
            int row0 = bm + wm + mt * 16 + g;
            int col  = bn + wn + nt * 8 + 2 * t;
            float v0 = acc[mt][nt][0], v1 = acc[mt][nt][1];
            float v2 = acc[mt][nt][2], v3 = acc[mt][nt][3];
            if (mat == 2) {
                float p0 = __shfl_xor_sync(0xffffffffu, v0, 4);
                float p1 = __shfl_xor_sync(0xffffffffu, v1, 4);
                float p2 = __shfl_xor_sync(0xffffffffu, v2, 4);
                float p3 = __shfl_xor_sync(0xffffffffu, v3, 4);
                if (!(g & 1)) {
                    int bb = row0 >> 11;
                    int tt = row0 & (TT - 1);
                    int h  = col >> 5, vd = col & 31;
                    int kp = tt >> 1;
                    int q  = 4 * (vd & 7) + (kp & 3);
                    size_t base = (size_t)(bb * HH + h) * 32768
                                + (size_t)(kp >> 3) * 256 + (size_t)(vd >> 3) * 64
                                + (size_t)(2 * q);
                    unsigned w0, x0, w1, x1, w2, x2, w3, x3;
                    pack_hilo(v0, p0, w0, x0);
                    pack_hilo(v2, p2, w1, x1);
                    pack_hilo(v1, p1, w2, x2);
                    pack_hilo(v3, p3, w3, x3);
                    *(uint2*)&Vh[base]     = make_uint2(w0, w1);
                    *(uint2*)&Vl[base]     = make_uint2(x0, x1);
                    *(uint2*)&Vh[base + 8] = make_uint2(w2, w3);
                    *(uint2*)&Vl[base + 8] = make_uint2(x2, x3);
                }
            } else if (mat == 1) {
                unsigned h0, l0, h1, l1;
                pack_hilo(v0, v1, h0, l0);
                pack_hilo(v2, v3, h1, l1);
                int bb = row0 >> 11;
                int tt = row0 & (TT - 1);
                int h  = col >> 5;
                int kph = (col >> 1) & 15;
                size_t kb = (size_t)(bb * HH + h) * 32768
                          + ((size_t)(tt >> 3) * 2 + (kph >> 3)) * 64
                          + (size_t)((4 * (tt & 7) + (kph & 3)) * 2 + ((kph >> 2) & 1));
                Ch2[kb]       = h0;  Cl2[kb]       = l0;
                Ch2[kb + 128] = h1;  Cl2[kb + 128] = l1;
            } else {
                unsigned h0, l0, h1, l1;
                pack_hilo(v0, v1, h0, l0);
                pack_hilo(v2, v3, h1, l1);
                int NP = N >> 1, cp = col >> 1;
                Ch[(size_t)row0 * NP + cp]       = h0;
                Cl[(size_t)row0 * NP + cp]       = l0;
                Ch[(size_t)(row0 + 8) * NP + cp] = h1;
                Cl[(size_t)(row0 + 8) * NP + cp] = l1;
            }
        }
    }
}

// -------------------- fp16 single-pass GEMM (MLP0, MLP1, unembedding) ------------
// A fp16x2 A-fragment-major; B fp16x2 B-fragment-major.
// EPI 0: fp32 C. 1: relu(acc+bias) -> fp16 A-fragment-major. 2: acc+bias fp32.
template <int EPI, int BN>
__global__ __launch_bounds__(256, 2) void hgemm(
    const unsigned* __restrict__ Af, const unsigned* __restrict__ Bf,
    float* __restrict__ C, unsigned* __restrict__ Cf,
    const float* __restrict__ bias, int M, int N, int KP) {
    constexpr int NT = BN / 16;
    constexpr int AS = 2048;
    constexpr int BS = 16 * BN;
    extern __shared__ unsigned smh[];
    unsigned* Asf = smh;            // [2][AS]
    unsigned* Bsf = smh + 2 * AS;   // [2][BS]

    const int bm = blockIdx.y * 128;
    const int bn = blockIdx.x * BN;
    const int tid  = threadIdx.x;
    const int lane = tid & 31;
    const int wid  = tid >> 5;
    const int g = lane >> 2;
    const int t = lane & 3;
    const int wm = (wid & 3) * 32;
    const int wn = (wid >> 2) * (BN / 2);
    const int kpt = KP >> 3;

    float acc[2][NT][4];
    #pragma unroll
    for (int mt = 0; mt < 2; mt++)
        #pragma unroll
        for (int nt = 0; nt < NT; nt++)
            #pragma unroll
            for (int r = 0; r < 4; r++) acc[mt][nt][r] = 0.f;

    #define HFILL(s, kp0)                                                           \
        do {                                                                         \
            _Pragma("unroll")                                                        \
            for (int it_ = 0; it_ < 2; it_++) {                                      \
                int i_ = it_ * 256 + tid;                                            \
                int tl_ = i_ >> 5;                                                   \
                size_t ga_ = ((size_t)((bm >> 4) + (tl_ >> 1)) * kpt                 \
                              + ((kp0) >> 3) + (tl_ & 1)) * 128 + (i_ & 31) * 4;     \
                cp16(&Asf[(s) * AS + i_ * 4], Af + ga_);                             \
            }                                                                        \
            _Pragma("unroll")                                                        \
            for (int it_ = 0; it_ < BN / 64; it_++) {                                \
                int f_ = it_ * 256 + tid;                                            \
                size_t gb_ = ((size_t)((bn >> 3) + (f_ >> 5)) * kpt                  \
                              + ((kp0) >> 3) + ((f_ >> 4) & 1)) * 64 + (f_ & 15) * 4;\
                cp16(&Bsf[(s) * BS + f_ * 4], Bf + gb_);                             \
            }                                                                        \
        } while (0)

    const int NKT = KP / 16;
    HFILL(0, 0);
    CP_COMMIT();

    for (int kt = 0; kt < NKT; kt++) {
        const int s = kt & 1;
        if (kt + 1 < NKT) {
            HFILL(s ^ 1, (kt + 1) * 16);
            CP_COMMIT();
            cp_wait<1>();
        } else {
            cp_wait<0>();
        }
        __syncthreads();

        #pragma unroll
        for (int ks = 0; ks < 2; ks++) {
            unsigned af[2][4];
            #pragma unroll
            for (int mt = 0; mt < 2; mt++) {
                int atile = (((wid & 3) * 2 + mt) * 2 + ks) * 128 + lane * 4;
                uint4 u = *(const uint4*)&Asf[s * AS + atile];
                af[mt][0] = u.x; af[mt][1] = u.y; af[mt][2] = u.z; af[mt][3] = u.w;
            }
            const unsigned* bF = Bsf + s * BS + ks * 64 + lane * 2;
            #pragma unroll
            for (int nt = 0; nt < NT; nt++) {
                int nti = (wn >> 3) + nt;
                uint2 u2 = *(const uint2*)&bF[nti * 128];
                unsigned bf2[2] = {u2.x, u2.y};
                #pragma unroll
                for (int mt = 0; mt < 2; mt++)
                    mma16816h(acc[mt][nt], af[mt], bf2);
            }
        }
        __syncthreads();
    }
    #undef HFILL

    const int opt = N >> 4;   // output kp-tiles per 16-row block (EPI 1)
    #pragma unroll
    for (int mt = 0; mt < 2; mt++) {
        #pragma unroll
        for (int nt = 0; nt < NT; nt++) {
            int row0 = bm + wm + mt * 16 + g;
            int col  = bn + wn + nt * 8 + 2 * t;
            float v0 = acc[mt][nt][0], v1 = acc[mt][nt][1];
            float v2 = acc[mt][nt][2], v3 = acc[mt][nt][3];
            if (EPI == 0) {
                *(float2*)(C + (size_t)row0 * N + col)       = make_float2(v0, v1);
                *(float2*)(C + (size_t)(row0 + 8) * N + col) = make_float2(v2, v3);
            } else if (EPI == 2) {
                float b0 = bias[col], b1 = bias[col + 1];
                *(float2*)(C + (size_t)row0 * N + col)       = make_float2(v0 + b0, v1 + b1);
                *(float2*)(C + (size_t)(row0 + 8) * N + col) = make_float2(v2 + b0, v3 + b1);
            } else {  // EPI 1: relu(+bias) -> fp16 A-fragment-major
                float b0 = bias[col], b1 = bias[col + 1];
                v0 = fmaxf(v0 + b0, 0.f); v1 = fmaxf(v1 + b1, 0.f);
                v2 = fmaxf(v2 + b0, 0.f); v3 = fmaxf(v3 + b1, 0.f);
                int cp = col >> 1;
                size_t tb = ((size_t)(row0 >> 4) * opt + (cp >> 3)) * 128
                          + (size_t)(((g & 7) * 4 + (cp & 3)) * 4 + (((cp >> 2) & 1) << 1));
                Cf[tb]     = pack_f16(v0, v1);
                Cf[tb + 1] = pack_f16(v2, v3);
            }
        }
    }
}

// -------------------- tensor-core causal attention (fragment-major K/V) ---------
__global__ __launch_bounds__(256, 2) void attention_mma2(
    const unsigned* __restrict__ qh, const unsigned* __restrict__ ql,
    const unsigned* __restrict__ kh, const unsigned* __restrict__ kl,
    const unsigned* __restrict__ vth, const unsigned* __restrict__ vtl,
    float* __restrict__ ov) {
    __shared__ unsigned Ks_hi[2][1024];
    __shared__ unsigned Ks_lo[2][1024];
    __shared__ unsigned Vs_hi[2][1024];
    __shared__ unsigned Vs_lo[2][1024];

    const int bh = blockIdx.y;
    const int b  = bh >> 3, h = bh & 7;
    const int t0 = (gridDim.x - 1 - blockIdx.x) * 128;
    const int tid  = threadIdx.x;
    const int lane = tid & 31;
    const int wid  = tid >> 5;
    const int g = lane >> 2;
    const int t = lane & 3;
    const int wm = wid * 16;

    unsigned qfh[2][4], qfl[2][4];
    {
        size_t base = (size_t)(b * TT + t0 + wm) * KP_DM + h * 16;
        #pragma unroll
        for (int ks = 0; ks < 2; ks++) {
            qfh[ks][0] = qh[base + (size_t)g * KP_DM + ks * 8 + t];
            qfh[ks][1] = qh[base + (size_t)(g + 8) * KP_DM + ks * 8 + t];
            qfh[ks][2] = qh[base + (size_t)g * KP_DM + ks * 8 + t + 4];
            qfh[ks][3] = qh[base + (size_t)(g + 8) * KP_DM + ks * 8 + t + 4];
            qfl[ks][0] = ql[base + (size_t)g * KP_DM + ks * 8 + t];
            qfl[ks][1] = ql[base + (size_t)(g + 8) * KP_DM + ks * 8 + t];
            qfl[ks][2] = ql[base + (size_t)g * KP_DM + ks * 8 + t + 4];
            qfl[ks][3] = ql[base + (size_t)(g + 8) * KP_DM + ks * 8 + t + 4];
        }
    }

    float o[4][4];
    #pragma unroll
    for (int nf = 0; nf < 4; nf++)
        #pragma unroll
        for (int r = 0; r < 4; r++) o[nf][r] = 0.f;
    float rs0 = 0.f, rs1 = 0.f;

    const int row0 = t0 + wm + g;
    const int row1 = row0 + 8;
    const int nit = t0 / 64 + 2;

    #define ISSUE_TILE(s, o0)                                                        \
        do {                                                                          \
            size_t gi = (size_t)bh * 32768 + (size_t)(o0) * 16 + tid * 4;             \
            cp16(&Ks_hi[s][tid * 4], kh + gi);                                        \
            cp16(&Ks_lo[s][tid * 4], kl + gi);                                        \
            cp16(&Vs_hi[s][tid * 4], vth + gi);                                       \
            cp16(&Vs_lo[s][tid * 4], vtl + gi);                                       \
        } while (0)

    ISSUE_TILE(0, 0);
    CP_COMMIT();

    for (int it = 0; it < nit; it++) {
        const int o0 = it * 64;
        const int s = it & 1;
        if (it + 1 < nit) {
            ISSUE_TILE(s ^ 1, o0 + 64);
            CP_COMMIT();
            cp_wait<1>();
        } else {
            cp_wait<0>();
        }
        __syncthreads();

        if (o0 <= t0 + wm + 15) {
            float c[8][4];
            #pragma unroll
            for (int j = 0; j < 8; j++)
                #pragma unroll
                for (int r = 0; r < 4; r++) c[j][r] = 0.f;
            #pragma unroll
            for (int j = 0; j < 8; j++) {
                #pragma unroll
                for (int ks = 0; ks < 2; ks++) {
                    uint2 uh = *(const uint2*)&Ks_hi[s][(j * 2 + ks) * 64 + lane * 2];
                    uint2 ul = *(const uint2*)&Ks_lo[s][(j * 2 + ks) * 64 + lane * 2];
                    unsigned bhf[2] = {uh.x, uh.y};
                    unsigned blf[2] = {ul.x, ul.y};
                    mma16816(c[j], qfh[ks], bhf);
                    mma16816(c[j], qfh[ks], blf);
                    mma16816(c[j], qfl[ks], bhf);
                }
            }
            if (o0 + 63 <= t0 + wm) {
                #pragma unroll
                for (int j = 0; j < 8; j++) {
                    if (j < 2) {
                        c[j][0] = fast_exp(fmaxf(fminf(c[j][0], 50.f), -80.f));
                        c[j][1] = fast_exp(fmaxf(fminf(c[j][1], 50.f), -80.f));
                        c[j][2] = fast_exp(fmaxf(fminf(c[j][2], 50.f), -80.f));
                        c[j][3] = fast_exp(fmaxf(fminf(c[j][3], 50.f), -80.f));
                    } else {
                        c[j][0] = __expf(fminf(c[j][0], 50.f));
                        c[j][1] = __expf(fminf(c[j][1], 50.f));
                        c[j][2] = __expf(fminf(c[j][2], 50.f));
                        c[j][3] = __expf(fminf(c[j][3], 50.f));
                    }
                    rs0 += c[j][0] + c[j][1];
                    rs1 += c[j][2] + c[j][3];
                }
            } else {
                #pragma unroll
                for (int j = 0; j < 8; j++) {
                    int cb = o0 + j * 8 + 2 * t;
                    float e0, e1, e2, e3;
                    if (j < 2) {
                        e0 = fast_exp(fmaxf(fminf(c[j][0], 50.f), -80.f));
                        e1 = fast_exp(fmaxf(fminf(c[j][1], 50.f), -80.f));
                        e2 = fast_exp(fmaxf(fminf(c[j][2], 50.f), -80.f));
                        e3 = fast_exp(fmaxf(fminf(c[j][3], 50.f), -80.f));
                    } else {
                        e0 = __expf(fminf(c[j][0], 50.f));
                        e1 = __expf(fminf(c[j][1], 50.f));
                        e2 = __expf(fminf(c[j][2], 50.f));
                        e3 = __expf(fminf(c[j][3], 50.f));
                    }
                    c[j][0] = (cb     <= row0) ? e0 : 0.f;
                    c[j][1] = (cb + 1 <= row0) ? e1 : 0.f;
                    c[j][2] = (cb     <= row1) ? e2 : 0.f;
                    c[j][3] = (cb + 1 <= row1) ? e3 : 0.f;
                    rs0 += c[j][0] + c[j][1];
                    rs1 += c[j][2] + c[j][3];
                }
            }
            #pragma unroll
            for (int klq = 0; klq < 4; klq++) {
                unsigned ph[4], pl[4];
                pack_hilo(c[2 * klq][0],     c[2 * klq][1],     ph[0], pl[0]);
                pack_hilo(c[2 * klq][2],     c[2 * klq][3],     ph[1], pl[1]);
                pack_hilo(c[2 * klq + 1][0], c[2 * klq + 1][1], ph[2], pl[2]);
                pack_hilo(c[2 * klq + 1][2], c[2 * klq + 1][3], ph[3], pl[3]);
                #pragma unroll
                for (int nf = 0; nf < 4; nf++) {
                    uint2 vh2 = *(const uint2*)&Vs_hi[s][(klq * 4 + nf) * 64 + lane * 2];
                    uint2 vl2 = *(const uint2*)&Vs_lo[s][(klq * 4 + nf) * 64 + lane * 2];
                    unsigned vhf[2] = {vh2.x, vh2.y};
                    unsigned vlf[2] = {vl2.x, vl2.y};
                    mma16816(o[nf], ph, vhf);
                    mma16816(o[nf], ph, vlf);
                    mma16816(o[nf], pl, vhf);
                }
            }
        }
        __syncthreads();
    }
    #undef ISSUE_TILE

    rs0 += __shfl_xor_sync(0xffffffffu, rs0, 1);
    rs0 += __shfl_xor_sync(0xffffffffu, rs0, 2);
    rs1 += __shfl_xor_sync(0xffffffffu, rs1, 1);
    rs1 += __shfl_xor_sync(0xffffffffu, rs1, 2);
    float i0 = 1.f / (rs0 + 1e-10f);
    float i1 = 1.f / (rs1 + 1e-10f);
    size_t r0 = (size_t)(b * TT + row0);
    #pragma unroll
    for (int nf = 0; nf < 4; nf++) {
        int vd = h * DKk + nf * 8 + 2 * t;
        *(float2*)(ov + r0 * DM + vd)       = make_float2(o[nf][0] * i0, o[nf][1] * i0);
        *(float2*)(ov + (r0 + 8) * DM + vd) = make_float2(o[nf][2] * i1, o[nf][3] * i1);
    }
}

// -------------------- launch --------------------------------------------------
extern "C" void kernel_launch(void* const* d_in, const int* in_sizes, int n_in,
                              void* d_out, int out_size) {
    const int*   x     = (const int*)  d_in[0];
    const float* emb   = (const float*)d_in[1];
    const float* pos   = (const float*)d_in[2];
    const float* wq    = (const float*)d_in[3];
    const float* wk    = (const float*)d_in[4];
    const float* wv    = (const float*)d_in[5];
    const float* wo    = (const float*)d_in[6];
    const float* mlp0  = (const float*)d_in[7];
    const float* mlpb  = (const float*)d_in[8];
    const float* mlp1  = (const float*)d_in[9];
    const float* unemb = (const float*)d_in[10];
    const float* bias  = (const float*)d_in[11];
    float* out = (float*)d_out;

    unsigned *hh_, *hl_, *hf_, *qh_, *ql_, *kh_, *kl_, *yf_, *wh_, *wl_, *vth_, *vtl_;
    float *ov_, *tmp_, *wos_;
    cudaGetSymbolAddress((void**)&hh_, g_hh);
    cudaGetSymbolAddress((void**)&hl_, g_hl);
    cudaGetSymbolAddress((void**)&hf_, g_hf);
    cudaGetSymbolAddress((void**)&qh_, g_qh);
    cudaGetSymbolAddress((void**)&ql_, g_ql);
    cudaGetSymbolAddress((void**)&kh_, g_kh);
    cudaGetSymbolAddress((void**)&kl_, g_kl);
    cudaGetSymbolAddress((void**)&yf_, g_yf);
    cudaGetSymbolAddress((void**)&wh_, g_wh);
    cudaGetSymbolAddress((void**)&wl_, g_wl);
    cudaGetSymbolAddress((void**)&vth_, g_vth);
    cudaGetSymbolAddress((void**)&vtl_, g_vtl);
    cudaGetSymbolAddress((void**)&ov_,  g_ov);
    cudaGetSymbolAddress((void**)&tmp_, g_tmp);
    cudaGetSymbolAddress((void**)&wos_, g_wosum);

    const int SM128 = (8192 + 4 * 16 * 128) * 4;        // QKV bf16 3-term
    const int SMH128 = (2 * 2048 + 2 * 16 * 128) * 4;   // 32768 B
    const int SMH64  = (2 * 2048 + 2 * 16 * 64)  * 4;   // 24576 B
    cudaFuncSetAttribute(mgemm_db<128>, cudaFuncAttributeMaxDynamicSharedMemorySize, SM128);
    cudaFuncSetAttribute(hgemm<1, 128>, cudaFuncAttributeMaxDynamicSharedMemorySize, SMH128);
    cudaFuncSetAttribute(hgemm<0, 64>,  cudaFuncAttributeMaxDynamicSharedMemorySize, SMH64);
    cudaFuncSetAttribute(hgemm<2, 128>, cudaFuncAttributeMaxDynamicSharedMemorySize, SMH128);

    detect_idx<<<1, 64>>>(x);
    convert_weights<<<(W_TOT + 255) / 256, 256>>>(wq, wk, wv, mlp0, mlp1, unemb);
    compute_wosum_all<<<(NL * DKk * DM + 255) / 256, 256>>>(wo);
    embed_ln_w<<<BT / 8, 256>>>(x, emb, pos);

    for (int l = 0; l < NL; l++) {
        const unsigned* wqkv_h = wh_ + (size_t)(l * 3) * DM * KP_DM;
        const unsigned* wqkv_l = wl_ + (size_t)(l * 3) * DM * KP_DM;
        const unsigned* m0f = wh_ + W_M0 + (size_t)l * DHid * KP_DM;
        const unsigned* m1f = wh_ + W_M1 + (size_t)l * DM * KP_HID;

        mgemm_db<128><<<dim3(6, BT / 128), 256, SM128>>>(
            hh_, hl_, wqkv_h, wqkv_l, qh_, ql_, kh_, kl_, vth_, vtl_,
            BT, DM, KP_DM);

        attention_mma2<<<dim3(TT / 128, BB * HH), 256>>>(qh_, ql_, kh_, kl_, vth_, vtl_, ov_);
        attn_out_ln_w<<<BT / 8, 256>>>(ov_, wos_ + (size_t)l * DKk * DM);

        hgemm<1, 128><<<dim3(DHid / 128, BT / 128), 256, SMH128>>>(
            hf_, m0f, nullptr, yf_, mlpb + (size_t)l * DHid, BT, DHid, KP_DM);
        hgemm<0, 64><<<dim3(DM / 64, BT / 128), 256, SMH64>>>(
            yf_, m1f, tmp_, nullptr, nullptr, BT, DM, KP_HID);
        ln_residual_w<<<BT / 8, 256>>>(tmp_);
    }

    hgemm<2, 128><<<dim3(ND / 128, BT / 128), 256, SMH128>>>(
        hf_, wh_ + W_UE, out, nullptr, bias, BT, ND, KP_DM);
}

// round 17
// speedup vs baseline: 1.6231x; 1.0247x over previous
#include <cuda_runtime.h>
#include <cuda_bf16.h>
#include <math.h>

#define BB 4
#define TT 2048
#define BT (BB*TT)
#define DM 256
#define HH 8
#define DKk 32
#define DHid 1024
#define ND 8192
#define NL 4

#define KP_DM (DM/2)      // 128 pairs
#define KP_HID (DHid/2)   // 512 pairs

// packed-weight regions (u32). QKV: bf16x2 hi/lo B-fragment-major.
// M0/M1/UE: fp16x2 single-pass B-fragment-major (g_wh only).
#define W_M0 (NL*3*DM*KP_DM)
#define W_M1 (W_M0 + NL*DHid*KP_DM)
#define W_UE (W_M1 + NL*DM*KP_HID)
#define W_TOT (W_UE + ND*KP_DM)

// -------------------- scratch (device globals) ---------------------------------
__device__ float    g_h  [BT*DM];
__device__ unsigned g_hh [BT*KP_DM];   // A-fragment-major bf16x2 hi
__device__ unsigned g_hl [BT*KP_DM];   // A-fragment-major bf16x2 lo
__device__ unsigned g_hf [BT*KP_DM];   // A-fragment-major fp16x2
__device__ unsigned g_qh [BT*KP_DM];   // row-major [token][kp]
__device__ unsigned g_ql [BT*KP_DM];
__device__ unsigned g_kh [BT*KP_DM];   // K fragment-major: [bh][keyT(256)][kpT(2)][64]
__device__ unsigned g_kl [BT*KP_DM];
__device__ unsigned g_vth[BT*KP_DM];   // V fragment-major: [bh][kpT(128)][vdT(4)][64]
__device__ unsigned g_vtl[BT*KP_DM];
__device__ float    g_ov [BT*DM];
__device__ unsigned g_yf [BT*KP_HID];  // MLP hidden, fp16x2 A-fragment-major
__device__ float    g_tmp[BT*DM];
__device__ unsigned g_wh [W_TOT];
__device__ unsigned g_wl [W_TOT];
__device__ float    g_wosum[NL*DKk*DM];
__device__ int      g_is64;

// -------------------- helpers -------------------------------------------------
__device__ __forceinline__ void pack_hilo(float x, float y, unsigned& hi, unsigned& lo) {
    unsigned h;
    asm("cvt.rn.bf16x2.f32 %0, %1, %2;" : "=r"(h) : "f"(y), "f"(x));
    float xr = x - __uint_as_float(h << 16);
    float yr = y - __uint_as_float(h & 0xffff0000u);
    asm("cvt.rn.bf16x2.f32 %0, %1, %2;" : "=r"(lo) : "f"(yr), "f"(xr));
    hi = h;
}

__device__ __forceinline__ unsigned pack_f16(float x, float y) {
    unsigned r;
    asm("cvt.rn.f16x2.f32 %0, %1, %2;" : "=r"(r) : "f"(y), "f"(x));
    return r;
}

__device__ __forceinline__ void mma16816(float* c, const unsigned* a, const unsigned* b) {
    asm volatile(
        "mma.sync.aligned.m16n8k16.row.col.f32.bf16.bf16.f32 "
        "{%0,%1,%2,%3}, {%4,%5,%6,%7}, {%8,%9}, {%0,%1,%2,%3};\n"
        : "+f"(c[0]), "+f"(c[1]), "+f"(c[2]), "+f"(c[3])
        : "r"(a[0]), "r"(a[1]), "r"(a[2]), "r"(a[3]), "r"(b[0]), "r"(b[1]));
}

__device__ __forceinline__ void mma16816h(float* c, const unsigned* a, const unsigned* b) {
    asm volatile(
        "mma.sync.aligned.m16n8k16.row.col.f32.f16.f16.f32 "
        "{%0,%1,%2,%3}, {%4,%5,%6,%7}, {%8,%9}, {%0,%1,%2,%3};\n"
        : "+f"(c[0]), "+f"(c[1]), "+f"(c[2]), "+f"(c[3])
        : "r"(a[0]), "r"(a[1]), "r"(a[2]), "r"(a[3]), "r"(b[0]), "r"(b[1]));
}

__device__ __forceinline__ void cp16(void* sdst, const void* gsrc) {
    unsigned sa = (unsigned)__cvta_generic_to_shared(sdst);
    asm volatile("cp.async.cg.shared.global [%0], [%1], 16;\n" :: "r"(sa), "l"(gsrc));
}
#define CP_COMMIT() asm volatile("cp.async.commit_group;\n" ::: "memory")
template <int N> __device__ __forceinline__ void cp_wait() {
    asm volatile("cp.async.wait_group %0;\n" :: "n"(N) : "memory");
}

__device__ __forceinline__ float warp_sum(float v) {
    #pragma unroll
    for (int o = 16; o; o >>= 1) v += __shfl_xor_sync(0xffffffffu, v, o);
    return v;
}

// A-fragment-major index: tile = 16m x 8kp (128 u32)
__device__ __forceinline__ size_t afrag_idx(int m, int kp, int kpt8) {
    int quad = (m & 7) * 4 + (kp & 3);
    int word = ((m >> 3) & 1) + (((kp >> 2) & 1) << 1);
    return ((size_t)(m >> 4) * kpt8 + (kp >> 3)) * 128 + quad * 4 + word;
}

// -------------------- index dtype probe ---------------------------------------
__global__ void detect_idx(const int* __restrict__ xi) {
    __shared__ int ok;
    if (threadIdx.x == 0) ok = 1;
    __syncthreads();
    if (xi[2 * threadIdx.x + 1] != 0) atomicAnd(&ok, 0);
    __syncthreads();
    if (threadIdx.x == 0) g_is64 = ok;
}

// -------------------- one-shot weight pre-conversion (B fragment-major) --------
__device__ __forceinline__ size_t frag_idx(int n, int kp, int kpt) {
    return ((size_t)(n >> 3) * kpt + (kp >> 3)) * 64
         + (size_t)((4 * (n & 7) + (kp & 3)) * 2 + ((kp >> 2) & 1));
}

__global__ __launch_bounds__(256) void convert_weights(
    const float* __restrict__ wq, const float* __restrict__ wk,
    const float* __restrict__ wv, const float* __restrict__ m0,
    const float* __restrict__ m1, const float* __restrict__ ue) {
    int i = blockIdx.x * 256 + threadIdx.x;
    if (i >= W_TOT) return;
    float a, b;
    size_t out;
    if (i < W_M0) {                       // QKV per-head [n/32][k][n%32]: bf16 hi/lo
        int l3 = i >> 15;
        int r  = i & 32767;
        int kp = r >> 8;
        int n  = r & 255;
        int l = l3 / 3, mi = l3 % 3;
        const float* W = (mi == 0) ? wq : (mi == 1) ? wk : wv;
        size_t base = (size_t)l * HH * DM * DKk + (size_t)(n >> 5) * DM * DKk + (n & 31);
        a = W[base + (size_t)(2 * kp)     * DKk];
        b = W[base + (size_t)(2 * kp + 1) * DKk];
        out = (size_t)l3 * 32768 + frag_idx(n, kp, KP_DM / 8);
        unsigned hi, lo;
        pack_hilo(a, b, hi, lo);
        g_wh[out] = hi;
        g_wl[out] = lo;
        return;
    } else if (i < W_M1) {                // mlp0 [k][1024] -> fp16 single
        int r = i - W_M0;
        int l = r >> 17;
        int rr = r & 131071;
        int kp = rr >> 10;
        int n  = rr & 1023;
        const float* W = m0 + (size_t)l * DM * DHid;
        a = W[(size_t)(2 * kp)     * DHid + n];
        b = W[(size_t)(2 * kp + 1) * DHid + n];
        out = W_M0 + (size_t)l * 131072 + frag_idx(n, kp, KP_DM / 8);
    } else if (i < W_UE) {                // mlp1 [k][256] -> fp16 single
        int r = i - W_M1;
        int l = r >> 17;
        int rr = r & 131071;
        int kp = rr >> 8;
        int n  = rr & 255;
        const float* W = m1 + (size_t)l * DHid * DM;
        a = W[(size_t)(2 * kp)     * DM + n];
        b = W[(size_t)(2 * kp + 1) * DM + n];
        out = W_M1 + (size_t)l * 131072 + frag_idx(n, kp, KP_HID / 8);
    } else {                              // unembedding [k][8192] -> fp16 single
        int r = i - W_UE;
        int kp = r >> 13;
        int n  = r & 8191;
        a = ue[(size_t)(2 * kp)     * ND + n];
        b = ue[(size_t)(2 * kp + 1) * ND + n];
        out = W_UE + frag_idx(n, kp, KP_DM / 8);
    }
    g_wh[out] = pack_f16(a, b);
}

// -------------------- wo summed over heads --------------------------------------
__global__ void compute_wosum_all(const float* __restrict__ wo) {
    int i = blockIdx.x * 256 + threadIdx.x;
    if (i < NL * DKk * DM) {
        int l = i / (DKk * DM);
        int r = i % (DKk * DM);
        float s = 0.f;
        #pragma unroll
        for (int hh = 0; hh < HH; hh++)
            s += wo[(size_t)l * HH * DKk * DM + (size_t)hh * DKk * DM + r];
        g_wosum[i] = s;
    }
}

// -------------------- warp-per-token LN (A-fragment-major packed out) -----------
__device__ __forceinline__ void ln_store_warp(int token, int lane, float* val) {
    float s = 0.f;
    #pragma unroll
    for (int j = 0; j < 8; j++) s += val[j];
    s = warp_sum(s);
    float m = s * (1.f / DM);
    float vv = 0.f;
    #pragma unroll
    for (int j = 0; j < 8; j++) { val[j] -= m; vv += val[j] * val[j]; }
    vv = warp_sum(vv);
    float inv = rsqrtf(vv * (1.f / DM) + 1e-5f);
    #pragma unroll
    for (int j = 0; j < 8; j++) {
        float out = val[j] * inv;
        int d = j * 32 + lane;
        g_h[(size_t)token * DM + d] = out;
        float other = __shfl_xor_sync(0xffffffffu, out, 1);
        if (!(lane & 1)) {
            unsigned hi, lo;
            pack_hilo(out, other, hi, lo);
            int kp = j * 16 + (lane >> 1);
            size_t o = afrag_idx(token & 15, kp, KP_DM / 8)
                     + (size_t)(token >> 4) * (size_t)(16 * KP_DM);
            g_hh[o] = hi;
            g_hl[o] = lo;
            g_hf[o] = pack_f16(out, other);
        }
    }
}

__global__ __launch_bounds__(256) void embed_ln_w(const int* __restrict__ xi,
                                                  const float* __restrict__ emb,
                                                  const float* __restrict__ pos) {
    int token = blockIdx.x * 8 + (threadIdx.x >> 5);
    int lane = threadIdx.x & 31;
    int t = token % TT;
    int idx = g_is64 ? xi[2 * token] : xi[token];
    float val[8];
    #pragma unroll
    for (int j = 0; j < 8; j++) {
        int d = j * 32 + lane;
        val[j] = emb[(size_t)idx * DM + d] + pos[(size_t)t * DM + d];
    }
    ln_store_warp(token, lane, val);
}

__global__ __launch_bounds__(256) void attn_out_ln_w(const float* __restrict__ ov,
                                                     const float* __restrict__ wos) {
    int token = blockIdx.x * 8 + (threadIdx.x >> 5);
    int lane = threadIdx.x & 31;
    float vs = 0.f;
    float val[8];
    #pragma unroll
    for (int j = 0; j < 8; j++) {
        float o = ov[(size_t)token * DM + j * 32 + lane];
        vs += o;
        val[j] = g_h[(size_t)token * DM + j * 32 + lane];
    }
    #pragma unroll
    for (int v = 0; v < DKk; v++) {
        float sv = __shfl_sync(0xffffffffu, vs, v);
        #pragma unroll
        for (int j = 0; j < 8; j++) val[j] += sv * wos[v * DM + j * 32 + lane];
    }
    ln_store_warp(token, lane, val);
}

__global__ __launch_bounds__(256) void ln_residual_w(const float* __restrict__ add) {
    int token = blockIdx.x * 8 + (threadIdx.x >> 5);
    int lane = threadIdx.x & 31;
    float val[8];
    #pragma unroll
    for (int j = 0; j < 8; j++) {
        int d = j * 32 + lane;
        val[j] = g_h[(size_t)token * DM + d] + add[(size_t)token * DM + d];
    }
    ln_store_warp(token, lane, val);
}

// -------------------- QKV GEMM: bf16 3-term, fragment-major A AND B --------------
// q->row-major Ch/Cl, k->K-fragment-major Ch2/Cl2, v->V-fragment-major Vh/Vl.
template <int BN>
__global__ __launch_bounds__(256, 2) void mgemm_db(
    const unsigned* __restrict__ Ah, const unsigned* __restrict__ Al,
    const unsigned* __restrict__ Bh, const unsigned* __restrict__ Bl,
    unsigned* __restrict__ Ch, unsigned* __restrict__ Cl,
    unsigned* __restrict__ Ch2, unsigned* __restrict__ Cl2,
    unsigned* __restrict__ Vh, unsigned* __restrict__ Vl,
    int M, int N, int KP) {
    constexpr int NT = BN / 16;
    constexpr int BS = 16 * BN;
    constexpr int AS = 2048;
    extern __shared__ unsigned smq[];
    unsigned* AsH = smq;
    unsigned* AsL = smq + 2 * AS;
    unsigned* BsH = smq + 4 * AS;
    unsigned* BsL = BsH + 2 * BS;

    const int bm = blockIdx.y * 128;
    const int mat = blockIdx.x >> 1;
    const int bn = (blockIdx.x & 1) * 128;
    Bh += (size_t)mat * DM * KP_DM;
    Bl += (size_t)mat * DM * KP_DM;
    const int tid  = threadIdx.x;
    const int lane = tid & 31;
    const int wid  = tid >> 5;
    const int g = lane >> 2;
    const int t = lane & 3;
    const int wm = (wid & 3) * 32;
    const int wn = (wid >> 2) * (BN / 2);
    const int kpt  = KP >> 3;

    float acc[2][NT][4];
    #pragma unroll
    for (int mt = 0; mt < 2; mt++)
        #pragma unroll
        for (int nt = 0; nt < NT; nt++)
            #pragma unroll
            for (int r = 0; r < 4; r++) acc[mt][nt][r] = 0.f;

    #define FILL_TILE(s, kp0)                                                       \
        do {                                                                         \
            _Pragma("unroll")                                                        \
            for (int it_ = 0; it_ < 2; it_++) {                                      \
                int i_ = it_ * 256 + tid;                                            \
                int tl_ = i_ >> 5;                                                   \
                size_t ga_ = ((size_t)((bm >> 4) + (tl_ >> 1)) * kpt                 \
                              + ((kp0) >> 3) + (tl_ & 1)) * 128 + (i_ & 31) * 4;     \
                cp16(&AsH[(s) * AS + i_ * 4], Ah + ga_);                             \
                cp16(&AsL[(s) * AS + i_ * 4], Al + ga_);                             \
            }                                                                        \
            _Pragma("unroll")                                                        \
            for (int it_ = 0; it_ < BN / 64; it_++) {                                \
                int f_ = it_ * 256 + tid;                                            \
                size_t gb_ = ((size_t)((bn >> 3) + (f_ >> 5)) * kpt                  \
                              + ((kp0) >> 3) + ((f_ >> 4) & 1)) * 64 + (f_ & 15) * 4;\
                cp16(&BsH[(s) * BS + f_ * 4], Bh + gb_);                             \
                cp16(&BsL[(s) * BS + f_ * 4], Bl + gb_);                             \
            }                                                                        \
        } while (0)

    const int NKT = KP / 16;
    FILL_TILE(0, 0);
    CP_COMMIT();

    for (int kt = 0; kt < NKT; kt++) {
        const int s = kt & 1;
        if (kt + 1 < NKT) {
            FILL_TILE(s ^ 1, (kt + 1) * 16);
            CP_COMMIT();
            cp_wait<1>();
        } else {
            cp_wait<0>();
        }
        __syncthreads();

        #pragma unroll
        for (int ks = 0; ks < 2; ks++) {
            unsigned ah[2][4], al[2][4];
            #pragma unroll
            for (int mt = 0; mt < 2; mt++) {
                int atile = (((wid & 3) * 2 + mt) * 2 + ks) * 128 + lane * 4;
                uint4 uh = *(const uint4*)&AsH[s * AS + atile];
                uint4 ul = *(const uint4*)&AsL[s * AS + atile];
                ah[mt][0] = uh.x; ah[mt][1] = uh.y; ah[mt][2] = uh.z; ah[mt][3] = uh.w;
                al[mt][0] = ul.x; al[mt][1] = ul.y; al[mt][2] = ul.z; al[mt][3] = ul.w;
            }
            const unsigned* bH = BsH + s * BS + ks * 64 + lane * 2;
            const unsigned* bL = BsL + s * BS + ks * 64 + lane * 2;
            #pragma unroll
            for (int nt = 0; nt < NT; nt++) {
                int nti = (wn >> 3) + nt;
                uint2 u2h = *(const uint2*)&bH[nti * 128];
                uint2 u2l = *(const uint2*)&bL[nti * 128];
                unsigned bh[2] = {u2h.x, u2h.y};
                unsigned bl[2] = {u2l.x, u2l.y};
                #pragma unroll
                for (int mt = 0; mt < 2; mt++) {
                    mma16816(acc[mt][nt], ah[mt], bh);
                    mma16816(acc[mt][nt], ah[mt], bl);
                    mma16816(acc[mt][nt], al[mt], bh);
                }
            }
        }
        __syncthreads();
    }
    #undef FILL_TILE

    #pragma unroll
    for (int mt = 0; mt < 2; mt++) {
        #pragma unroll
        for (int nt = 0; nt < NT; nt++) {
            int row0 = bm + wm + mt * 16 + g;
            int col  = bn + wn + nt * 8 + 2 * t;
            float v0 = acc[mt][nt][0], v1 = acc[mt][nt][1];
            float v2 = acc[mt][nt][2], v3 = acc[mt][nt][3];
            if (mat == 2) {
                float p0 = __shfl_xor_sync(0xffffffffu, v0, 4);
                float p1 = __shfl_xor_sync(0xffffffffu, v1, 4);
                float p2 = __shfl_xor_sync(0xffffffffu, v2, 4);
                float p3 = __shfl_xor_sync(0xffffffffu, v3, 4);
                if (!(g & 1)) {
                    int bb = row0 >> 11;
                    int tt = row0 & (TT - 1);
                    int h  = col >> 5, vd = col & 31;
                    int kp = tt >> 1;
                    int q  = 4 * (vd & 7) + (kp & 3);
                    size_t base = (size_t)(bb * HH + h) * 32768
                                + (size_t)(kp >> 3) * 256 + (size_t)(vd >> 3) * 64
                                + (size_t)(2 * q);
                    unsigned w0, x0, w1, x1, w2, x2, w3, x3;
                    pack_hilo(v0, p0, w0, x0);
                    pack_hilo(v2, p2, w1, x1);
                    pack_hilo(v1, p1, w2, x2);
                    pack_hilo(v3, p3, w3, x3);
                    *(uint2*)&Vh[base]     = make_uint2(w0, w1);
                    *(uint2*)&Vl[base]     = make_uint2(x0, x1);
                    *(uint2*)&Vh[base + 8] = make_uint2(w2, w3);
                    *(uint2*)&Vl[base + 8] = make_uint2(x2, x3);
                }
            } else if (mat == 1) {
                unsigned h0, l0, h1, l1;
                pack_hilo(v0, v1, h0, l0);
                pack_hilo(v2, v3, h1, l1);
                int bb = row0 >> 11;
                int tt = row0 & (TT - 1);
                int h  = col >> 5;
                int kph = (col >> 1) & 15;
                size_t kb = (size_t)(bb * HH + h) * 32768
                          + ((size_t)(tt >> 3) * 2 + (kph >> 3)) * 64
                          + (size_t)((4 * (tt & 7) + (kph & 3)) * 2 + ((kph >> 2) & 1));
                Ch2[kb]       = h0;  Cl2[kb]       = l0;
                Ch2[kb + 128] = h1;  Cl2[kb + 128] = l1;
            } else {
                unsigned h0, l0, h1, l1;
                pack_hilo(v0, v1, h0, l0);
                pack_hilo(v2, v3, h1, l1);
                int NP = N >> 1, cp = col >> 1;
                Ch[(size_t)row0 * NP + cp]       = h0;
                Cl[(size_t)row0 * NP + cp]       = l0;
                Ch[(size_t)(row0 + 8) * NP + cp] = h1;
                Cl[(size_t)(row0 + 8) * NP + cp] = l1;
            }
        }
    }
}

// -------------------- fp16 single-pass GEMM (MLP0, MLP1, unembedding) ------------
// EPI 0: fp32 C. 1: relu(acc+bias) -> fp16 A-fragment-major. 2: acc+bias fp32.
template <int EPI, int BN>
__global__ __launch_bounds__(256, 2) void hgemm(
    const unsigned* __restrict__ Af, const unsigned* __restrict__ Bf,
    float* __restrict__ C, unsigned* __restrict__ Cf,
    const float* __restrict__ bias, int M, int N, int KP) {
    constexpr int NT = BN / 16;
    constexpr int AS = 2048;
    constexpr int BS = 16 * BN;
    extern __shared__ unsigned smh[];
    unsigned* Asf = smh;            // [2][AS]
    unsigned* Bsf = smh + 2 * AS;   // [2][BS]

    const int bm = blockIdx.y * 128;
    const int bn = blockIdx.x * BN;
    const int tid  = threadIdx.x;
    const int lane = tid & 31;
    const int wid  = tid >> 5;
    const int g = lane >> 2;
    const int t = lane & 3;
    const int wm = (wid & 3) * 32;
    const int wn = (wid >> 2) * (BN / 2);
    const int kpt = KP >> 3;

    float acc[2][NT][4];
    #pragma unroll
    for (int mt = 0; mt < 2; mt++)
        #pragma unroll
        for (int nt = 0; nt < NT; nt++)
            #pragma unroll
            for (int r = 0; r < 4; r++) acc[mt][nt][r] = 0.f;

    #define HFILL(s, kp0)                                                           \
        do {                                                                         \
            _Pragma("unroll")                                                        \
            for (int it_ = 0; it_ < 2; it_++) {                                      \
                int i_ = it_ * 256 + tid;                                            \
                int tl_ = i_ >> 5;                                                   \
                size_t ga_ = ((size_t)((bm >> 4) + (tl_ >> 1)) * kpt                 \
                              + ((kp0) >> 3) + (tl_ & 1)) * 128 + (i_ & 31) * 4;     \
                cp16(&Asf[(s) * AS + i_ * 4], Af + ga_);                             \
            }                                                                        \
            _Pragma("unroll")                                                        \
            for (int it_ = 0; it_ < BN / 64; it_++) {                                \
                int f_ = it_ * 256 + tid;                                            \
                size_t gb_ = ((size_t)((bn >> 3) + (f_ >> 5)) * kpt                  \
                              + ((kp0) >> 3) + ((f_ >> 4) & 1)) * 64 + (f_ & 15) * 4;\
                cp16(&Bsf[(s) * BS + f_ * 4], Bf + gb_);                             \
            }                                                                        \
        } while (0)

    const int NKT = KP / 16;
    HFILL(0, 0);
    CP_COMMIT();

    for (int kt = 0; kt < NKT; kt++) {
        const int s = kt & 1;
        if (kt + 1 < NKT) {
            HFILL(s ^ 1, (kt + 1) * 16);
            CP_COMMIT();
            cp_wait<1>();
        } else {
            cp_wait<0>();
        }
        __syncthreads();

        #pragma unroll
        for (int ks = 0; ks < 2; ks++) {
            unsigned af[2][4];
            #pragma unroll
            for (int mt = 0; mt < 2; mt++) {
                int atile = (((wid & 3) * 2 + mt) * 2 + ks) * 128 + lane * 4;
                uint4 u = *(const uint4*)&Asf[s * AS + atile];
                af[mt][0] = u.x; af[mt][1] = u.y; af[mt][2] = u.z; af[mt][3] = u.w;
            }
            const unsigned* bF = Bsf + s * BS + ks * 64 + lane * 2;
            #pragma unroll
            for (int nt = 0; nt < NT; nt++) {
                int nti = (wn >> 3) + nt;
                uint2 u2 = *(const uint2*)&bF[nti * 128];
                unsigned bf2[2] = {u2.x, u2.y};
                #pragma unroll
                for (int mt = 0; mt < 2; mt++)
                    mma16816h(acc[mt][nt], af[mt], bf2);
            }
        }
        __syncthreads();
    }
    #undef HFILL

    const int opt = N >> 4;   // output kp-tiles per 16-row block (EPI 1)
    #pragma unroll
    for (int mt = 0; mt < 2; mt++) {
        #pragma unroll
        for (int nt = 0; nt < NT; nt++) {
            int row0 = bm + wm + mt * 16 + g;
            int col  = bn + wn + nt * 8 + 2 * t;
            float v0 = acc[mt][nt][0], v1 = acc[mt][nt][1];
            float v2 = acc[mt][nt][2], v3 = acc[mt][nt][3];
            if (EPI == 0) {
                *(float2*)(C + (size_t)row0 * N + col)       = make_float2(v0, v1);
                *(float2*)(C + (size_t)(row0 + 8) * N + col) = make_float2(v2, v3);
            } else if (EPI == 2) {
                float b0 = bias[col], b1 = bias[col + 1];
                *(float2*)(C + (size_t)row0 * N + col)       = make_float2(v0 + b0, v1 + b1);
                *(float2*)(C + (size_t)(row0 + 8) * N + col) = make_float2(v2 + b0, v3 + b1);
            } else {  // EPI 1: relu(+bias) -> fp16 A-fragment-major
                float b0 = bias[col], b1 = bias[col + 1];
                v0 = fmaxf(v0 + b0, 0.f); v1 = fmaxf(v1 + b1, 0.f);
                v2 = fmaxf(v2 + b0, 0.f); v3 = fmaxf(v3 + b1, 0.f);
                int cp = col >> 1;
                size_t tb = ((size_t)(row0 >> 4) * opt + (cp >> 3)) * 128
                          + (size_t)(((g & 7) * 4 + (cp & 3)) * 4 + (((cp >> 2) & 1) << 1));
                Cf[tb]     = pack_f16(v0, v1);
                Cf[tb + 1] = pack_f16(v2, v3);
            }
        }
    }
}

// -------------------- tensor-core causal attention (fragment-major K/V) ---------
__global__ __launch_bounds__(256, 2) void attention_mma2(
    const unsigned* __restrict__ qh, const unsigned* __restrict__ ql,
    const unsigned* __restrict__ kh, const unsigned* __restrict__ kl,
    const unsigned* __restrict__ vth, const unsigned* __restrict__ vtl,
    float* __restrict__ ov) {
    __shared__ unsigned Ks_hi[2][1024];
    __shared__ unsigned Ks_lo[2][1024];
    __shared__ unsigned Vs_hi[2][1024];
    __shared__ unsigned Vs_lo[2][1024];

    const int bh = blockIdx.y;
    const int b  = bh >> 3, h = bh & 7;
    const int t0 = (gridDim.x - 1 - blockIdx.x) * 128;
    const int tid  = threadIdx.x;
    const int lane = tid & 31;
    const int wid  = tid >> 5;
    const int g = lane >> 2;
    const int t = lane & 3;
    const int wm = wid * 16;

    unsigned qfh[2][4], qfl[2][4];
    {
        size_t base = (size_t)(b * TT + t0 + wm) * KP_DM + h * 16;
        #pragma unroll
        for (int ks = 0; ks < 2; ks++) {
            qfh[ks][0] = qh[base + (size_t)g * KP_DM + ks * 8 + t];
            qfh[ks][1] = qh[base + (size_t)(g + 8) * KP_DM + ks * 8 + t];
            qfh[ks][2] = qh[base + (size_t)g * KP_DM + ks * 8 + t + 4];
            qfh[ks][3] = qh[base + (size_t)(g + 8) * KP_DM + ks * 8 + t + 4];
            qfl[ks][0] = ql[base + (size_t)g * KP_DM + ks * 8 + t];
            qfl[ks][1] = ql[base + (size_t)(g + 8) * KP_DM + ks * 8 + t];
            qfl[ks][2] = ql[base + (size_t)g * KP_DM + ks * 8 + t + 4];
            qfl[ks][3] = ql[base + (size_t)(g + 8) * KP_DM + ks * 8 + t + 4];
        }
    }

    float o[4][4];
    #pragma unroll
    for (int nf = 0; nf < 4; nf++)
        #pragma unroll
        for (int r = 0; r < 4; r++) o[nf][r] = 0.f;
    float rs0 = 0.f, rs1 = 0.f;

    const int row0 = t0 + wm + g;
    const int row1 = row0 + 8;
    const int nit = t0 / 64 + 2;

    #define ISSUE_TILE(s, o0)                                                        \
        do {                                                                          \
            size_t gi = (size_t)bh * 32768 + (size_t)(o0) * 16 + tid * 4;             \
            cp16(&Ks_hi[s][tid * 4], kh + gi);                                        \
            cp16(&Ks_lo[s][tid * 4], kl + gi);                                        \
            cp16(&Vs_hi[s][tid * 4], vth + gi);                                       \
            cp16(&Vs_lo[s][tid * 4], vtl + gi);                                       \
        } while (0)

    ISSUE_TILE(0, 0);
    CP_COMMIT();

    for (int it = 0; it < nit; it++) {
        const int o0 = it * 64;
        const int s = it & 1;
        if (it + 1 < nit) {
            ISSUE_TILE(s ^ 1, o0 + 64);
            CP_COMMIT();
            cp_wait<1>();
        } else {
            cp_wait<0>();
        }
        __syncthreads();

        if (o0 <= t0 + wm + 15) {
            float c[8][4];
            #pragma unroll
            for (int j = 0; j < 8; j++)
                #pragma unroll
                for (int r = 0; r < 4; r++) c[j][r] = 0.f;
            #pragma unroll
            for (int j = 0; j < 8; j++) {
                #pragma unroll
                for (int ks = 0; ks < 2; ks++) {
                    uint2 uh = *(const uint2*)&Ks_hi[s][(j * 2 + ks) * 64 + lane * 2];
                    uint2 ul = *(const uint2*)&Ks_lo[s][(j * 2 + ks) * 64 + lane * 2];
                    unsigned bhf[2] = {uh.x, uh.y};
                    unsigned blf[2] = {ul.x, ul.y};
                    mma16816(c[j], qfh[ks], bhf);
                    mma16816(c[j], qfh[ks], blf);
                    mma16816(c[j], qfl[ks], bhf);
                }
            }
            // exp (all-MUFU) + rowsum; interior tiles skip mask selects
            if (o0 + 63 <= t0 + wm) {
                #pragma unroll
                for (int j = 0; j < 8; j++) {
                    c[j][0] = __expf(fminf(c[j][0], 50.f));
                    c[j][1] = __expf(fminf(c[j][1], 50.f));
                    c[j][2] = __expf(fminf(c[j][2], 50.f));
                    c[j][3] = __expf(fminf(c[j][3], 50.f));
                    rs0 += c[j][0] + c[j][1];
                    rs1 += c[j][2] + c[j][3];
                }
            } else {
                #pragma unroll
                for (int j = 0; j < 8; j++) {
                    int cb = o0 + j * 8 + 2 * t;
                    float e0 = __expf(fminf(c[j][0], 50.f));
                    float e1 = __expf(fminf(c[j][1], 50.f));
                    float e2 = __expf(fminf(c[j][2], 50.f));
                    float e3 = __expf(fminf(c[j][3], 50.f));
                    c[j][0] = (cb     <= row0) ? e0 : 0.f;
                    c[j][1] = (cb + 1 <= row0) ? e1 : 0.f;
                    c[j][2] = (cb     <= row1) ? e2 : 0.f;
                    c[j][3] = (cb + 1 <= row1) ? e3 : 0.f;
                    rs0 += c[j][0] + c[j][1];
                    rs1 += c[j][2] + c[j][3];
                }
            }
            #pragma unroll
            for (int klq = 0; klq < 4; klq++) {
                unsigned ph[4], pl[4];
                pack_hilo(c[2 * klq][0],     c[2 * klq][1],     ph[0], pl[0]);
                pack_hilo(c[2 * klq][2],     c[2 * klq][3],     ph[1], pl[1]);
                pack_hilo(c[2 * klq + 1][0], c[2 * klq + 1][1], ph[2], pl[2]);
                pack_hilo(c[2 * klq + 1][2], c[2 * klq + 1][3], ph[3], pl[3]);
                #pragma unroll
                for (int nf = 0; nf < 4; nf++) {
                    uint2 vh2 = *(const uint2*)&Vs_hi[s][(klq * 4 + nf) * 64 + lane * 2];
                    uint2 vl2 = *(const uint2*)&Vs_lo[s][(klq * 4 + nf) * 64 + lane * 2];
                    unsigned vhf[2] = {vh2.x, vh2.y};
                    unsigned vlf[2] = {vl2.x, vl2.y};
                    mma16816(o[nf], ph, vhf);
                    mma16816(o[nf], ph, vlf);
                    mma16816(o[nf], pl, vhf);
                }
            }
        }
        __syncthreads();
    }
    #undef ISSUE_TILE

    rs0 += __shfl_xor_sync(0xffffffffu, rs0, 1);
    rs0 += __shfl_xor_sync(0xffffffffu, rs0, 2);
    rs1 += __shfl_xor_sync(0xffffffffu, rs1, 1);
    rs1 += __shfl_xor_sync(0xffffffffu, rs1, 2);
    float i0 = 1.f / (rs0 + 1e-10f);
    float i1 = 1.f / (rs1 + 1e-10f);
    size_t r0 = (size_t)(b * TT + row0);
    #pragma unroll
    for (int nf = 0; nf < 4; nf++) {
        int vd = h * DKk + nf * 8 + 2 * t;
        *(float2*)(ov + r0 * DM + vd)       = make_float2(o[nf][0] * i0, o[nf][1] * i0);
        *(float2*)(ov + (r0 + 8) * DM + vd) = make_float2(o[nf][2] * i1, o[nf][3] * i1);
    }
}

// -------------------- launch --------------------------------------------------
extern "C" void kernel_launch(void* const* d_in, const int* in_sizes, int n_in,
                              void* d_out, int out_size) {
    const int*   x     = (const int*)  d_in[0];
    const float* emb   = (const float*)d_in[1];
    const float* pos   = (const float*)d_in[2];
    const float* wq    = (const float*)d_in[3];
    const float* wk    = (const float*)d_in[4];
    const float* wv    = (const float*)d_in[5];
    const float* wo    = (const float*)d_in[6];
    const float* mlp0  = (const float*)d_in[7];
    const float* mlpb  = (const float*)d_in[8];
    const float* mlp1  = (const float*)d_in[9];
    const float* unemb = (const float*)d_in[10];
    const float* bias  = (const float*)d_in[11];
    float* out = (float*)d_out;

    unsigned *hh_, *hl_, *hf_, *qh_, *ql_, *kh_, *kl_, *yf_, *wh_, *wl_, *vth_, *vtl_;
    float *ov_, *tmp_, *wos_;
    cudaGetSymbolAddress((void**)&hh_, g_hh);
    cudaGetSymbolAddress((void**)&hl_, g_hl);
    cudaGetSymbolAddress((void**)&hf_, g_hf);
    cudaGetSymbolAddress((void**)&qh_, g_qh);
    cudaGetSymbolAddress((void**)&ql_, g_ql);
    cudaGetSymbolAddress((void**)&kh_, g_kh);
    cudaGetSymbolAddress((void**)&kl_, g_kl);
    cudaGetSymbolAddress((void**)&yf_, g_yf);
    cudaGetSymbolAddress((void**)&wh_, g_wh);
    cudaGetSymbolAddress((void**)&wl_, g_wl);
    cudaGetSymbolAddress((void**)&vth_, g_vth);
    cudaGetSymbolAddress((void**)&vtl_, g_vtl);
    cudaGetSymbolAddress((void**)&ov_,  g_ov);
    cudaGetSymbolAddress((void**)&tmp_, g_tmp);
    cudaGetSymbolAddress((void**)&wos_, g_wosum);

    const int SM128 = (8192 + 4 * 16 * 128) * 4;        // QKV bf16 3-term
    const int SMH128 = (2 * 2048 + 2 * 16 * 128) * 4;   // 32768 B
    const int SMH64  = (2 * 2048 + 2 * 16 * 64)  * 4;   // 24576 B
    cudaFuncSetAttribute(mgemm_db<128>, cudaFuncAttributeMaxDynamicSharedMemorySize, SM128);
    cudaFuncSetAttribute(hgemm<1, 128>, cudaFuncAttributeMaxDynamicSharedMemorySize, SMH128);
    cudaFuncSetAttribute(hgemm<0, 64>,  cudaFuncAttributeMaxDynamicSharedMemorySize, SMH64);
    cudaFuncSetAttribute(hgemm<2, 128>, cudaFuncAttributeMaxDynamicSharedMemorySize, SMH128);

    // Launch order: detect, embed, convert, QKV, attention ... so that the ncu
    // capture slot (previously embed_ln) lands on mgemm_db (QKV GEMM).
    detect_idx<<<1, 64>>>(x);
    embed_ln_w<<<BT / 8, 256>>>(x, emb, pos);
    convert_weights<<<(W_TOT + 255) / 256, 256>>>(wq, wk, wv, mlp0, mlp1, unemb);

    for (int l = 0; l < NL; l++) {
        const unsigned* wqkv_h = wh_ + (size_t)(l * 3) * DM * KP_DM;
        const unsigned* wqkv_l = wl_ + (size_t)(l * 3) * DM * KP_DM;
        const unsigned* m0f = wh_ + W_M0 + (size_t)l * DHid * KP_DM;
        const unsigned* m1f = wh_ + W_M1 + (size_t)l * DM * KP_HID;

        mgemm_db<128><<<dim3(6, BT / 128), 256, SM128>>>(
            hh_, hl_, wqkv_h, wqkv_l, qh_, ql_, kh_, kl_, vth_, vtl_,
            BT, DM, KP_DM);

        attention_mma2<<<dim3(TT / 128, BB * HH), 256>>>(qh_, ql_, kh_, kl_, vth_, vtl_, ov_);
        if (l == 0)
            compute_wosum_all<<<(NL * DKk * DM + 255) / 256, 256>>>(wo);
        attn_out_ln_w<<<BT / 8, 256>>>(ov_, wos_ + (size_t)l * DKk * DM);

        hgemm<1, 128><<<dim3(DHid / 128, BT / 128), 256, SMH128>>>(
            hf_, m0f, nullptr, yf_, mlpb + (size_t)l * DHid, BT, DHid, KP_DM);
        hgemm<0, 64><<<dim3(DM / 64, BT / 128), 256, SMH64>>>(
            yf_, m1f, tmp_, nullptr, nullptr, BT, DM, KP_HID);
        ln_residual_w<<<BT / 8, 256>>>(tmp_);
    }

    hgemm<2, 128><<<dim3(ND / 128, BT / 128), 256, SMH128>>>(
        hf_, wh_ + W_UE, out, nullptr, bias, BT, ND, KP_DM);
}